// round 8
// baseline (speedup 1.0000x reference)
#include <cuda_runtime.h>
#include <cuda.h>
#include <cuda_bf16.h>
#include <math.h>
#include <stdint.h>

#define DM 1024
#define NH 16
#define HD 64
#define MSL 5000
#define BB 2
#define SS 2048
#define MT (BB*SS)   // 4096 rows total

// Scratch (allocation-free rule: device globals)
__device__ __nv_bfloat16 g_ah[MT*DM];     // GEMM A hi (xpe-split, later o-split)
__device__ __nv_bfloat16 g_al[MT*DM];     // GEMM A lo
__device__ __nv_bfloat16 g_wh[4*DM*DM];   // stacked Wq|Wk|Wv|Wo hi
__device__ __nv_bfloat16 g_wl[4*DM*DM];
// split-bf16 Q/K/V in [B,H,S,hd] (Q pre-scaled by 1/32)
__device__ __nv_bfloat16 g_qh[MT*DM];
__device__ __nv_bfloat16 g_ql[MT*DM];
__device__ __nv_bfloat16 g_kh[MT*DM];
__device__ __nv_bfloat16 g_kl[MT*DM];
__device__ __nv_bfloat16 g_vh[MT*DM];
__device__ __nv_bfloat16 g_vl[MT*DM];

// ---------------------------------------------------------------------------
// helpers
// ---------------------------------------------------------------------------
__device__ __forceinline__ uint32_t smem_u32(const void* p) {
    uint32_t a;
    asm("{ .reg .u64 t; cvta.to.shared.u64 t, %1; cvt.u32.u64 %0, t; }" : "=r"(a) : "l"(p));
    return a;
}

#define MBAR_INIT(addr, cnt) \
    asm volatile("mbarrier.init.shared.b64 [%0], %1;" :: "r"(addr), "r"(cnt) : "memory")

#define EXPECT_TX(addr, bytes) \
    asm volatile("mbarrier.arrive.expect_tx.shared.b64 _, [%0], %1;" :: "r"(addr), "r"(bytes) : "memory")

#define TMA2D(smem, mapp, x, y, mbar) \
    asm volatile("cp.async.bulk.tensor.2d.shared::cluster.global.tile.mbarrier::complete_tx::bytes " \
        "[%0], [%1, {%2, %3}], [%4];" \
        :: "r"(smem), "l"(mapp), "r"(x), "r"(y), "r"(mbar) : "memory")

__device__ __forceinline__ void mbar_wait(uint32_t addr, uint32_t parity) {
    uint32_t done;
    asm volatile(
        "{\n\t.reg .pred p;\n\t"
        "mbarrier.try_wait.parity.shared.b64 p, [%1], %2;\n\t"
        "selp.b32 %0,1,0,p;\n\t}"
        : "=r"(done) : "r"(addr), "r"(parity) : "memory");
    while (!done) {
        asm volatile(
            "{\n\t.reg .pred p;\n\t"
            "mbarrier.try_wait.parity.shared.b64 p, [%1], %2, 0x989680;\n\t"
            "selp.b32 %0,1,0,p;\n\t}"
            : "=r"(done) : "r"(addr), "r"(parity) : "memory");
    }
}

#define LDSM4(r, addr) \
    asm volatile("ldmatrix.sync.aligned.m8n8.x4.shared.b16 {%0,%1,%2,%3}, [%4];" \
        : "=r"((r)[0]), "=r"((r)[1]), "=r"((r)[2]), "=r"((r)[3]) : "r"(addr))

#define LDSM4T(r, addr) \
    asm volatile("ldmatrix.sync.aligned.m8n8.x4.trans.shared.b16 {%0,%1,%2,%3}, [%4];" \
        : "=r"((r)[0]), "=r"((r)[1]), "=r"((r)[2]), "=r"((r)[3]) : "r"(addr))

#define MMA16816(d, a, b0v, b1v) \
    asm volatile("mma.sync.aligned.m16n8k16.row.col.f32.bf16.bf16.f32 " \
        "{%0,%1,%2,%3}, {%4,%5,%6,%7}, {%8,%9}, {%0,%1,%2,%3};" \
        : "+f"((d)[0]), "+f"((d)[1]), "+f"((d)[2]), "+f"((d)[3]) \
        : "r"((a)[0]), "r"((a)[1]), "r"((a)[2]), "r"((a)[3]), "r"(b0v), "r"(b1v))

__device__ __forceinline__ uint32_t pack_bf(float hi, float lo) {
    uint32_t d;
    asm("cvt.rn.bf16x2.f32 %0, %1, %2;" : "=r"(d) : "f"(hi), "f"(lo));
    return d;
}
__device__ __forceinline__ float bf_round(float v) {
    return __bfloat162float(__float2bfloat16(v));
}

// ---------------------------------------------------------------------------
// Kernel 1: fused PE + split:  (x + a*sin_pe + (1-a)*rel) -> (g_ah, g_al)
// ---------------------------------------------------------------------------
__global__ void pe_split_kernel(const float* __restrict__ x,
                                const float* __restrict__ rel,
                                const float* __restrict__ alphap) {
    int idx = blockIdx.x*blockDim.x + threadIdx.x;
    if (idx >= MT*(DM/2)) return;
    int m  = idx >> 9;
    int pp = idx & 511;
    int s  = m & (SS-1);
    float a = alphap[0];
    float freq = __expf(-(float)(2*pp) * (9.210340371976184f/(float)DM));
    float ang = (float)s * freq;
    float sn, cs;
    sincosf(ang, &sn, &cs);
    const float* rr = rel + (size_t)(MSL - SS + s)*DM + 2*pp;
    float2 xv = *(const float2*)(x + (size_t)idx*2);
    float om = 1.0f - a;
    float ox = xv.x + a*sn + om*rr[0];
    float oy = xv.y + a*cs + om*rr[1];
    __nv_bfloat16 hx = __float2bfloat16(ox);
    __nv_bfloat16 hy = __float2bfloat16(oy);
    __nv_bfloat16 lx = __float2bfloat16(ox - __bfloat162float(hx));
    __nv_bfloat16 ly = __float2bfloat16(oy - __bfloat162float(hy));
    *(__nv_bfloat162*)(g_ah + (size_t)idx*2) = __nv_bfloat162(hx, hy);
    *(__nv_bfloat162*)(g_al + (size_t)idx*2) = __nv_bfloat162(lx, ly);
}

// ---------------------------------------------------------------------------
// Kernel 2: all four weight matrices -> (hi, lo) bf16 split in one launch.
// ---------------------------------------------------------------------------
#define NW4 (DM*DM/4)   // 262144 float4 per matrix
__global__ void split4_kernel(const float* __restrict__ w0,
                              const float* __restrict__ w1,
                              const float* __restrict__ w2,
                              const float* __restrict__ w3) {
    int i = blockIdx.x*blockDim.x + threadIdx.x;
    if (i >= 4*NW4) return;
    const int which = i >> 18;            // NW4 = 2^18
    const int j = i & (NW4 - 1);
    const float* src = (which == 0) ? w0 : (which == 1) ? w1 : (which == 2) ? w2 : w3;
    float4 v = ((const float4*)src)[j];
    __nv_bfloat16 h0 = __float2bfloat16(v.x);
    __nv_bfloat16 h1 = __float2bfloat16(v.y);
    __nv_bfloat16 h2 = __float2bfloat16(v.z);
    __nv_bfloat16 h3 = __float2bfloat16(v.w);
    __nv_bfloat16 l0 = __float2bfloat16(v.x - __bfloat162float(h0));
    __nv_bfloat16 l1 = __float2bfloat16(v.y - __bfloat162float(h1));
    __nv_bfloat16 l2 = __float2bfloat16(v.z - __bfloat162float(h2));
    __nv_bfloat16 l3 = __float2bfloat16(v.w - __bfloat162float(h3));
    size_t o = (size_t)which*DM*DM + (size_t)j*4;
    __nv_bfloat162* hp = (__nv_bfloat162*)(g_wh + o);
    __nv_bfloat162* lp = (__nv_bfloat162*)(g_wl + o);
    hp[0] = __nv_bfloat162(h0, h1); hp[1] = __nv_bfloat162(h2, h3);
    lp[0] = __nv_bfloat162(l0, l1); lp[1] = __nv_bfloat162(l2, l3);
}

// ---------------------------------------------------------------------------
// TMA split-bf16 GEMM. Block 128x128, 256 threads, warp tile 64x32.
// K-chunk 64, THREE-stage TMA pipeline (SW128), mbarrier completion.
// mode 0: merged QKV (gridDim.x=24), n0>>10 selects target; mode 3: out proj
// (W rows offset by wbase in the stacked weight tensor).
// ---------------------------------------------------------------------------
#define GB 16384                  // one operand tile: 128 rows x 128B (SW128)
#define GSTG (4*GB)               // AH AL BH BL = 65536
#define GEMM_SMEM (3*GSTG + 1088) // 3 stages + mbars/align

__global__ void __launch_bounds__(256, 1) gemm_tma(
    const __grid_constant__ CUtensorMap mAh,
    const __grid_constant__ CUtensorMap mAl,
    const __grid_constant__ CUtensorMap mWh,
    const __grid_constant__ CUtensorMap mWl,
    const float* __restrict__ b0, const float* __restrict__ b1,
    const float* __restrict__ b2, float* __restrict__ outp,
    int wbase, int mode)
{
    extern __shared__ char smem[];
    const uint32_t sb = (smem_u32(smem) + 1023) & ~1023u;
    const uint32_t mb = sb + 3*GSTG;
    const int t  = threadIdx.x;
    const int m0 = blockIdx.y * 128;
    const int n0 = blockIdx.x * 128;

    if (t == 0) { MBAR_INIT(mb, 1); MBAR_INIT(mb + 8, 1); MBAR_INIT(mb + 16, 1); }
    __syncthreads();

    auto issue = [&](int ck) {
        const uint32_t d   = sb + (uint32_t)(ck % 3) * GSTG;
        const uint32_t bar = mb + (uint32_t)(ck % 3) * 8;
        EXPECT_TX(bar, (uint32_t)GSTG);
        TMA2D(d + 0*GB, &mAh, ck*64, m0, bar);
        TMA2D(d + 1*GB, &mAl, ck*64, m0, bar);
        TMA2D(d + 2*GB, &mWh, ck*64, wbase + n0, bar);
        TMA2D(d + 3*GB, &mWl, ck*64, wbase + n0, bar);
    };
    if (t == 0) { issue(0); issue(1); issue(2); }

    const int wid = t >> 5, l = t & 31;
    const int warpM = wid & 1;
    const int warpN = wid >> 1;
    const int q  = l >> 3, lr = l & 7;

    float acc[16][4];
    #pragma unroll
    for (int i = 0; i < 16; i++)
        #pragma unroll
        for (int j = 0; j < 4; j++) acc[i][j] = 0.f;

    // fragment row offsets (row*128); all rows == lr (mod 8) -> lane-const XOR
    uint32_t arow[4], brow[2];
    #pragma unroll
    for (int mt = 0; mt < 4; mt++) arow[mt] = (uint32_t)(warpM*64 + mt*16 + (q & 1)*8 + lr) * 128;
    #pragma unroll
    for (int np = 0; np < 2; np++) brow[np] = (uint32_t)(warpN*32 + np*16 + (q >> 1)*8 + lr) * 128;
    uint32_t axc[4], bxc[4];
    #pragma unroll
    for (int s = 0; s < 4; s++) {
        axc[s] = (uint32_t)((((q >> 1) + 2*s) ^ lr) * 16);
        bxc[s] = (uint32_t)((((q & 1) + 2*s) ^ lr) * 16);
    }

    int ph0 = 0, ph1 = 0, ph2 = 0;
    for (int ch = 0; ch < DM/64; ch++) {
        const int bsel = ch % 3;
        if (bsel == 0)      { mbar_wait(mb,      (uint32_t)ph0); ph0 ^= 1; }
        else if (bsel == 1) { mbar_wait(mb + 8,  (uint32_t)ph1); ph1 ^= 1; }
        else                { mbar_wait(mb + 16, (uint32_t)ph2); ph2 ^= 1; }
        const uint32_t bs = sb + (uint32_t)bsel * GSTG;

        #pragma unroll
        for (int s = 0; s < 4; s++) {
            uint32_t ah[4][4], alr[4][4];
            #pragma unroll
            for (int mt = 0; mt < 4; mt++) {
                uint32_t ao = arow[mt] + axc[s];
                LDSM4(ah[mt],  bs + 0*GB + ao);
                LDSM4(alr[mt], bs + 1*GB + ao);
            }
            uint32_t bh[2][4], bl[2][4];
            #pragma unroll
            for (int np = 0; np < 2; np++) {
                uint32_t bo = brow[np] + bxc[s];
                LDSM4(bh[np], bs + 2*GB + bo);
                LDSM4(bl[np], bs + 3*GB + bo);
            }
            #pragma unroll
            for (int mt = 0; mt < 4; mt++)
                #pragma unroll
                for (int nt = 0; nt < 4; nt++) {
                    const int np = nt >> 1, h = (nt & 1) * 2;
                    MMA16816(acc[mt*4+nt], ah[mt], bh[np][h], bh[np][h+1]);
                }
            #pragma unroll
            for (int mt = 0; mt < 4; mt++)
                #pragma unroll
                for (int nt = 0; nt < 4; nt++) {
                    const int np = nt >> 1, h = (nt & 1) * 2;
                    MMA16816(acc[mt*4+nt], ah[mt], bl[np][h], bl[np][h+1]);
                }
            #pragma unroll
            for (int mt = 0; mt < 4; mt++)
                #pragma unroll
                for (int nt = 0; nt < 4; nt++) {
                    const int np = nt >> 1, h = (nt & 1) * 2;
                    MMA16816(acc[mt*4+nt], alr[mt], bh[np][h], bh[np][h+1]);
                }
        }
        __syncthreads();
        if (t == 0 && ch + 3 < DM/64) issue(ch + 3);
    }

    // epilogue
    if (mode == 0) {
        const int which = n0 >> 10;
        const float ascale = (which == 0) ? 0.03125f : 1.0f;
        __nv_bfloat16* oh = (which == 0) ? g_qh : (which == 1) ? g_kh : g_vh;
        __nv_bfloat16* ol = (which == 0) ? g_ql : (which == 1) ? g_kl : g_vl;
        const float* bias = (which == 0) ? b0 : (which == 1) ? b1 : b2;
        const int nloc0 = n0 & 1023;
        #pragma unroll
        for (int nt = 0; nt < 4; nt++) {
            const int n = nloc0 + warpN*32 + nt*8 + (l & 3)*2;
            const float bx = bias[n], by = bias[n+1];
            #pragma unroll
            for (int mt = 0; mt < 4; mt++) {
                const float* d = acc[mt*4 + nt];
                #pragma unroll
                for (int half = 0; half < 2; half++) {
                    const int m = m0 + warpM*64 + mt*16 + (l >> 2) + half*8;
                    float vx = (d[half*2 + 0] + bx) * ascale;
                    float vy = (d[half*2 + 1] + by) * ascale;
                    const int bb = m >> 11, s = m & (SS-1);
                    const int hh = n >> 6, dd = n & 63;
                    size_t o = (size_t)((bb*NH + hh)*SS + s)*HD + dd;
                    __nv_bfloat16 hx = __float2bfloat16(vx);
                    __nv_bfloat16 hy = __float2bfloat16(vy);
                    __nv_bfloat16 lx = __float2bfloat16(vx - __bfloat162float(hx));
                    __nv_bfloat16 ly = __float2bfloat16(vy - __bfloat162float(hy));
                    *(__nv_bfloat162*)(oh + o) = __nv_bfloat162(hx, hy);
                    *(__nv_bfloat162*)(ol + o) = __nv_bfloat162(lx, ly);
                }
            }
        }
    } else {
        #pragma unroll
        for (int nt = 0; nt < 4; nt++) {
            const int n = n0 + warpN*32 + nt*8 + (l & 3)*2;
            const float bx = b0[n], by = b0[n+1];
            #pragma unroll
            for (int mt = 0; mt < 4; mt++) {
                const float* d = acc[mt*4 + nt];
                #pragma unroll
                for (int half = 0; half < 2; half++) {
                    const int m = m0 + warpM*64 + mt*16 + (l >> 2) + half*8;
                    float2 v;
                    v.x = d[half*2 + 0] + bx;
                    v.y = d[half*2 + 1] + by;
                    *(float2*)&outp[(size_t)m*DM + n] = v;
                }
            }
        }
    }
}

// ---------------------------------------------------------------------------
// Flash attention on tensor cores (split-bf16, online softmax), TMA staging.
// Block: 128 queries x one (b,h); 256 threads = 8 warps, warp = 16 q rows.
// KV tile 64, THREE-stage TMA pipeline (SW128). Same math as round 5.
// ---------------------------------------------------------------------------
#define FQB 16384                 // Q array tile: 128 rows x 128B
#define FKB 8192                  // KV array tile: 64 rows x 128B
#define FSTG (4*FKB)              // KH KL VH VL = 32768
#define FL_SMEM (2*FQB + 3*FSTG + 1088)

__global__ void __launch_bounds__(256, 1) flash_tma(
    const __grid_constant__ CUtensorMap mQh,
    const __grid_constant__ CUtensorMap mQl,
    const __grid_constant__ CUtensorMap mKh,
    const __grid_constant__ CUtensorMap mKl,
    const __grid_constant__ CUtensorMap mVh,
    const __grid_constant__ CUtensorMap mVl)
{
    extern __shared__ char fsm[];
    const uint32_t sb  = (smem_u32(fsm) + 1023) & ~1023u;
    const uint32_t kvb = sb + 2*FQB;
    const uint32_t mbq = sb + 2*FQB + 3*FSTG;
    const int bh = blockIdx.y;
    const int q0 = blockIdx.x * 128;
    const int row0 = bh * SS;               // tensor row base for this (b,h)
    const int t = threadIdx.x, wid = t >> 5, l = t & 31;
    const int q = l >> 3, lr = l & 7;
    const int wq0 = wid * 16;

    if (t == 0) {
        MBAR_INIT(mbq, 1);
        MBAR_INIT(mbq + 8, 1); MBAR_INIT(mbq + 16, 1); MBAR_INIT(mbq + 24, 1);
    }
    __syncthreads();

    auto kvissue = [&](int ti) {
        const uint32_t d   = kvb + (uint32_t)(ti % 3) * FSTG;
        const uint32_t bar = mbq + 8 + (uint32_t)(ti % 3) * 8;
        EXPECT_TX(bar, (uint32_t)FSTG);
        const int y = row0 + ti*64;
        TMA2D(d + 0*FKB, &mKh, 0, y, bar);
        TMA2D(d + 1*FKB, &mKl, 0, y, bar);
        TMA2D(d + 2*FKB, &mVh, 0, y, bar);
        TMA2D(d + 3*FKB, &mVl, 0, y, bar);
    };
    if (t == 0) {
        EXPECT_TX(mbq, (uint32_t)(2*FQB));
        TMA2D(sb,       &mQh, 0, row0 + q0, mbq);
        TMA2D(sb + FQB, &mQl, 0, row0 + q0, mbq);
        kvissue(0);
        kvissue(1);
        kvissue(2);
    }

    mbar_wait(mbq, 0);

    // Q fragments (persistent): row = wq0 + (q&1)*8 + lr, col16 = (q>>1)+2kt
    uint32_t qhf[4][4], qlf[4][4];
    {
        const uint32_t qrow = (uint32_t)(wq0 + (q & 1)*8 + lr) * 128;
        #pragma unroll
        for (int kt = 0; kt < 4; kt++) {
            const uint32_t c = (uint32_t)((((q >> 1) + 2*kt) ^ lr) * 16);
            LDSM4(qhf[kt], sb + qrow + c);
            LDSM4(qlf[kt], sb + FQB + qrow + c);
        }
    }

    // fragment address invariants for K and V
    uint32_t krow[4], vrow[4], kxc[4], vxc[4];
    #pragma unroll
    for (int np = 0; np < 4; np++) krow[np] = (uint32_t)(np*16 + (q >> 1)*8 + lr) * 128;
    #pragma unroll
    for (int kt = 0; kt < 4; kt++) vrow[kt] = (uint32_t)(kt*16 + (q & 1)*8 + lr) * 128;
    #pragma unroll
    for (int kt = 0; kt < 4; kt++) kxc[kt] = (uint32_t)((((q & 1) + 2*kt) ^ lr) * 16);
    #pragma unroll
    for (int g = 0; g < 4; g++)  vxc[g]  = (uint32_t)(((2*g + (q >> 1)) ^ lr) * 16);

    float oacc[8][4];
    #pragma unroll
    for (int i = 0; i < 8; i++)
        #pragma unroll
        for (int j = 0; j < 4; j++) oacc[i][j] = 0.f;
    float mprev0 = -1e30f, mprev1 = -1e30f, lsum0 = 0.f, lsum1 = 0.f;

    int kvph0 = 0, kvph1 = 0, kvph2 = 0;
    for (int ti = 0; ti < SS/64; ti++) {
        const int bsel = ti % 3;
        if (bsel == 0)      { mbar_wait(mbq + 8,  (uint32_t)kvph0); kvph0 ^= 1; }
        else if (bsel == 1) { mbar_wait(mbq + 16, (uint32_t)kvph1); kvph1 ^= 1; }
        else                { mbar_wait(mbq + 24, (uint32_t)kvph2); kvph2 ^= 1; }
        const uint32_t kb = kvb + (uint32_t)bsel * FSTG;

        float sacc[8][4];
        #pragma unroll
        for (int i = 0; i < 8; i++)
            #pragma unroll
            for (int j = 0; j < 4; j++) sacc[i][j] = 0.f;

        #pragma unroll
        for (int kt = 0; kt < 4; kt++) {
            uint32_t khf[4][4], klf[4][4];
            #pragma unroll
            for (int np = 0; np < 4; np++) {
                uint32_t ba = krow[np] + kxc[kt];
                LDSM4(khf[np], kb + 0*FKB + ba);
                LDSM4(klf[np], kb + 1*FKB + ba);
            }
            #pragma unroll
            for (int nt = 0; nt < 8; nt++) {
                const int np = nt >> 1, h = (nt & 1)*2;
                MMA16816(sacc[nt], qhf[kt], khf[np][h], khf[np][h+1]);
            }
            #pragma unroll
            for (int nt = 0; nt < 8; nt++) {
                const int np = nt >> 1, h = (nt & 1)*2;
                MMA16816(sacc[nt], qhf[kt], klf[np][h], klf[np][h+1]);
            }
            #pragma unroll
            for (int nt = 0; nt < 8; nt++) {
                const int np = nt >> 1, h = (nt & 1)*2;
                MMA16816(sacc[nt], qlf[kt], khf[np][h], khf[np][h+1]);
            }
        }

        float m0 = sacc[0][0], m1 = sacc[0][2];
        #pragma unroll
        for (int nt = 0; nt < 8; nt++) {
            m0 = fmaxf(m0, fmaxf(sacc[nt][0], sacc[nt][1]));
            m1 = fmaxf(m1, fmaxf(sacc[nt][2], sacc[nt][3]));
        }
        m0 = fmaxf(m0, __shfl_xor_sync(0xffffffffu, m0, 1));
        m0 = fmaxf(m0, __shfl_xor_sync(0xffffffffu, m0, 2));
        m1 = fmaxf(m1, __shfl_xor_sync(0xffffffffu, m1, 1));
        m1 = fmaxf(m1, __shfl_xor_sync(0xffffffffu, m1, 2));

        const float mn0 = fmaxf(mprev0, m0);
        const float mn1 = fmaxf(mprev1, m1);
        const float a0 = __expf(mprev0 - mn0);
        const float a1 = __expf(mprev1 - mn1);
        mprev0 = mn0; mprev1 = mn1;

        float rs0 = 0.f, rs1 = 0.f;
        #pragma unroll
        for (int nt = 0; nt < 8; nt++) {
            sacc[nt][0] = __expf(sacc[nt][0] - mn0);
            sacc[nt][1] = __expf(sacc[nt][1] - mn0);
            sacc[nt][2] = __expf(sacc[nt][2] - mn1);
            sacc[nt][3] = __expf(sacc[nt][3] - mn1);
            rs0 += sacc[nt][0] + sacc[nt][1];
            rs1 += sacc[nt][2] + sacc[nt][3];
        }
        rs0 += __shfl_xor_sync(0xffffffffu, rs0, 1);
        rs0 += __shfl_xor_sync(0xffffffffu, rs0, 2);
        rs1 += __shfl_xor_sync(0xffffffffu, rs1, 1);
        rs1 += __shfl_xor_sync(0xffffffffu, rs1, 2);
        lsum0 = lsum0*a0 + rs0;
        lsum1 = lsum1*a1 + rs1;
        #pragma unroll
        for (int nj = 0; nj < 8; nj++) {
            oacc[nj][0] *= a0; oacc[nj][1] *= a0;
            oacc[nj][2] *= a1; oacc[nj][3] *= a1;
        }

        #pragma unroll
        for (int kt = 0; kt < 4; kt++) {
            uint32_t ph[4], pl[4];
            #pragma unroll
            for (int e = 0; e < 4; e++) {
                const float* s0 = sacc[2*kt + (e >> 1)];
                const float x0 = s0[(e & 1)*2], x1 = s0[(e & 1)*2 + 1];
                ph[e] = pack_bf(x1, x0);
                pl[e] = pack_bf(x1 - bf_round(x1), x0 - bf_round(x0));
            }
            uint32_t vhf[4][4], vlf[4][4];
            #pragma unroll
            for (int g = 0; g < 4; g++) {
                uint32_t va = vrow[kt] + vxc[g];
                LDSM4T(vhf[g], kb + 2*FKB + va);
                LDSM4T(vlf[g], kb + 3*FKB + va);
            }
            #pragma unroll
            for (int nj = 0; nj < 8; nj++) {
                const int g = nj >> 1, o = (nj & 1)*2;
                MMA16816(oacc[nj], ph, vhf[g][o], vhf[g][o+1]);
            }
            #pragma unroll
            for (int nj = 0; nj < 8; nj++) {
                const int g = nj >> 1, o = (nj & 1)*2;
                MMA16816(oacc[nj], ph, vlf[g][o], vlf[g][o+1]);
            }
            #pragma unroll
            for (int nj = 0; nj < 8; nj++) {
                const int g = nj >> 1, o = (nj & 1)*2;
                MMA16816(oacc[nj], pl, vhf[g][o], vhf[g][o+1]);
            }
        }

        __syncthreads();
        if (t == 0 && ti + 3 < SS/64) kvissue(ti + 3);
    }

    const float inv0 = 1.0f / lsum0;
    const float inv1 = 1.0f / lsum1;
    const int r0 = q0 + wq0 + (l >> 2);
    const int bb = bh >> 4, hh = bh & 15;
    #pragma unroll
    for (int nj = 0; nj < 8; nj++) {
        const int col = hh*HD + nj*8 + (l & 3)*2;
        {
            const float e0 = oacc[nj][0]*inv0, e1 = oacc[nj][1]*inv0;
            __nv_bfloat16 h0 = __float2bfloat16(e0), h1 = __float2bfloat16(e1);
            __nv_bfloat16 l0 = __float2bfloat16(e0 - __bfloat162float(h0));
            __nv_bfloat16 l1 = __float2bfloat16(e1 - __bfloat162float(h1));
            size_t o = (size_t)(bb*SS + r0)*DM + col;
            *(__nv_bfloat162*)(g_ah + o) = __nv_bfloat162(h0, h1);
            *(__nv_bfloat162*)(g_al + o) = __nv_bfloat162(l0, l1);
        }
        {
            const float e0 = oacc[nj][2]*inv1, e1 = oacc[nj][3]*inv1;
            __nv_bfloat16 h0 = __float2bfloat16(e0), h1 = __float2bfloat16(e1);
            __nv_bfloat16 l0 = __float2bfloat16(e0 - __bfloat162float(h0));
            __nv_bfloat16 l1 = __float2bfloat16(e1 - __bfloat162float(h1));
            size_t o = (size_t)(bb*SS + r0 + 8)*DM + col;
            *(__nv_bfloat162*)(g_ah + o) = __nv_bfloat162(h0, h1);
            *(__nv_bfloat162*)(g_al + o) = __nv_bfloat162(l0, l1);
        }
    }
}

// ---------------------------------------------------------------------------
// host: tensor-map construction via driver entry point (no -lcuda needed)
// ---------------------------------------------------------------------------
typedef CUresult (CUDAAPI *PFN_encodeTiled)(
    CUtensorMap*, CUtensorMapDataType, cuuint32_t, void*,
    const cuuint64_t*, const cuuint64_t*, const cuuint32_t*, const cuuint32_t*,
    CUtensorMapInterleave, CUtensorMapSwizzle, CUtensorMapL2promotion,
    CUtensorMapFloatOOBfill);

static PFN_encodeTiled get_encoder() {
    static PFN_encodeTiled fn = nullptr;
    if (!fn) {
        void* p = nullptr;
        cudaDriverEntryPointQueryResult qr;
        cudaGetDriverEntryPoint("cuTensorMapEncodeTiled", &p, cudaEnableDefault, &qr);
        fn = (PFN_encodeTiled)p;
    }
    return fn;
}

static void mk2d(CUtensorMap* m, void* base, uint64_t d0, uint64_t rows,
                 uint32_t b0, uint32_t b1) {
    cuuint64_t dims[2]    = {d0, rows};
    cuuint64_t strides[1] = {d0 * 2};     // bytes
    cuuint32_t box[2]     = {b0, b1};
    cuuint32_t es[2]      = {1, 1};
    get_encoder()(m, CU_TENSOR_MAP_DATA_TYPE_BFLOAT16, 2, base,
                  dims, strides, box, es,
                  CU_TENSOR_MAP_INTERLEAVE_NONE, CU_TENSOR_MAP_SWIZZLE_128B,
                  CU_TENSOR_MAP_L2_PROMOTION_L2_128B,
                  CU_TENSOR_MAP_FLOAT_OOB_FILL_NONE);
}

extern "C" void kernel_launch(void* const* d_in, const int* in_sizes, int n_in,
                              void* d_out, int out_size) {
    const float* x     = (const float*)d_in[0];
    const float* rel   = (const float*)d_in[1];
    const float* alpha = (const float*)d_in[2];
    const float* Wq    = (const float*)d_in[3];
    const float* bq    = (const float*)d_in[4];
    const float* Wk    = (const float*)d_in[5];
    const float* bk    = (const float*)d_in[6];
    const float* Wv    = (const float*)d_in[7];
    const float* bv    = (const float*)d_in[8];
    const float* Wo    = (const float*)d_in[9];
    const float* bo    = (const float*)d_in[10];
    float* out = (float*)d_out;

    cudaFuncSetAttribute(gemm_tma,  cudaFuncAttributeMaxDynamicSharedMemorySize, GEMM_SMEM);
    cudaFuncSetAttribute(flash_tma, cudaFuncAttributeMaxDynamicSharedMemorySize, FL_SMEM);

    void *ah, *al, *wh, *wl, *qh, *ql, *kh, *kl, *vh, *vl;
    cudaGetSymbolAddress(&ah, g_ah);
    cudaGetSymbolAddress(&al, g_al);
    cudaGetSymbolAddress(&wh, g_wh);
    cudaGetSymbolAddress(&wl, g_wl);
    cudaGetSymbolAddress(&qh, g_qh);
    cudaGetSymbolAddress(&ql, g_ql);
    cudaGetSymbolAddress(&kh, g_kh);
    cudaGetSymbolAddress(&kl, g_kl);
    cudaGetSymbolAddress(&vh, g_vh);
    cudaGetSymbolAddress(&vl, g_vl);

    CUtensorMap mAh, mAl, mWh, mWl, mQh, mQl, mKh, mKl, mVh, mVl;
    mk2d(&mAh, ah, DM, MT,          64, 128);
    mk2d(&mAl, al, DM, MT,          64, 128);
    mk2d(&mWh, wh, DM, 4*DM,        64, 128);
    mk2d(&mWl, wl, DM, 4*DM,        64, 128);
    mk2d(&mQh, qh, HD, BB*NH*SS,    64, 128);
    mk2d(&mQl, ql, HD, BB*NH*SS,    64, 128);
    mk2d(&mKh, kh, HD, BB*NH*SS,    64, 64);
    mk2d(&mKl, kl, HD, BB*NH*SS,    64, 64);
    mk2d(&mVh, vh, HD, BB*NH*SS,    64, 64);
    mk2d(&mVl, vl, HD, BB*NH*SS,    64, 64);

    pe_split_kernel<<<(MT*(DM/2) + 255)/256, 256>>>(x, rel, alpha);
    split4_kernel<<<(4*NW4 + 255)/256, 256>>>(Wq, Wk, Wv, Wo);

    gemm_tma<<<dim3(3*DM/128, MT/128), 256, GEMM_SMEM>>>(
        mAh, mAl, mWh, mWl, bq, bk, bv, nullptr, 0, 0);

    flash_tma<<<dim3(SS/128, BB*NH), 256, FL_SMEM>>>(mQh, mQl, mKh, mKl, mVh, mVl);

    gemm_tma<<<dim3(DM/128, MT/128), 256, GEMM_SMEM>>>(
        mAh, mAl, mWh, mWl, bo, bo, bo, out, 3*DM, 3);
}

// round 9
// speedup vs baseline: 1.0814x; 1.0814x over previous
#include <cuda_runtime.h>
#include <cuda.h>
#include <cuda_bf16.h>
#include <math.h>
#include <stdint.h>

#define DM 1024
#define NH 16
#define HD 64
#define MSL 5000
#define BB 2
#define SS 2048
#define MT (BB*SS)   // 4096 rows total

// Scratch (allocation-free rule: device globals)
__device__ __nv_bfloat16 g_ah[MT*DM];     // GEMM A hi (xpe-split, later o-split)
__device__ __nv_bfloat16 g_al[MT*DM];     // GEMM A lo
__device__ __nv_bfloat16 g_wh[4*DM*DM];   // stacked Wq|Wk|Wv|Wo hi
__device__ __nv_bfloat16 g_wl[4*DM*DM];
// split-bf16 Q/K/V in [B,H,S,hd] (Q pre-scaled by 1/32)
__device__ __nv_bfloat16 g_qh[MT*DM];
__device__ __nv_bfloat16 g_ql[MT*DM];
__device__ __nv_bfloat16 g_kh[MT*DM];
__device__ __nv_bfloat16 g_kl[MT*DM];
__device__ __nv_bfloat16 g_vh[MT*DM];
__device__ __nv_bfloat16 g_vl[MT*DM];

// ---------------------------------------------------------------------------
// helpers
// ---------------------------------------------------------------------------
__device__ __forceinline__ uint32_t smem_u32(const void* p) {
    uint32_t a;
    asm("{ .reg .u64 t; cvta.to.shared.u64 t, %1; cvt.u32.u64 %0, t; }" : "=r"(a) : "l"(p));
    return a;
}

#define MBAR_INIT(addr, cnt) \
    asm volatile("mbarrier.init.shared.b64 [%0], %1;" :: "r"(addr), "r"(cnt) : "memory")

#define EXPECT_TX(addr, bytes) \
    asm volatile("mbarrier.arrive.expect_tx.shared.b64 _, [%0], %1;" :: "r"(addr), "r"(bytes) : "memory")

#define TMA2D(smem, mapp, x, y, mbar) \
    asm volatile("cp.async.bulk.tensor.2d.shared::cluster.global.tile.mbarrier::complete_tx::bytes " \
        "[%0], [%1, {%2, %3}], [%4];" \
        :: "r"(smem), "l"(mapp), "r"(x), "r"(y), "r"(mbar) : "memory")

__device__ __forceinline__ void mbar_wait(uint32_t addr, uint32_t parity) {
    uint32_t done;
    asm volatile(
        "{\n\t.reg .pred p;\n\t"
        "mbarrier.try_wait.parity.shared.b64 p, [%1], %2;\n\t"
        "selp.b32 %0,1,0,p;\n\t}"
        : "=r"(done) : "r"(addr), "r"(parity) : "memory");
    while (!done) {
        asm volatile(
            "{\n\t.reg .pred p;\n\t"
            "mbarrier.try_wait.parity.shared.b64 p, [%1], %2, 0x989680;\n\t"
            "selp.b32 %0,1,0,p;\n\t}"
            : "=r"(done) : "r"(addr), "r"(parity) : "memory");
    }
}

#define LDSM4(r, addr) \
    asm volatile("ldmatrix.sync.aligned.m8n8.x4.shared.b16 {%0,%1,%2,%3}, [%4];" \
        : "=r"((r)[0]), "=r"((r)[1]), "=r"((r)[2]), "=r"((r)[3]) : "r"(addr))

#define LDSM4T(r, addr) \
    asm volatile("ldmatrix.sync.aligned.m8n8.x4.trans.shared.b16 {%0,%1,%2,%3}, [%4];" \
        : "=r"((r)[0]), "=r"((r)[1]), "=r"((r)[2]), "=r"((r)[3]) : "r"(addr))

#define MMA16816(d, a, b0v, b1v) \
    asm volatile("mma.sync.aligned.m16n8k16.row.col.f32.bf16.bf16.f32 " \
        "{%0,%1,%2,%3}, {%4,%5,%6,%7}, {%8,%9}, {%0,%1,%2,%3};" \
        : "+f"((d)[0]), "+f"((d)[1]), "+f"((d)[2]), "+f"((d)[3]) \
        : "r"((a)[0]), "r"((a)[1]), "r"((a)[2]), "r"((a)[3]), "r"(b0v), "r"(b1v))

__device__ __forceinline__ uint32_t pack_bf(float hi, float lo) {
    uint32_t d;
    asm("cvt.rn.bf16x2.f32 %0, %1, %2;" : "=r"(d) : "f"(hi), "f"(lo));
    return d;
}
__device__ __forceinline__ float bf_round(float v) {
    return __bfloat162float(__float2bfloat16(v));
}

// ---------------------------------------------------------------------------
// Kernel 1: fused PE + split:  (x + a*sin_pe + (1-a)*rel) -> (g_ah, g_al)
// ---------------------------------------------------------------------------
__global__ void pe_split_kernel(const float* __restrict__ x,
                                const float* __restrict__ rel,
                                const float* __restrict__ alphap) {
    int idx = blockIdx.x*blockDim.x + threadIdx.x;
    if (idx >= MT*(DM/2)) return;
    int m  = idx >> 9;
    int pp = idx & 511;
    int s  = m & (SS-1);
    float a = alphap[0];
    float freq = __expf(-(float)(2*pp) * (9.210340371976184f/(float)DM));
    float ang = (float)s * freq;
    float sn, cs;
    sincosf(ang, &sn, &cs);
    const float* rr = rel + (size_t)(MSL - SS + s)*DM + 2*pp;
    float2 xv = *(const float2*)(x + (size_t)idx*2);
    float om = 1.0f - a;
    float ox = xv.x + a*sn + om*rr[0];
    float oy = xv.y + a*cs + om*rr[1];
    __nv_bfloat16 hx = __float2bfloat16(ox);
    __nv_bfloat16 hy = __float2bfloat16(oy);
    __nv_bfloat16 lx = __float2bfloat16(ox - __bfloat162float(hx));
    __nv_bfloat16 ly = __float2bfloat16(oy - __bfloat162float(hy));
    *(__nv_bfloat162*)(g_ah + (size_t)idx*2) = __nv_bfloat162(hx, hy);
    *(__nv_bfloat162*)(g_al + (size_t)idx*2) = __nv_bfloat162(lx, ly);
}

// ---------------------------------------------------------------------------
// Kernel 2: all four weight matrices -> (hi, lo) bf16 split in one launch.
// ---------------------------------------------------------------------------
#define NW4 (DM*DM/4)   // 262144 float4 per matrix
__global__ void split4_kernel(const float* __restrict__ w0,
                              const float* __restrict__ w1,
                              const float* __restrict__ w2,
                              const float* __restrict__ w3) {
    int i = blockIdx.x*blockDim.x + threadIdx.x;
    if (i >= 4*NW4) return;
    const int which = i >> 18;            // NW4 = 2^18
    const int j = i & (NW4 - 1);
    const float* src = (which == 0) ? w0 : (which == 1) ? w1 : (which == 2) ? w2 : w3;
    float4 v = ((const float4*)src)[j];
    __nv_bfloat16 h0 = __float2bfloat16(v.x);
    __nv_bfloat16 h1 = __float2bfloat16(v.y);
    __nv_bfloat16 h2 = __float2bfloat16(v.z);
    __nv_bfloat16 h3 = __float2bfloat16(v.w);
    __nv_bfloat16 l0 = __float2bfloat16(v.x - __bfloat162float(h0));
    __nv_bfloat16 l1 = __float2bfloat16(v.y - __bfloat162float(h1));
    __nv_bfloat16 l2 = __float2bfloat16(v.z - __bfloat162float(h2));
    __nv_bfloat16 l3 = __float2bfloat16(v.w - __bfloat162float(h3));
    size_t o = (size_t)which*DM*DM + (size_t)j*4;
    __nv_bfloat162* hp = (__nv_bfloat162*)(g_wh + o);
    __nv_bfloat162* lp = (__nv_bfloat162*)(g_wl + o);
    hp[0] = __nv_bfloat162(h0, h1); hp[1] = __nv_bfloat162(h2, h3);
    lp[0] = __nv_bfloat162(l0, l1); lp[1] = __nv_bfloat162(l2, l3);
}

// ---------------------------------------------------------------------------
// TMA split-bf16 GEMM. Block 128x128, 256 threads, warp tile 64x32.
// K-chunk 64, THREE-stage TMA pipeline (SW128), mbarrier completion.
// mode 0: merged QKV (gridDim.x=24), n0>>10 selects target; mode 3: out proj
// (W rows offset by wbase in the stacked weight tensor).
// ---------------------------------------------------------------------------
#define GB 16384                  // one operand tile: 128 rows x 128B (SW128)
#define GSTG (4*GB)               // AH AL BH BL = 65536
#define GEMM_SMEM (3*GSTG + 1088) // 3 stages + mbars/align

__global__ void __launch_bounds__(256, 1) gemm_tma(
    const __grid_constant__ CUtensorMap mAh,
    const __grid_constant__ CUtensorMap mAl,
    const __grid_constant__ CUtensorMap mWh,
    const __grid_constant__ CUtensorMap mWl,
    const float* __restrict__ b0, const float* __restrict__ b1,
    const float* __restrict__ b2, float* __restrict__ outp,
    int wbase, int mode)
{
    extern __shared__ char smem[];
    const uint32_t sb = (smem_u32(smem) + 1023) & ~1023u;
    const uint32_t mb = sb + 3*GSTG;
    const int t  = threadIdx.x;
    const int m0 = blockIdx.y * 128;
    const int n0 = blockIdx.x * 128;

    if (t == 0) { MBAR_INIT(mb, 1); MBAR_INIT(mb + 8, 1); MBAR_INIT(mb + 16, 1); }
    __syncthreads();

    auto issue = [&](int ck) {
        const uint32_t d   = sb + (uint32_t)(ck % 3) * GSTG;
        const uint32_t bar = mb + (uint32_t)(ck % 3) * 8;
        EXPECT_TX(bar, (uint32_t)GSTG);
        TMA2D(d + 0*GB, &mAh, ck*64, m0, bar);
        TMA2D(d + 1*GB, &mAl, ck*64, m0, bar);
        TMA2D(d + 2*GB, &mWh, ck*64, wbase + n0, bar);
        TMA2D(d + 3*GB, &mWl, ck*64, wbase + n0, bar);
    };
    if (t == 0) { issue(0); issue(1); issue(2); }

    const int wid = t >> 5, l = t & 31;
    const int warpM = wid & 1;
    const int warpN = wid >> 1;
    const int q  = l >> 3, lr = l & 7;

    float acc[16][4];
    #pragma unroll
    for (int i = 0; i < 16; i++)
        #pragma unroll
        for (int j = 0; j < 4; j++) acc[i][j] = 0.f;

    // fragment row offsets (row*128); all rows == lr (mod 8) -> lane-const XOR
    uint32_t arow[4], brow[2];
    #pragma unroll
    for (int mt = 0; mt < 4; mt++) arow[mt] = (uint32_t)(warpM*64 + mt*16 + (q & 1)*8 + lr) * 128;
    #pragma unroll
    for (int np = 0; np < 2; np++) brow[np] = (uint32_t)(warpN*32 + np*16 + (q >> 1)*8 + lr) * 128;
    uint32_t axc[4], bxc[4];
    #pragma unroll
    for (int s = 0; s < 4; s++) {
        axc[s] = (uint32_t)((((q >> 1) + 2*s) ^ lr) * 16);
        bxc[s] = (uint32_t)((((q & 1) + 2*s) ^ lr) * 16);
    }

    int ph0 = 0, ph1 = 0, ph2 = 0;
    for (int ch = 0; ch < DM/64; ch++) {
        const int bsel = ch % 3;
        if (bsel == 0)      { mbar_wait(mb,      (uint32_t)ph0); ph0 ^= 1; }
        else if (bsel == 1) { mbar_wait(mb + 8,  (uint32_t)ph1); ph1 ^= 1; }
        else                { mbar_wait(mb + 16, (uint32_t)ph2); ph2 ^= 1; }
        const uint32_t bs = sb + (uint32_t)bsel * GSTG;

        #pragma unroll
        for (int s = 0; s < 4; s++) {
            uint32_t ah[4][4], alr[4][4];
            #pragma unroll
            for (int mt = 0; mt < 4; mt++) {
                uint32_t ao = arow[mt] + axc[s];
                LDSM4(ah[mt],  bs + 0*GB + ao);
                LDSM4(alr[mt], bs + 1*GB + ao);
            }
            uint32_t bh[2][4], bl[2][4];
            #pragma unroll
            for (int np = 0; np < 2; np++) {
                uint32_t bo = brow[np] + bxc[s];
                LDSM4(bh[np], bs + 2*GB + bo);
                LDSM4(bl[np], bs + 3*GB + bo);
            }
            #pragma unroll
            for (int mt = 0; mt < 4; mt++)
                #pragma unroll
                for (int nt = 0; nt < 4; nt++) {
                    const int np = nt >> 1, h = (nt & 1) * 2;
                    MMA16816(acc[mt*4+nt], ah[mt], bh[np][h], bh[np][h+1]);
                }
            #pragma unroll
            for (int mt = 0; mt < 4; mt++)
                #pragma unroll
                for (int nt = 0; nt < 4; nt++) {
                    const int np = nt >> 1, h = (nt & 1) * 2;
                    MMA16816(acc[mt*4+nt], ah[mt], bl[np][h], bl[np][h+1]);
                }
            #pragma unroll
            for (int mt = 0; mt < 4; mt++)
                #pragma unroll
                for (int nt = 0; nt < 4; nt++) {
                    const int np = nt >> 1, h = (nt & 1) * 2;
                    MMA16816(acc[mt*4+nt], alr[mt], bh[np][h], bh[np][h+1]);
                }
        }
        __syncthreads();
        if (t == 0 && ch + 3 < DM/64) issue(ch + 3);
    }

    // epilogue
    if (mode == 0) {
        const int which = n0 >> 10;
        const float ascale = (which == 0) ? 0.03125f : 1.0f;
        __nv_bfloat16* oh = (which == 0) ? g_qh : (which == 1) ? g_kh : g_vh;
        __nv_bfloat16* ol = (which == 0) ? g_ql : (which == 1) ? g_kl : g_vl;
        const float* bias = (which == 0) ? b0 : (which == 1) ? b1 : b2;
        const int nloc0 = n0 & 1023;
        #pragma unroll
        for (int nt = 0; nt < 4; nt++) {
            const int n = nloc0 + warpN*32 + nt*8 + (l & 3)*2;
            const float bx = bias[n], by = bias[n+1];
            #pragma unroll
            for (int mt = 0; mt < 4; mt++) {
                const float* d = acc[mt*4 + nt];
                #pragma unroll
                for (int half = 0; half < 2; half++) {
                    const int m = m0 + warpM*64 + mt*16 + (l >> 2) + half*8;
                    float vx = (d[half*2 + 0] + bx) * ascale;
                    float vy = (d[half*2 + 1] + by) * ascale;
                    const int bb = m >> 11, s = m & (SS-1);
                    const int hh = n >> 6, dd = n & 63;
                    size_t o = (size_t)((bb*NH + hh)*SS + s)*HD + dd;
                    __nv_bfloat16 hx = __float2bfloat16(vx);
                    __nv_bfloat16 hy = __float2bfloat16(vy);
                    __nv_bfloat16 lx = __float2bfloat16(vx - __bfloat162float(hx));
                    __nv_bfloat16 ly = __float2bfloat16(vy - __bfloat162float(hy));
                    *(__nv_bfloat162*)(oh + o) = __nv_bfloat162(hx, hy);
                    *(__nv_bfloat162*)(ol + o) = __nv_bfloat162(lx, ly);
                }
            }
        }
    } else {
        #pragma unroll
        for (int nt = 0; nt < 4; nt++) {
            const int n = n0 + warpN*32 + nt*8 + (l & 3)*2;
            const float bx = b0[n], by = b0[n+1];
            #pragma unroll
            for (int mt = 0; mt < 4; mt++) {
                const float* d = acc[mt*4 + nt];
                #pragma unroll
                for (int half = 0; half < 2; half++) {
                    const int m = m0 + warpM*64 + mt*16 + (l >> 2) + half*8;
                    float2 v;
                    v.x = d[half*2 + 0] + bx;
                    v.y = d[half*2 + 1] + by;
                    *(float2*)&outp[(size_t)m*DM + n] = v;
                }
            }
        }
    }
}

// ---------------------------------------------------------------------------
// Flash attention on tensor cores (split-bf16, online softmax), TMA staging.
// Block: 64 queries x one (b,h); 128 threads = 4 warps, warp = 16 q rows.
// 2 CTAs/SM (ping-pong: one CTA's MMAs overlap the other's softmax).
// KV tile 64, double-buffered TMA (SW128). Same per-warp math as round 8.
// ---------------------------------------------------------------------------
#define FQB 8192                  // Q array tile: 64 rows x 128B
#define FKB 8192                  // KV array tile: 64 rows x 128B
#define FSTG (4*FKB)              // KH KL VH VL = 32768
#define FL_SMEM (2*FQB + 2*FSTG + 1088)   // 83008 -> 2 CTAs/SM

__global__ void __launch_bounds__(128, 2) flash_tma(
    const __grid_constant__ CUtensorMap mQh,
    const __grid_constant__ CUtensorMap mQl,
    const __grid_constant__ CUtensorMap mKh,
    const __grid_constant__ CUtensorMap mKl,
    const __grid_constant__ CUtensorMap mVh,
    const __grid_constant__ CUtensorMap mVl)
{
    extern __shared__ char fsm[];
    const uint32_t sb  = (smem_u32(fsm) + 1023) & ~1023u;
    const uint32_t kvb = sb + 2*FQB;
    const uint32_t mbq = sb + 2*FQB + 2*FSTG;
    const int bh = blockIdx.y;
    const int q0 = blockIdx.x * 64;
    const int row0 = bh * SS;               // tensor row base for this (b,h)
    const int t = threadIdx.x, wid = t >> 5, l = t & 31;
    const int q = l >> 3, lr = l & 7;
    const int wq0 = wid * 16;

    if (t == 0) { MBAR_INIT(mbq, 1); MBAR_INIT(mbq + 8, 1); MBAR_INIT(mbq + 16, 1); }
    __syncthreads();

    auto kvissue = [&](int ti) {
        const uint32_t d   = kvb + (uint32_t)(ti & 1) * FSTG;
        const uint32_t bar = mbq + 8 + (uint32_t)(ti & 1) * 8;
        EXPECT_TX(bar, (uint32_t)FSTG);
        const int y = row0 + ti*64;
        TMA2D(d + 0*FKB, &mKh, 0, y, bar);
        TMA2D(d + 1*FKB, &mKl, 0, y, bar);
        TMA2D(d + 2*FKB, &mVh, 0, y, bar);
        TMA2D(d + 3*FKB, &mVl, 0, y, bar);
    };
    if (t == 0) {
        EXPECT_TX(mbq, (uint32_t)(2*FQB));
        TMA2D(sb,       &mQh, 0, row0 + q0, mbq);
        TMA2D(sb + FQB, &mQl, 0, row0 + q0, mbq);
        kvissue(0);
        kvissue(1);
    }

    mbar_wait(mbq, 0);

    // Q fragments (persistent): row = wq0 + (q&1)*8 + lr, col16 = (q>>1)+2kt
    uint32_t qhf[4][4], qlf[4][4];
    {
        const uint32_t qrow = (uint32_t)(wq0 + (q & 1)*8 + lr) * 128;
        #pragma unroll
        for (int kt = 0; kt < 4; kt++) {
            const uint32_t c = (uint32_t)((((q >> 1) + 2*kt) ^ lr) * 16);
            LDSM4(qhf[kt], sb + qrow + c);
            LDSM4(qlf[kt], sb + FQB + qrow + c);
        }
    }

    // fragment address invariants for K and V
    uint32_t krow[4], vrow[4], kxc[4], vxc[4];
    #pragma unroll
    for (int np = 0; np < 4; np++) krow[np] = (uint32_t)(np*16 + (q >> 1)*8 + lr) * 128;
    #pragma unroll
    for (int kt = 0; kt < 4; kt++) vrow[kt] = (uint32_t)(kt*16 + (q & 1)*8 + lr) * 128;
    #pragma unroll
    for (int kt = 0; kt < 4; kt++) kxc[kt] = (uint32_t)((((q & 1) + 2*kt) ^ lr) * 16);
    #pragma unroll
    for (int g = 0; g < 4; g++)  vxc[g]  = (uint32_t)(((2*g + (q >> 1)) ^ lr) * 16);

    float oacc[8][4];
    #pragma unroll
    for (int i = 0; i < 8; i++)
        #pragma unroll
        for (int j = 0; j < 4; j++) oacc[i][j] = 0.f;
    float mprev0 = -1e30f, mprev1 = -1e30f, lsum0 = 0.f, lsum1 = 0.f;

    int kvph0 = 0, kvph1 = 0;
    for (int ti = 0; ti < SS/64; ti++) {
        const int bsel = ti & 1;
        if (bsel == 0) { mbar_wait(mbq + 8,  (uint32_t)kvph0); kvph0 ^= 1; }
        else           { mbar_wait(mbq + 16, (uint32_t)kvph1); kvph1 ^= 1; }
        const uint32_t kb = kvb + (uint32_t)bsel * FSTG;

        float sacc[8][4];
        #pragma unroll
        for (int i = 0; i < 8; i++)
            #pragma unroll
            for (int j = 0; j < 4; j++) sacc[i][j] = 0.f;

        #pragma unroll
        for (int kt = 0; kt < 4; kt++) {
            uint32_t khf[4][4], klf[4][4];
            #pragma unroll
            for (int np = 0; np < 4; np++) {
                uint32_t ba = krow[np] + kxc[kt];
                LDSM4(khf[np], kb + 0*FKB + ba);
                LDSM4(klf[np], kb + 1*FKB + ba);
            }
            #pragma unroll
            for (int nt = 0; nt < 8; nt++) {
                const int np = nt >> 1, h = (nt & 1)*2;
                MMA16816(sacc[nt], qhf[kt], khf[np][h], khf[np][h+1]);
            }
            #pragma unroll
            for (int nt = 0; nt < 8; nt++) {
                const int np = nt >> 1, h = (nt & 1)*2;
                MMA16816(sacc[nt], qhf[kt], klf[np][h], klf[np][h+1]);
            }
            #pragma unroll
            for (int nt = 0; nt < 8; nt++) {
                const int np = nt >> 1, h = (nt & 1)*2;
                MMA16816(sacc[nt], qlf[kt], khf[np][h], khf[np][h+1]);
            }
        }

        float m0 = sacc[0][0], m1 = sacc[0][2];
        #pragma unroll
        for (int nt = 0; nt < 8; nt++) {
            m0 = fmaxf(m0, fmaxf(sacc[nt][0], sacc[nt][1]));
            m1 = fmaxf(m1, fmaxf(sacc[nt][2], sacc[nt][3]));
        }
        m0 = fmaxf(m0, __shfl_xor_sync(0xffffffffu, m0, 1));
        m0 = fmaxf(m0, __shfl_xor_sync(0xffffffffu, m0, 2));
        m1 = fmaxf(m1, __shfl_xor_sync(0xffffffffu, m1, 1));
        m1 = fmaxf(m1, __shfl_xor_sync(0xffffffffu, m1, 2));

        const float mn0 = fmaxf(mprev0, m0);
        const float mn1 = fmaxf(mprev1, m1);
        const float a0 = __expf(mprev0 - mn0);
        const float a1 = __expf(mprev1 - mn1);
        mprev0 = mn0; mprev1 = mn1;

        float rs0 = 0.f, rs1 = 0.f;
        #pragma unroll
        for (int nt = 0; nt < 8; nt++) {
            sacc[nt][0] = __expf(sacc[nt][0] - mn0);
            sacc[nt][1] = __expf(sacc[nt][1] - mn0);
            sacc[nt][2] = __expf(sacc[nt][2] - mn1);
            sacc[nt][3] = __expf(sacc[nt][3] - mn1);
            rs0 += sacc[nt][0] + sacc[nt][1];
            rs1 += sacc[nt][2] + sacc[nt][3];
        }
        rs0 += __shfl_xor_sync(0xffffffffu, rs0, 1);
        rs0 += __shfl_xor_sync(0xffffffffu, rs0, 2);
        rs1 += __shfl_xor_sync(0xffffffffu, rs1, 1);
        rs1 += __shfl_xor_sync(0xffffffffu, rs1, 2);
        lsum0 = lsum0*a0 + rs0;
        lsum1 = lsum1*a1 + rs1;
        #pragma unroll
        for (int nj = 0; nj < 8; nj++) {
            oacc[nj][0] *= a0; oacc[nj][1] *= a0;
            oacc[nj][2] *= a1; oacc[nj][3] *= a1;
        }

        #pragma unroll
        for (int kt = 0; kt < 4; kt++) {
            uint32_t ph[4], pl[4];
            #pragma unroll
            for (int e = 0; e < 4; e++) {
                const float* s0 = sacc[2*kt + (e >> 1)];
                const float x0 = s0[(e & 1)*2], x1 = s0[(e & 1)*2 + 1];
                ph[e] = pack_bf(x1, x0);
                pl[e] = pack_bf(x1 - bf_round(x1), x0 - bf_round(x0));
            }
            uint32_t vhf[4][4], vlf[4][4];
            #pragma unroll
            for (int g = 0; g < 4; g++) {
                uint32_t va = vrow[kt] + vxc[g];
                LDSM4T(vhf[g], kb + 2*FKB + va);
                LDSM4T(vlf[g], kb + 3*FKB + va);
            }
            #pragma unroll
            for (int nj = 0; nj < 8; nj++) {
                const int g = nj >> 1, o = (nj & 1)*2;
                MMA16816(oacc[nj], ph, vhf[g][o], vhf[g][o+1]);
            }
            #pragma unroll
            for (int nj = 0; nj < 8; nj++) {
                const int g = nj >> 1, o = (nj & 1)*2;
                MMA16816(oacc[nj], ph, vlf[g][o], vlf[g][o+1]);
            }
            #pragma unroll
            for (int nj = 0; nj < 8; nj++) {
                const int g = nj >> 1, o = (nj & 1)*2;
                MMA16816(oacc[nj], pl, vhf[g][o], vhf[g][o+1]);
            }
        }

        __syncthreads();
        if (t == 0 && ti + 2 < SS/64) kvissue(ti + 2);
    }

    const float inv0 = 1.0f / lsum0;
    const float inv1 = 1.0f / lsum1;
    const int r0 = q0 + wq0 + (l >> 2);
    const int bb = bh >> 4, hh = bh & 15;
    #pragma unroll
    for (int nj = 0; nj < 8; nj++) {
        const int col = hh*HD + nj*8 + (l & 3)*2;
        {
            const float e0 = oacc[nj][0]*inv0, e1 = oacc[nj][1]*inv0;
            __nv_bfloat16 h0 = __float2bfloat16(e0), h1 = __float2bfloat16(e1);
            __nv_bfloat16 l0 = __float2bfloat16(e0 - __bfloat162float(h0));
            __nv_bfloat16 l1 = __float2bfloat16(e1 - __bfloat162float(h1));
            size_t o = (size_t)(bb*SS + r0)*DM + col;
            *(__nv_bfloat162*)(g_ah + o) = __nv_bfloat162(h0, h1);
            *(__nv_bfloat162*)(g_al + o) = __nv_bfloat162(l0, l1);
        }
        {
            const float e0 = oacc[nj][2]*inv1, e1 = oacc[nj][3]*inv1;
            __nv_bfloat16 h0 = __float2bfloat16(e0), h1 = __float2bfloat16(e1);
            __nv_bfloat16 l0 = __float2bfloat16(e0 - __bfloat162float(h0));
            __nv_bfloat16 l1 = __float2bfloat16(e1 - __bfloat162float(h1));
            size_t o = (size_t)(bb*SS + r0 + 8)*DM + col;
            *(__nv_bfloat162*)(g_ah + o) = __nv_bfloat162(h0, h1);
            *(__nv_bfloat162*)(g_al + o) = __nv_bfloat162(l0, l1);
        }
    }
}

// ---------------------------------------------------------------------------
// host: tensor-map construction via driver entry point (no -lcuda needed)
// ---------------------------------------------------------------------------
typedef CUresult (CUDAAPI *PFN_encodeTiled)(
    CUtensorMap*, CUtensorMapDataType, cuuint32_t, void*,
    const cuuint64_t*, const cuuint64_t*, const cuuint32_t*, const cuuint32_t*,
    CUtensorMapInterleave, CUtensorMapSwizzle, CUtensorMapL2promotion,
    CUtensorMapFloatOOBfill);

static PFN_encodeTiled get_encoder() {
    static PFN_encodeTiled fn = nullptr;
    if (!fn) {
        void* p = nullptr;
        cudaDriverEntryPointQueryResult qr;
        cudaGetDriverEntryPoint("cuTensorMapEncodeTiled", &p, cudaEnableDefault, &qr);
        fn = (PFN_encodeTiled)p;
    }
    return fn;
}

static void mk2d(CUtensorMap* m, void* base, uint64_t d0, uint64_t rows,
                 uint32_t b0, uint32_t b1) {
    cuuint64_t dims[2]    = {d0, rows};
    cuuint64_t strides[1] = {d0 * 2};     // bytes
    cuuint32_t box[2]     = {b0, b1};
    cuuint32_t es[2]      = {1, 1};
    get_encoder()(m, CU_TENSOR_MAP_DATA_TYPE_BFLOAT16, 2, base,
                  dims, strides, box, es,
                  CU_TENSOR_MAP_INTERLEAVE_NONE, CU_TENSOR_MAP_SWIZZLE_128B,
                  CU_TENSOR_MAP_L2_PROMOTION_L2_128B,
                  CU_TENSOR_MAP_FLOAT_OOB_FILL_NONE);
}

extern "C" void kernel_launch(void* const* d_in, const int* in_sizes, int n_in,
                              void* d_out, int out_size) {
    const float* x     = (const float*)d_in[0];
    const float* rel   = (const float*)d_in[1];
    const float* alpha = (const float*)d_in[2];
    const float* Wq    = (const float*)d_in[3];
    const float* bq    = (const float*)d_in[4];
    const float* Wk    = (const float*)d_in[5];
    const float* bk    = (const float*)d_in[6];
    const float* Wv    = (const float*)d_in[7];
    const float* bv    = (const float*)d_in[8];
    const float* Wo    = (const float*)d_in[9];
    const float* bo    = (const float*)d_in[10];
    float* out = (float*)d_out;

    cudaFuncSetAttribute(gemm_tma,  cudaFuncAttributeMaxDynamicSharedMemorySize, GEMM_SMEM);
    cudaFuncSetAttribute(flash_tma, cudaFuncAttributeMaxDynamicSharedMemorySize, FL_SMEM);

    void *ah, *al, *wh, *wl, *qh, *ql, *kh, *kl, *vh, *vl;
    cudaGetSymbolAddress(&ah, g_ah);
    cudaGetSymbolAddress(&al, g_al);
    cudaGetSymbolAddress(&wh, g_wh);
    cudaGetSymbolAddress(&wl, g_wl);
    cudaGetSymbolAddress(&qh, g_qh);
    cudaGetSymbolAddress(&ql, g_ql);
    cudaGetSymbolAddress(&kh, g_kh);
    cudaGetSymbolAddress(&kl, g_kl);
    cudaGetSymbolAddress(&vh, g_vh);
    cudaGetSymbolAddress(&vl, g_vl);

    CUtensorMap mAh, mAl, mWh, mWl, mQh, mQl, mKh, mKl, mVh, mVl;
    mk2d(&mAh, ah, DM, MT,          64, 128);
    mk2d(&mAl, al, DM, MT,          64, 128);
    mk2d(&mWh, wh, DM, 4*DM,        64, 128);
    mk2d(&mWl, wl, DM, 4*DM,        64, 128);
    mk2d(&mQh, qh, HD, BB*NH*SS,    64, 64);
    mk2d(&mQl, ql, HD, BB*NH*SS,    64, 64);
    mk2d(&mKh, kh, HD, BB*NH*SS,    64, 64);
    mk2d(&mKl, kl, HD, BB*NH*SS,    64, 64);
    mk2d(&mVh, vh, HD, BB*NH*SS,    64, 64);
    mk2d(&mVl, vl, HD, BB*NH*SS,    64, 64);

    pe_split_kernel<<<(MT*(DM/2) + 255)/256, 256>>>(x, rel, alpha);
    split4_kernel<<<(4*NW4 + 255)/256, 256>>>(Wq, Wk, Wv, Wo);

    gemm_tma<<<dim3(3*DM/128, MT/128), 256, GEMM_SMEM>>>(
        mAh, mAl, mWh, mWl, bq, bk, bv, nullptr, 0, 0);

    flash_tma<<<dim3(SS/64, BB*NH), 128, FL_SMEM>>>(mQh, mQl, mKh, mKl, mVh, mVl);

    gemm_tma<<<dim3(DM/128, MT/128), 256, GEMM_SMEM>>>(
        mAh, mAl, mWh, mWl, bo, bo, bo, out, 3*DM, 3);
}

// round 10
// speedup vs baseline: 1.1541x; 1.0672x over previous
#include <cuda_runtime.h>
#include <cuda.h>
#include <cuda_bf16.h>
#include <math.h>
#include <stdint.h>

#define DM 1024
#define NH 16
#define HD 64
#define MSL 5000
#define BB 2
#define SS 2048
#define MT (BB*SS)   // 4096 rows total

// Scratch (allocation-free rule: device globals)
__device__ __nv_bfloat16 g_ah[MT*DM];     // GEMM A hi (xpe-split, later o-split)
__device__ __nv_bfloat16 g_al[MT*DM];     // GEMM A lo
__device__ __nv_bfloat16 g_wh[4*DM*DM];   // stacked Wq|Wk|Wv|Wo hi
__device__ __nv_bfloat16 g_wl[4*DM*DM];
// split-bf16 Q/K/V in [B,H,S,hd] (Q pre-scaled by 1/32)
__device__ __nv_bfloat16 g_qh[MT*DM];
__device__ __nv_bfloat16 g_ql[MT*DM];
__device__ __nv_bfloat16 g_kh[MT*DM];
__device__ __nv_bfloat16 g_kl[MT*DM];
__device__ __nv_bfloat16 g_vh[MT*DM];
__device__ __nv_bfloat16 g_vl[MT*DM];

// ---------------------------------------------------------------------------
// helpers
// ---------------------------------------------------------------------------
__device__ __forceinline__ uint32_t smem_u32(const void* p) {
    uint32_t a;
    asm("{ .reg .u64 t; cvta.to.shared.u64 t, %1; cvt.u32.u64 %0, t; }" : "=r"(a) : "l"(p));
    return a;
}

#define MBAR_INIT(addr, cnt) \
    asm volatile("mbarrier.init.shared.b64 [%0], %1;" :: "r"(addr), "r"(cnt) : "memory")

#define EXPECT_TX(addr, bytes) \
    asm volatile("mbarrier.arrive.expect_tx.shared.b64 _, [%0], %1;" :: "r"(addr), "r"(bytes) : "memory")

#define TMA2D(smem, mapp, x, y, mbar) \
    asm volatile("cp.async.bulk.tensor.2d.shared::cluster.global.tile.mbarrier::complete_tx::bytes " \
        "[%0], [%1, {%2, %3}], [%4];" \
        :: "r"(smem), "l"(mapp), "r"(x), "r"(y), "r"(mbar) : "memory")

__device__ __forceinline__ void mbar_wait(uint32_t addr, uint32_t parity) {
    uint32_t done;
    asm volatile(
        "{\n\t.reg .pred p;\n\t"
        "mbarrier.try_wait.parity.shared.b64 p, [%1], %2;\n\t"
        "selp.b32 %0,1,0,p;\n\t}"
        : "=r"(done) : "r"(addr), "r"(parity) : "memory");
    while (!done) {
        asm volatile(
            "{\n\t.reg .pred p;\n\t"
            "mbarrier.try_wait.parity.shared.b64 p, [%1], %2, 0x989680;\n\t"
            "selp.b32 %0,1,0,p;\n\t}"
            : "=r"(done) : "r"(addr), "r"(parity) : "memory");
    }
}

#define LDSM4(r, addr) \
    asm volatile("ldmatrix.sync.aligned.m8n8.x4.shared.b16 {%0,%1,%2,%3}, [%4];" \
        : "=r"((r)[0]), "=r"((r)[1]), "=r"((r)[2]), "=r"((r)[3]) : "r"(addr))

#define LDSM4T(r, addr) \
    asm volatile("ldmatrix.sync.aligned.m8n8.x4.trans.shared.b16 {%0,%1,%2,%3}, [%4];" \
        : "=r"((r)[0]), "=r"((r)[1]), "=r"((r)[2]), "=r"((r)[3]) : "r"(addr))

#define MMA16816(d, a, b0v, b1v) \
    asm volatile("mma.sync.aligned.m16n8k16.row.col.f32.bf16.bf16.f32 " \
        "{%0,%1,%2,%3}, {%4,%5,%6,%7}, {%8,%9}, {%0,%1,%2,%3};" \
        : "+f"((d)[0]), "+f"((d)[1]), "+f"((d)[2]), "+f"((d)[3]) \
        : "r"((a)[0]), "r"((a)[1]), "r"((a)[2]), "r"((a)[3]), "r"(b0v), "r"(b1v))

__device__ __forceinline__ uint32_t pack_bf(float hi, float lo) {
    uint32_t d;
    asm("cvt.rn.bf16x2.f32 %0, %1, %2;" : "=r"(d) : "f"(hi), "f"(lo));
    return d;
}
__device__ __forceinline__ float bf_round(float v) {
    return __bfloat162float(__float2bfloat16(v));
}

// ---------------------------------------------------------------------------
// Kernel 1: fused PE + split:  (x + a*sin_pe + (1-a)*rel) -> (g_ah, g_al)
// ---------------------------------------------------------------------------
__global__ void pe_split_kernel(const float* __restrict__ x,
                                const float* __restrict__ rel,
                                const float* __restrict__ alphap) {
    int idx = blockIdx.x*blockDim.x + threadIdx.x;
    if (idx >= MT*(DM/2)) return;
    int m  = idx >> 9;
    int pp = idx & 511;
    int s  = m & (SS-1);
    float a = alphap[0];
    float freq = __expf(-(float)(2*pp) * (9.210340371976184f/(float)DM));
    float ang = (float)s * freq;
    float sn, cs;
    sincosf(ang, &sn, &cs);
    const float* rr = rel + (size_t)(MSL - SS + s)*DM + 2*pp;
    float2 xv = *(const float2*)(x + (size_t)idx*2);
    float om = 1.0f - a;
    float ox = xv.x + a*sn + om*rr[0];
    float oy = xv.y + a*cs + om*rr[1];
    __nv_bfloat16 hx = __float2bfloat16(ox);
    __nv_bfloat16 hy = __float2bfloat16(oy);
    __nv_bfloat16 lx = __float2bfloat16(ox - __bfloat162float(hx));
    __nv_bfloat16 ly = __float2bfloat16(oy - __bfloat162float(hy));
    *(__nv_bfloat162*)(g_ah + (size_t)idx*2) = __nv_bfloat162(hx, hy);
    *(__nv_bfloat162*)(g_al + (size_t)idx*2) = __nv_bfloat162(lx, ly);
}

// ---------------------------------------------------------------------------
// Kernel 2: all four weight matrices -> (hi, lo) bf16 split in one launch.
// ---------------------------------------------------------------------------
#define NW4 (DM*DM/4)   // 262144 float4 per matrix
__global__ void split4_kernel(const float* __restrict__ w0,
                              const float* __restrict__ w1,
                              const float* __restrict__ w2,
                              const float* __restrict__ w3) {
    int i = blockIdx.x*blockDim.x + threadIdx.x;
    if (i >= 4*NW4) return;
    const int which = i >> 18;            // NW4 = 2^18
    const int j = i & (NW4 - 1);
    const float* src = (which == 0) ? w0 : (which == 1) ? w1 : (which == 2) ? w2 : w3;
    float4 v = ((const float4*)src)[j];
    __nv_bfloat16 h0 = __float2bfloat16(v.x);
    __nv_bfloat16 h1 = __float2bfloat16(v.y);
    __nv_bfloat16 h2 = __float2bfloat16(v.z);
    __nv_bfloat16 h3 = __float2bfloat16(v.w);
    __nv_bfloat16 l0 = __float2bfloat16(v.x - __bfloat162float(h0));
    __nv_bfloat16 l1 = __float2bfloat16(v.y - __bfloat162float(h1));
    __nv_bfloat16 l2 = __float2bfloat16(v.z - __bfloat162float(h2));
    __nv_bfloat16 l3 = __float2bfloat16(v.w - __bfloat162float(h3));
    size_t o = (size_t)which*DM*DM + (size_t)j*4;
    __nv_bfloat162* hp = (__nv_bfloat162*)(g_wh + o);
    __nv_bfloat162* lp = (__nv_bfloat162*)(g_wl + o);
    hp[0] = __nv_bfloat162(h0, h1); hp[1] = __nv_bfloat162(h2, h3);
    lp[0] = __nv_bfloat162(l0, l1); lp[1] = __nv_bfloat162(l2, l3);
}

// ---------------------------------------------------------------------------
// TMA split-bf16 GEMM. Block 128x64, 128 threads (4 warps 2Mx2N),
// warp tile 64x32 (identical inner loops to round 9). K-chunk 64,
// 2-stage TMA, smem 99KB -> 2 CTAs/SM ping-pong.
// mode 0: merged QKV (gridDim.x=48), n0>>10 selects target; mode 3: out proj.
// ---------------------------------------------------------------------------
#define GA 16384                  // A operand tile: 128 rows x 128B (SW128)
#define GW 8192                   // W operand tile: 64 rows x 128B
#define GSTG (2*GA + 2*GW)        // AH AL WH WL = 49152
#define GEMM_SMEM (2*GSTG + 1088) // 2 stages + mbars/align = 99392

__global__ void __launch_bounds__(128, 2) gemm_tma(
    const __grid_constant__ CUtensorMap mAh,
    const __grid_constant__ CUtensorMap mAl,
    const __grid_constant__ CUtensorMap mWh,
    const __grid_constant__ CUtensorMap mWl,
    const float* __restrict__ b0, const float* __restrict__ b1,
    const float* __restrict__ b2, float* __restrict__ outp,
    int wbase, int mode)
{
    extern __shared__ char smem[];
    const uint32_t sb = (smem_u32(smem) + 1023) & ~1023u;
    const uint32_t mb = sb + 2*GSTG;
    const int t  = threadIdx.x;
    const int m0 = blockIdx.y * 128;
    const int n0 = blockIdx.x * 64;

    if (t == 0) { MBAR_INIT(mb, 1); MBAR_INIT(mb + 8, 1); }
    __syncthreads();

    auto issue = [&](int ck) {
        const uint32_t d   = sb + (uint32_t)(ck & 1) * GSTG;
        const uint32_t bar = mb + (uint32_t)(ck & 1) * 8;
        EXPECT_TX(bar, (uint32_t)GSTG);
        TMA2D(d + 0,         &mAh, ck*64, m0, bar);
        TMA2D(d + GA,        &mAl, ck*64, m0, bar);
        TMA2D(d + 2*GA,      &mWh, ck*64, wbase + n0, bar);
        TMA2D(d + 2*GA + GW, &mWl, ck*64, wbase + n0, bar);
    };
    if (t == 0) { issue(0); issue(1); }

    const int wid = t >> 5, l = t & 31;
    const int warpM = wid & 1;
    const int warpN = wid >> 1;          // 0..1
    const int q  = l >> 3, lr = l & 7;

    float acc[16][4];
    #pragma unroll
    for (int i = 0; i < 16; i++)
        #pragma unroll
        for (int j = 0; j < 4; j++) acc[i][j] = 0.f;

    // fragment row offsets (row*128); all rows == lr (mod 8) -> lane-const XOR
    uint32_t arow[4], brow[2];
    #pragma unroll
    for (int mt = 0; mt < 4; mt++) arow[mt] = (uint32_t)(warpM*64 + mt*16 + (q & 1)*8 + lr) * 128;
    #pragma unroll
    for (int np = 0; np < 2; np++) brow[np] = (uint32_t)(warpN*32 + np*16 + (q >> 1)*8 + lr) * 128;
    uint32_t axc[4], bxc[4];
    #pragma unroll
    for (int s = 0; s < 4; s++) {
        axc[s] = (uint32_t)((((q >> 1) + 2*s) ^ lr) * 16);
        bxc[s] = (uint32_t)((((q & 1) + 2*s) ^ lr) * 16);
    }

    int ph0 = 0, ph1 = 0;
    for (int ch = 0; ch < DM/64; ch++) {
        const int bsel = ch & 1;
        if (bsel == 0) { mbar_wait(mb,     (uint32_t)ph0); ph0 ^= 1; }
        else           { mbar_wait(mb + 8, (uint32_t)ph1); ph1 ^= 1; }
        const uint32_t bs = sb + (uint32_t)bsel * GSTG;

        #pragma unroll
        for (int s = 0; s < 4; s++) {
            uint32_t ah[4][4], alr[4][4];
            #pragma unroll
            for (int mt = 0; mt < 4; mt++) {
                uint32_t ao = arow[mt] + axc[s];
                LDSM4(ah[mt],  bs + 0  + ao);
                LDSM4(alr[mt], bs + GA + ao);
            }
            uint32_t bh[2][4], bl[2][4];
            #pragma unroll
            for (int np = 0; np < 2; np++) {
                uint32_t bo = brow[np] + bxc[s];
                LDSM4(bh[np], bs + 2*GA      + bo);
                LDSM4(bl[np], bs + 2*GA + GW + bo);
            }
            #pragma unroll
            for (int mt = 0; mt < 4; mt++)
                #pragma unroll
                for (int nt = 0; nt < 4; nt++) {
                    const int np = nt >> 1, h = (nt & 1) * 2;
                    MMA16816(acc[mt*4+nt], ah[mt], bh[np][h], bh[np][h+1]);
                }
            #pragma unroll
            for (int mt = 0; mt < 4; mt++)
                #pragma unroll
                for (int nt = 0; nt < 4; nt++) {
                    const int np = nt >> 1, h = (nt & 1) * 2;
                    MMA16816(acc[mt*4+nt], ah[mt], bl[np][h], bl[np][h+1]);
                }
            #pragma unroll
            for (int mt = 0; mt < 4; mt++)
                #pragma unroll
                for (int nt = 0; nt < 4; nt++) {
                    const int np = nt >> 1, h = (nt & 1) * 2;
                    MMA16816(acc[mt*4+nt], alr[mt], bh[np][h], bh[np][h+1]);
                }
        }
        __syncthreads();
        if (t == 0 && ch + 2 < DM/64) issue(ch + 2);
    }

    // epilogue
    if (mode == 0) {
        const int which = n0 >> 10;
        const float ascale = (which == 0) ? 0.03125f : 1.0f;
        __nv_bfloat16* oh = (which == 0) ? g_qh : (which == 1) ? g_kh : g_vh;
        __nv_bfloat16* ol = (which == 0) ? g_ql : (which == 1) ? g_kl : g_vl;
        const float* bias = (which == 0) ? b0 : (which == 1) ? b1 : b2;
        const int nloc0 = n0 & 1023;
        #pragma unroll
        for (int nt = 0; nt < 4; nt++) {
            const int n = nloc0 + warpN*32 + nt*8 + (l & 3)*2;
            const float bx = bias[n], by = bias[n+1];
            #pragma unroll
            for (int mt = 0; mt < 4; mt++) {
                const float* d = acc[mt*4 + nt];
                #pragma unroll
                for (int half = 0; half < 2; half++) {
                    const int m = m0 + warpM*64 + mt*16 + (l >> 2) + half*8;
                    float vx = (d[half*2 + 0] + bx) * ascale;
                    float vy = (d[half*2 + 1] + by) * ascale;
                    const int bb = m >> 11, s = m & (SS-1);
                    const int hh = n >> 6, dd = n & 63;
                    size_t o = (size_t)((bb*NH + hh)*SS + s)*HD + dd;
                    __nv_bfloat16 hx = __float2bfloat16(vx);
                    __nv_bfloat16 hy = __float2bfloat16(vy);
                    __nv_bfloat16 lx = __float2bfloat16(vx - __bfloat162float(hx));
                    __nv_bfloat16 ly = __float2bfloat16(vy - __bfloat162float(hy));
                    *(__nv_bfloat162*)(oh + o) = __nv_bfloat162(hx, hy);
                    *(__nv_bfloat162*)(ol + o) = __nv_bfloat162(lx, ly);
                }
            }
        }
    } else {
        #pragma unroll
        for (int nt = 0; nt < 4; nt++) {
            const int n = n0 + warpN*32 + nt*8 + (l & 3)*2;
            const float bx = b0[n], by = b0[n+1];
            #pragma unroll
            for (int mt = 0; mt < 4; mt++) {
                const float* d = acc[mt*4 + nt];
                #pragma unroll
                for (int half = 0; half < 2; half++) {
                    const int m = m0 + warpM*64 + mt*16 + (l >> 2) + half*8;
                    float2 v;
                    v.x = d[half*2 + 0] + bx;
                    v.y = d[half*2 + 1] + by;
                    *(float2*)&outp[(size_t)m*DM + n] = v;
                }
            }
        }
    }
}

// ---------------------------------------------------------------------------
// Flash attention on tensor cores (split-bf16, online softmax), TMA staging.
// Block: 64 queries x one (b,h); 128 threads = 4 warps, warp = 16 q rows.
// 2 CTAs/SM (ping-pong). KV tile 64, double-buffered TMA (SW128).
// ---------------------------------------------------------------------------
#define FQB 8192                  // Q array tile: 64 rows x 128B
#define FKB 8192                  // KV array tile: 64 rows x 128B
#define FSTG (4*FKB)              // KH KL VH VL = 32768
#define FL_SMEM (2*FQB + 2*FSTG + 1088)   // 83008 -> 2 CTAs/SM

__global__ void __launch_bounds__(128, 2) flash_tma(
    const __grid_constant__ CUtensorMap mQh,
    const __grid_constant__ CUtensorMap mQl,
    const __grid_constant__ CUtensorMap mKh,
    const __grid_constant__ CUtensorMap mKl,
    const __grid_constant__ CUtensorMap mVh,
    const __grid_constant__ CUtensorMap mVl)
{
    extern __shared__ char fsm[];
    const uint32_t sb  = (smem_u32(fsm) + 1023) & ~1023u;
    const uint32_t kvb = sb + 2*FQB;
    const uint32_t mbq = sb + 2*FQB + 2*FSTG;
    const int bh = blockIdx.y;
    const int q0 = blockIdx.x * 64;
    const int row0 = bh * SS;               // tensor row base for this (b,h)
    const int t = threadIdx.x, wid = t >> 5, l = t & 31;
    const int q = l >> 3, lr = l & 7;
    const int wq0 = wid * 16;

    if (t == 0) { MBAR_INIT(mbq, 1); MBAR_INIT(mbq + 8, 1); MBAR_INIT(mbq + 16, 1); }
    __syncthreads();

    auto kvissue = [&](int ti) {
        const uint32_t d   = kvb + (uint32_t)(ti & 1) * FSTG;
        const uint32_t bar = mbq + 8 + (uint32_t)(ti & 1) * 8;
        EXPECT_TX(bar, (uint32_t)FSTG);
        const int y = row0 + ti*64;
        TMA2D(d + 0*FKB, &mKh, 0, y, bar);
        TMA2D(d + 1*FKB, &mKl, 0, y, bar);
        TMA2D(d + 2*FKB, &mVh, 0, y, bar);
        TMA2D(d + 3*FKB, &mVl, 0, y, bar);
    };
    if (t == 0) {
        EXPECT_TX(mbq, (uint32_t)(2*FQB));
        TMA2D(sb,       &mQh, 0, row0 + q0, mbq);
        TMA2D(sb + FQB, &mQl, 0, row0 + q0, mbq);
        kvissue(0);
        kvissue(1);
    }

    mbar_wait(mbq, 0);

    // Q fragments (persistent): row = wq0 + (q&1)*8 + lr, col16 = (q>>1)+2kt
    uint32_t qhf[4][4], qlf[4][4];
    {
        const uint32_t qrow = (uint32_t)(wq0 + (q & 1)*8 + lr) * 128;
        #pragma unroll
        for (int kt = 0; kt < 4; kt++) {
            const uint32_t c = (uint32_t)((((q >> 1) + 2*kt) ^ lr) * 16);
            LDSM4(qhf[kt], sb + qrow + c);
            LDSM4(qlf[kt], sb + FQB + qrow + c);
        }
    }

    // fragment address invariants for K and V
    uint32_t krow[4], vrow[4], kxc[4], vxc[4];
    #pragma unroll
    for (int np = 0; np < 4; np++) krow[np] = (uint32_t)(np*16 + (q >> 1)*8 + lr) * 128;
    #pragma unroll
    for (int kt = 0; kt < 4; kt++) vrow[kt] = (uint32_t)(kt*16 + (q & 1)*8 + lr) * 128;
    #pragma unroll
    for (int kt = 0; kt < 4; kt++) kxc[kt] = (uint32_t)((((q & 1) + 2*kt) ^ lr) * 16);
    #pragma unroll
    for (int g = 0; g < 4; g++)  vxc[g]  = (uint32_t)(((2*g + (q >> 1)) ^ lr) * 16);

    float oacc[8][4];
    #pragma unroll
    for (int i = 0; i < 8; i++)
        #pragma unroll
        for (int j = 0; j < 4; j++) oacc[i][j] = 0.f;
    float mprev0 = -1e30f, mprev1 = -1e30f, lsum0 = 0.f, lsum1 = 0.f;

    int kvph0 = 0, kvph1 = 0;
    for (int ti = 0; ti < SS/64; ti++) {
        const int bsel = ti & 1;
        if (bsel == 0) { mbar_wait(mbq + 8,  (uint32_t)kvph0); kvph0 ^= 1; }
        else           { mbar_wait(mbq + 16, (uint32_t)kvph1); kvph1 ^= 1; }
        const uint32_t kb = kvb + (uint32_t)bsel * FSTG;

        float sacc[8][4];
        #pragma unroll
        for (int i = 0; i < 8; i++)
            #pragma unroll
            for (int j = 0; j < 4; j++) sacc[i][j] = 0.f;

        #pragma unroll
        for (int kt = 0; kt < 4; kt++) {
            uint32_t khf[4][4], klf[4][4];
            #pragma unroll
            for (int np = 0; np < 4; np++) {
                uint32_t ba = krow[np] + kxc[kt];
                LDSM4(khf[np], kb + 0*FKB + ba);
                LDSM4(klf[np], kb + 1*FKB + ba);
            }
            #pragma unroll
            for (int nt = 0; nt < 8; nt++) {
                const int np = nt >> 1, h = (nt & 1)*2;
                MMA16816(sacc[nt], qhf[kt], khf[np][h], khf[np][h+1]);
            }
            #pragma unroll
            for (int nt = 0; nt < 8; nt++) {
                const int np = nt >> 1, h = (nt & 1)*2;
                MMA16816(sacc[nt], qhf[kt], klf[np][h], klf[np][h+1]);
            }
            #pragma unroll
            for (int nt = 0; nt < 8; nt++) {
                const int np = nt >> 1, h = (nt & 1)*2;
                MMA16816(sacc[nt], qlf[kt], khf[np][h], khf[np][h+1]);
            }
        }

        float m0 = sacc[0][0], m1 = sacc[0][2];
        #pragma unroll
        for (int nt = 0; nt < 8; nt++) {
            m0 = fmaxf(m0, fmaxf(sacc[nt][0], sacc[nt][1]));
            m1 = fmaxf(m1, fmaxf(sacc[nt][2], sacc[nt][3]));
        }
        m0 = fmaxf(m0, __shfl_xor_sync(0xffffffffu, m0, 1));
        m0 = fmaxf(m0, __shfl_xor_sync(0xffffffffu, m0, 2));
        m1 = fmaxf(m1, __shfl_xor_sync(0xffffffffu, m1, 1));
        m1 = fmaxf(m1, __shfl_xor_sync(0xffffffffu, m1, 2));

        const float mn0 = fmaxf(mprev0, m0);
        const float mn1 = fmaxf(mprev1, m1);
        const float a0 = __expf(mprev0 - mn0);
        const float a1 = __expf(mprev1 - mn1);
        mprev0 = mn0; mprev1 = mn1;

        float rs0 = 0.f, rs1 = 0.f;
        #pragma unroll
        for (int nt = 0; nt < 8; nt++) {
            sacc[nt][0] = __expf(sacc[nt][0] - mn0);
            sacc[nt][1] = __expf(sacc[nt][1] - mn0);
            sacc[nt][2] = __expf(sacc[nt][2] - mn1);
            sacc[nt][3] = __expf(sacc[nt][3] - mn1);
            rs0 += sacc[nt][0] + sacc[nt][1];
            rs1 += sacc[nt][2] + sacc[nt][3];
        }
        rs0 += __shfl_xor_sync(0xffffffffu, rs0, 1);
        rs0 += __shfl_xor_sync(0xffffffffu, rs0, 2);
        rs1 += __shfl_xor_sync(0xffffffffu, rs1, 1);
        rs1 += __shfl_xor_sync(0xffffffffu, rs1, 2);
        lsum0 = lsum0*a0 + rs0;
        lsum1 = lsum1*a1 + rs1;
        #pragma unroll
        for (int nj = 0; nj < 8; nj++) {
            oacc[nj][0] *= a0; oacc[nj][1] *= a0;
            oacc[nj][2] *= a1; oacc[nj][3] *= a1;
        }

        #pragma unroll
        for (int kt = 0; kt < 4; kt++) {
            uint32_t ph[4], pl[4];
            #pragma unroll
            for (int e = 0; e < 4; e++) {
                const float* s0 = sacc[2*kt + (e >> 1)];
                const float x0 = s0[(e & 1)*2], x1 = s0[(e & 1)*2 + 1];
                ph[e] = pack_bf(x1, x0);
                pl[e] = pack_bf(x1 - bf_round(x1), x0 - bf_round(x0));
            }
            uint32_t vhf[4][4], vlf[4][4];
            #pragma unroll
            for (int g = 0; g < 4; g++) {
                uint32_t va = vrow[kt] + vxc[g];
                LDSM4T(vhf[g], kb + 2*FKB + va);
                LDSM4T(vlf[g], kb + 3*FKB + va);
            }
            #pragma unroll
            for (int nj = 0; nj < 8; nj++) {
                const int g = nj >> 1, o = (nj & 1)*2;
                MMA16816(oacc[nj], ph, vhf[g][o], vhf[g][o+1]);
            }
            #pragma unroll
            for (int nj = 0; nj < 8; nj++) {
                const int g = nj >> 1, o = (nj & 1)*2;
                MMA16816(oacc[nj], ph, vlf[g][o], vlf[g][o+1]);
            }
            #pragma unroll
            for (int nj = 0; nj < 8; nj++) {
                const int g = nj >> 1, o = (nj & 1)*2;
                MMA16816(oacc[nj], pl, vhf[g][o], vhf[g][o+1]);
            }
        }

        __syncthreads();
        if (t == 0 && ti + 2 < SS/64) kvissue(ti + 2);
    }

    const float inv0 = 1.0f / lsum0;
    const float inv1 = 1.0f / lsum1;
    const int r0 = q0 + wq0 + (l >> 2);
    const int bb = bh >> 4, hh = bh & 15;
    #pragma unroll
    for (int nj = 0; nj < 8; nj++) {
        const int col = hh*HD + nj*8 + (l & 3)*2;
        {
            const float e0 = oacc[nj][0]*inv0, e1 = oacc[nj][1]*inv0;
            __nv_bfloat16 h0 = __float2bfloat16(e0), h1 = __float2bfloat16(e1);
            __nv_bfloat16 l0 = __float2bfloat16(e0 - __bfloat162float(h0));
            __nv_bfloat16 l1 = __float2bfloat16(e1 - __bfloat162float(h1));
            size_t o = (size_t)(bb*SS + r0)*DM + col;
            *(__nv_bfloat162*)(g_ah + o) = __nv_bfloat162(h0, h1);
            *(__nv_bfloat162*)(g_al + o) = __nv_bfloat162(l0, l1);
        }
        {
            const float e0 = oacc[nj][2]*inv1, e1 = oacc[nj][3]*inv1;
            __nv_bfloat16 h0 = __float2bfloat16(e0), h1 = __float2bfloat16(e1);
            __nv_bfloat16 l0 = __float2bfloat16(e0 - __bfloat162float(h0));
            __nv_bfloat16 l1 = __float2bfloat16(e1 - __bfloat162float(h1));
            size_t o = (size_t)(bb*SS + r0 + 8)*DM + col;
            *(__nv_bfloat162*)(g_ah + o) = __nv_bfloat162(h0, h1);
            *(__nv_bfloat162*)(g_al + o) = __nv_bfloat162(l0, l1);
        }
    }
}

// ---------------------------------------------------------------------------
// host: tensor-map construction via driver entry point (no -lcuda needed)
// ---------------------------------------------------------------------------
typedef CUresult (CUDAAPI *PFN_encodeTiled)(
    CUtensorMap*, CUtensorMapDataType, cuuint32_t, void*,
    const cuuint64_t*, const cuuint64_t*, const cuuint32_t*, const cuuint32_t*,
    CUtensorMapInterleave, CUtensorMapSwizzle, CUtensorMapL2promotion,
    CUtensorMapFloatOOBfill);

static PFN_encodeTiled get_encoder() {
    static PFN_encodeTiled fn = nullptr;
    if (!fn) {
        void* p = nullptr;
        cudaDriverEntryPointQueryResult qr;
        cudaGetDriverEntryPoint("cuTensorMapEncodeTiled", &p, cudaEnableDefault, &qr);
        fn = (PFN_encodeTiled)p;
    }
    return fn;
}

static void mk2d(CUtensorMap* m, void* base, uint64_t d0, uint64_t rows,
                 uint32_t b0, uint32_t b1) {
    cuuint64_t dims[2]    = {d0, rows};
    cuuint64_t strides[1] = {d0 * 2};     // bytes
    cuuint32_t box[2]     = {b0, b1};
    cuuint32_t es[2]      = {1, 1};
    get_encoder()(m, CU_TENSOR_MAP_DATA_TYPE_BFLOAT16, 2, base,
                  dims, strides, box, es,
                  CU_TENSOR_MAP_INTERLEAVE_NONE, CU_TENSOR_MAP_SWIZZLE_128B,
                  CU_TENSOR_MAP_L2_PROMOTION_L2_128B,
                  CU_TENSOR_MAP_FLOAT_OOB_FILL_NONE);
}

extern "C" void kernel_launch(void* const* d_in, const int* in_sizes, int n_in,
                              void* d_out, int out_size) {
    const float* x     = (const float*)d_in[0];
    const float* rel   = (const float*)d_in[1];
    const float* alpha = (const float*)d_in[2];
    const float* Wq    = (const float*)d_in[3];
    const float* bq    = (const float*)d_in[4];
    const float* Wk    = (const float*)d_in[5];
    const float* bk    = (const float*)d_in[6];
    const float* Wv    = (const float*)d_in[7];
    const float* bv    = (const float*)d_in[8];
    const float* Wo    = (const float*)d_in[9];
    const float* bo    = (const float*)d_in[10];
    float* out = (float*)d_out;

    cudaFuncSetAttribute(gemm_tma,  cudaFuncAttributeMaxDynamicSharedMemorySize, GEMM_SMEM);
    cudaFuncSetAttribute(flash_tma, cudaFuncAttributeMaxDynamicSharedMemorySize, FL_SMEM);

    void *ah, *al, *wh, *wl, *qh, *ql, *kh, *kl, *vh, *vl;
    cudaGetSymbolAddress(&ah, g_ah);
    cudaGetSymbolAddress(&al, g_al);
    cudaGetSymbolAddress(&wh, g_wh);
    cudaGetSymbolAddress(&wl, g_wl);
    cudaGetSymbolAddress(&qh, g_qh);
    cudaGetSymbolAddress(&ql, g_ql);
    cudaGetSymbolAddress(&kh, g_kh);
    cudaGetSymbolAddress(&kl, g_kl);
    cudaGetSymbolAddress(&vh, g_vh);
    cudaGetSymbolAddress(&vl, g_vl);

    CUtensorMap mAh, mAl, mWh, mWl, mQh, mQl, mKh, mKl, mVh, mVl;
    mk2d(&mAh, ah, DM, MT,          64, 128);
    mk2d(&mAl, al, DM, MT,          64, 128);
    mk2d(&mWh, wh, DM, 4*DM,        64, 64);
    mk2d(&mWl, wl, DM, 4*DM,        64, 64);
    mk2d(&mQh, qh, HD, BB*NH*SS,    64, 64);
    mk2d(&mQl, ql, HD, BB*NH*SS,    64, 64);
    mk2d(&mKh, kh, HD, BB*NH*SS,    64, 64);
    mk2d(&mKl, kl, HD, BB*NH*SS,    64, 64);
    mk2d(&mVh, vh, HD, BB*NH*SS,    64, 64);
    mk2d(&mVl, vl, HD, BB*NH*SS,    64, 64);

    pe_split_kernel<<<(MT*(DM/2) + 255)/256, 256>>>(x, rel, alpha);
    split4_kernel<<<(4*NW4 + 255)/256, 256>>>(Wq, Wk, Wv, Wo);

    gemm_tma<<<dim3(3*DM/64, MT/128), 128, GEMM_SMEM>>>(
        mAh, mAl, mWh, mWl, bq, bk, bv, nullptr, 0, 0);

    flash_tma<<<dim3(SS/64, BB*NH), 128, FL_SMEM>>>(mQh, mQl, mKh, mKl, mVh, mVl);

    gemm_tma<<<dim3(DM/64, MT/128), 128, GEMM_SMEM>>>(
        mAh, mAl, mWh, mWl, bo, bo, bo, out, 3*DM, 3);
}

// round 11
// speedup vs baseline: 1.3606x; 1.1790x over previous
#include <cuda_runtime.h>
#include <cuda.h>
#include <cuda_bf16.h>
#include <cuda_fp16.h>
#include <math.h>
#include <stdint.h>

#define DM 1024
#define NH 16
#define HD 64
#define MSL 5000
#define BB 2
#define SS 2048
#define MT (BB*SS)   // 4096 rows total

// Scratch (allocation-free rule: device globals)
__device__ __nv_bfloat16 g_ah[MT*DM];     // GEMM A hi (xpe-split, later o-split)
__device__ __nv_bfloat16 g_al[MT*DM];     // GEMM A lo
__device__ __nv_bfloat16 g_wh[4*DM*DM];   // stacked Wq|Wk|Wv|Wo hi
__device__ __nv_bfloat16 g_wl[4*DM*DM];
// fp16 Q/K/V in [B,H,S,hd] (Q pre-scaled by log2(e)/32; K,V split hi+lo)
__device__ __half g_qh[MT*DM];
__device__ __half g_kh[MT*DM];
__device__ __half g_kl[MT*DM];
__device__ __half g_vh[MT*DM];
__device__ __half g_vl[MT*DM];

// ---------------------------------------------------------------------------
// helpers
// ---------------------------------------------------------------------------
__device__ __forceinline__ uint32_t smem_u32(const void* p) {
    uint32_t a;
    asm("{ .reg .u64 t; cvta.to.shared.u64 t, %1; cvt.u32.u64 %0, t; }" : "=r"(a) : "l"(p));
    return a;
}

#define MBAR_INIT(addr, cnt) \
    asm volatile("mbarrier.init.shared.b64 [%0], %1;" :: "r"(addr), "r"(cnt) : "memory")

#define EXPECT_TX(addr, bytes) \
    asm volatile("mbarrier.arrive.expect_tx.shared.b64 _, [%0], %1;" :: "r"(addr), "r"(bytes) : "memory")

#define TMA2D(smem, mapp, x, y, mbar) \
    asm volatile("cp.async.bulk.tensor.2d.shared::cluster.global.tile.mbarrier::complete_tx::bytes " \
        "[%0], [%1, {%2, %3}], [%4];" \
        :: "r"(smem), "l"(mapp), "r"(x), "r"(y), "r"(mbar) : "memory")

__device__ __forceinline__ void mbar_wait(uint32_t addr, uint32_t parity) {
    uint32_t done;
    asm volatile(
        "{\n\t.reg .pred p;\n\t"
        "mbarrier.try_wait.parity.shared.b64 p, [%1], %2;\n\t"
        "selp.b32 %0,1,0,p;\n\t}"
        : "=r"(done) : "r"(addr), "r"(parity) : "memory");
    while (!done) {
        asm volatile(
            "{\n\t.reg .pred p;\n\t"
            "mbarrier.try_wait.parity.shared.b64 p, [%1], %2, 0x989680;\n\t"
            "selp.b32 %0,1,0,p;\n\t}"
            : "=r"(done) : "r"(addr), "r"(parity) : "memory");
    }
}

#define LDSM4(r, addr) \
    asm volatile("ldmatrix.sync.aligned.m8n8.x4.shared.b16 {%0,%1,%2,%3}, [%4];" \
        : "=r"((r)[0]), "=r"((r)[1]), "=r"((r)[2]), "=r"((r)[3]) : "r"(addr))

#define LDSM4T(r, addr) \
    asm volatile("ldmatrix.sync.aligned.m8n8.x4.trans.shared.b16 {%0,%1,%2,%3}, [%4];" \
        : "=r"((r)[0]), "=r"((r)[1]), "=r"((r)[2]), "=r"((r)[3]) : "r"(addr))

// bf16 MMA (GEMMs)
#define MMA16816(d, a, b0v, b1v) \
    asm volatile("mma.sync.aligned.m16n8k16.row.col.f32.bf16.bf16.f32 " \
        "{%0,%1,%2,%3}, {%4,%5,%6,%7}, {%8,%9}, {%0,%1,%2,%3};" \
        : "+f"((d)[0]), "+f"((d)[1]), "+f"((d)[2]), "+f"((d)[3]) \
        : "r"((a)[0]), "r"((a)[1]), "r"((a)[2]), "r"((a)[3]), "r"(b0v), "r"(b1v))

// fp16 MMA (flash)
#define MMA16816H(d, a, b0v, b1v) \
    asm volatile("mma.sync.aligned.m16n8k16.row.col.f32.f16.f16.f32 " \
        "{%0,%1,%2,%3}, {%4,%5,%6,%7}, {%8,%9}, {%0,%1,%2,%3};" \
        : "+f"((d)[0]), "+f"((d)[1]), "+f"((d)[2]), "+f"((d)[3]) \
        : "r"((a)[0]), "r"((a)[1]), "r"((a)[2]), "r"((a)[3]), "r"(b0v), "r"(b1v))

__device__ __forceinline__ uint32_t pack_h(float hi, float lo) {
    __half2 h = __floats2half2_rn(lo, hi);   // lo -> low half, hi -> high half
    return *reinterpret_cast<uint32_t*>(&h);
}
__device__ __forceinline__ float ex2(float x) {
    float r;
    asm("ex2.approx.ftz.f32 %0, %1;" : "=f"(r) : "f"(x));
    return r;
}

// ---------------------------------------------------------------------------
// Kernel 1: fused PE + split:  (x + a*sin_pe + (1-a)*rel) -> (g_ah, g_al)
// ---------------------------------------------------------------------------
__global__ void pe_split_kernel(const float* __restrict__ x,
                                const float* __restrict__ rel,
                                const float* __restrict__ alphap) {
    int idx = blockIdx.x*blockDim.x + threadIdx.x;
    if (idx >= MT*(DM/2)) return;
    int m  = idx >> 9;
    int pp = idx & 511;
    int s  = m & (SS-1);
    float a = alphap[0];
    float freq = __expf(-(float)(2*pp) * (9.210340371976184f/(float)DM));
    float ang = (float)s * freq;
    float sn, cs;
    sincosf(ang, &sn, &cs);
    const float* rr = rel + (size_t)(MSL - SS + s)*DM + 2*pp;
    float2 xv = *(const float2*)(x + (size_t)idx*2);
    float om = 1.0f - a;
    float ox = xv.x + a*sn + om*rr[0];
    float oy = xv.y + a*cs + om*rr[1];
    __nv_bfloat16 hx = __float2bfloat16(ox);
    __nv_bfloat16 hy = __float2bfloat16(oy);
    __nv_bfloat16 lx = __float2bfloat16(ox - __bfloat162float(hx));
    __nv_bfloat16 ly = __float2bfloat16(oy - __bfloat162float(hy));
    *(__nv_bfloat162*)(g_ah + (size_t)idx*2) = __nv_bfloat162(hx, hy);
    *(__nv_bfloat162*)(g_al + (size_t)idx*2) = __nv_bfloat162(lx, ly);
}

// ---------------------------------------------------------------------------
// Kernel 2: all four weight matrices -> (hi, lo) bf16 split in one launch.
// ---------------------------------------------------------------------------
#define NW4 (DM*DM/4)   // 262144 float4 per matrix
__global__ void split4_kernel(const float* __restrict__ w0,
                              const float* __restrict__ w1,
                              const float* __restrict__ w2,
                              const float* __restrict__ w3) {
    int i = blockIdx.x*blockDim.x + threadIdx.x;
    if (i >= 4*NW4) return;
    const int which = i >> 18;            // NW4 = 2^18
    const int j = i & (NW4 - 1);
    const float* src = (which == 0) ? w0 : (which == 1) ? w1 : (which == 2) ? w2 : w3;
    float4 v = ((const float4*)src)[j];
    __nv_bfloat16 h0 = __float2bfloat16(v.x);
    __nv_bfloat16 h1 = __float2bfloat16(v.y);
    __nv_bfloat16 h2 = __float2bfloat16(v.z);
    __nv_bfloat16 h3 = __float2bfloat16(v.w);
    __nv_bfloat16 l0 = __float2bfloat16(v.x - __bfloat162float(h0));
    __nv_bfloat16 l1 = __float2bfloat16(v.y - __bfloat162float(h1));
    __nv_bfloat16 l2 = __float2bfloat16(v.z - __bfloat162float(h2));
    __nv_bfloat16 l3 = __float2bfloat16(v.w - __bfloat162float(h3));
    size_t o = (size_t)which*DM*DM + (size_t)j*4;
    __nv_bfloat162* hp = (__nv_bfloat162*)(g_wh + o);
    __nv_bfloat162* lp = (__nv_bfloat162*)(g_wl + o);
    hp[0] = __nv_bfloat162(h0, h1); hp[1] = __nv_bfloat162(h2, h3);
    lp[0] = __nv_bfloat162(l0, l1); lp[1] = __nv_bfloat162(l2, l3);
}

// ---------------------------------------------------------------------------
// TMA split-bf16 GEMM. Block 128x64, 128 threads (4 warps 2Mx2N),
// warp tile 64x32. K-chunk 64, 2-stage TMA, 2 CTAs/SM ping-pong.
// mode 0: merged QKV (gridDim.x=48): Q -> fp16 (pre-scaled log2e/32),
//         K/V -> fp16 hi+lo split.  mode 3: out proj, fp32 row-major.
// ---------------------------------------------------------------------------
#define GA 16384                  // A operand tile: 128 rows x 128B (SW128)
#define GW 8192                   // W operand tile: 64 rows x 128B
#define GSTG (2*GA + 2*GW)        // AH AL WH WL = 49152
#define GEMM_SMEM (2*GSTG + 1088) // 2 stages + mbars/align = 99392

#define QSCALE 0.04508422002778f  // log2(e)/32

__global__ void __launch_bounds__(128, 2) gemm_tma(
    const __grid_constant__ CUtensorMap mAh,
    const __grid_constant__ CUtensorMap mAl,
    const __grid_constant__ CUtensorMap mWh,
    const __grid_constant__ CUtensorMap mWl,
    const float* __restrict__ b0, const float* __restrict__ b1,
    const float* __restrict__ b2, float* __restrict__ outp,
    int wbase, int mode)
{
    extern __shared__ char smem[];
    const uint32_t sb = (smem_u32(smem) + 1023) & ~1023u;
    const uint32_t mb = sb + 2*GSTG;
    const int t  = threadIdx.x;
    const int m0 = blockIdx.y * 128;
    const int n0 = blockIdx.x * 64;

    if (t == 0) { MBAR_INIT(mb, 1); MBAR_INIT(mb + 8, 1); }
    __syncthreads();

    auto issue = [&](int ck) {
        const uint32_t d   = sb + (uint32_t)(ck & 1) * GSTG;
        const uint32_t bar = mb + (uint32_t)(ck & 1) * 8;
        EXPECT_TX(bar, (uint32_t)GSTG);
        TMA2D(d + 0,         &mAh, ck*64, m0, bar);
        TMA2D(d + GA,        &mAl, ck*64, m0, bar);
        TMA2D(d + 2*GA,      &mWh, ck*64, wbase + n0, bar);
        TMA2D(d + 2*GA + GW, &mWl, ck*64, wbase + n0, bar);
    };
    if (t == 0) { issue(0); issue(1); }

    const int wid = t >> 5, l = t & 31;
    const int warpM = wid & 1;
    const int warpN = wid >> 1;          // 0..1
    const int q  = l >> 3, lr = l & 7;

    float acc[16][4];
    #pragma unroll
    for (int i = 0; i < 16; i++)
        #pragma unroll
        for (int j = 0; j < 4; j++) acc[i][j] = 0.f;

    uint32_t arow[4], brow[2];
    #pragma unroll
    for (int mt = 0; mt < 4; mt++) arow[mt] = (uint32_t)(warpM*64 + mt*16 + (q & 1)*8 + lr) * 128;
    #pragma unroll
    for (int np = 0; np < 2; np++) brow[np] = (uint32_t)(warpN*32 + np*16 + (q >> 1)*8 + lr) * 128;
    uint32_t axc[4], bxc[4];
    #pragma unroll
    for (int s = 0; s < 4; s++) {
        axc[s] = (uint32_t)((((q >> 1) + 2*s) ^ lr) * 16);
        bxc[s] = (uint32_t)((((q & 1) + 2*s) ^ lr) * 16);
    }

    int ph0 = 0, ph1 = 0;
    for (int ch = 0; ch < DM/64; ch++) {
        const int bsel = ch & 1;
        if (bsel == 0) { mbar_wait(mb,     (uint32_t)ph0); ph0 ^= 1; }
        else           { mbar_wait(mb + 8, (uint32_t)ph1); ph1 ^= 1; }
        const uint32_t bs = sb + (uint32_t)bsel * GSTG;

        #pragma unroll
        for (int s = 0; s < 4; s++) {
            uint32_t ah[4][4], alr[4][4];
            #pragma unroll
            for (int mt = 0; mt < 4; mt++) {
                uint32_t ao = arow[mt] + axc[s];
                LDSM4(ah[mt],  bs + 0  + ao);
                LDSM4(alr[mt], bs + GA + ao);
            }
            uint32_t bh[2][4], bl[2][4];
            #pragma unroll
            for (int np = 0; np < 2; np++) {
                uint32_t bo = brow[np] + bxc[s];
                LDSM4(bh[np], bs + 2*GA      + bo);
                LDSM4(bl[np], bs + 2*GA + GW + bo);
            }
            #pragma unroll
            for (int mt = 0; mt < 4; mt++)
                #pragma unroll
                for (int nt = 0; nt < 4; nt++) {
                    const int np = nt >> 1, h = (nt & 1) * 2;
                    MMA16816(acc[mt*4+nt], ah[mt], bh[np][h], bh[np][h+1]);
                }
            #pragma unroll
            for (int mt = 0; mt < 4; mt++)
                #pragma unroll
                for (int nt = 0; nt < 4; nt++) {
                    const int np = nt >> 1, h = (nt & 1) * 2;
                    MMA16816(acc[mt*4+nt], ah[mt], bl[np][h], bl[np][h+1]);
                }
            #pragma unroll
            for (int mt = 0; mt < 4; mt++)
                #pragma unroll
                for (int nt = 0; nt < 4; nt++) {
                    const int np = nt >> 1, h = (nt & 1) * 2;
                    MMA16816(acc[mt*4+nt], alr[mt], bh[np][h], bh[np][h+1]);
                }
        }
        __syncthreads();
        if (t == 0 && ch + 2 < DM/64) issue(ch + 2);
    }

    // epilogue
    if (mode == 0) {
        const int which = n0 >> 10;
        const float* bias = (which == 0) ? b0 : (which == 1) ? b1 : b2;
        const int nloc0 = n0 & 1023;
        #pragma unroll
        for (int nt = 0; nt < 4; nt++) {
            const int n = nloc0 + warpN*32 + nt*8 + (l & 3)*2;
            const float bx = bias[n], by = bias[n+1];
            #pragma unroll
            for (int mt = 0; mt < 4; mt++) {
                const float* d = acc[mt*4 + nt];
                #pragma unroll
                for (int half = 0; half < 2; half++) {
                    const int m = m0 + warpM*64 + mt*16 + (l >> 2) + half*8;
                    float vx = d[half*2 + 0] + bx;
                    float vy = d[half*2 + 1] + by;
                    const int bb = m >> 11, s = m & (SS-1);
                    const int hh = n >> 6, dd = n & 63;
                    size_t o = (size_t)((bb*NH + hh)*SS + s)*HD + dd;
                    if (which == 0) {
                        // Q: fp16 only, pre-scaled into log2 domain
                        *(__half2*)(g_qh + o) = __floats2half2_rn(vx*QSCALE, vy*QSCALE);
                    } else {
                        __half* oh = (which == 1) ? g_kh : g_vh;
                        __half* ol = (which == 1) ? g_kl : g_vl;
                        __half hx = __float2half_rn(vx);
                        __half hy = __float2half_rn(vy);
                        __half lx = __float2half_rn(vx - __half2float(hx));
                        __half ly = __float2half_rn(vy - __half2float(hy));
                        *(__half2*)(oh + o) = __halves2half2(hx, hy);
                        *(__half2*)(ol + o) = __halves2half2(lx, ly);
                    }
                }
            }
        }
    } else {
        #pragma unroll
        for (int nt = 0; nt < 4; nt++) {
            const int n = n0 + warpN*32 + nt*8 + (l & 3)*2;
            const float bx = b0[n], by = b0[n+1];
            #pragma unroll
            for (int mt = 0; mt < 4; mt++) {
                const float* d = acc[mt*4 + nt];
                #pragma unroll
                for (int half = 0; half < 2; half++) {
                    const int m = m0 + warpM*64 + mt*16 + (l >> 2) + half*8;
                    float2 v;
                    v.x = d[half*2 + 0] + bx;
                    v.y = d[half*2 + 1] + by;
                    *(float2*)&outp[(size_t)m*DM + n] = v;
                }
            }
        }
    }
}

// ---------------------------------------------------------------------------
// Flash attention, fp16 2-term products (Qh(Kh+Kl), Ph(Vh+Vl)), exp2 softmax.
// Block: 64 queries x one (b,h); 128 threads = 4 warps, warp = 16 q rows.
// 3 CTAs/SM. KV tile 64, double-buffered TMA (SW128).
// ---------------------------------------------------------------------------
#define FQB 8192                  // Q tile: 64 rows x 128B (hi only)
#define FKB 8192                  // KV array tile: 64 rows x 128B
#define FSTG (4*FKB)              // KH KL VH VL = 32768
#define FL_SMEM (FQB + 2*FSTG + 1088)   // 74816 -> 3 CTAs/SM

__global__ void __launch_bounds__(128, 3) flash_tma(
    const __grid_constant__ CUtensorMap mQh,
    const __grid_constant__ CUtensorMap mKh,
    const __grid_constant__ CUtensorMap mKl,
    const __grid_constant__ CUtensorMap mVh,
    const __grid_constant__ CUtensorMap mVl)
{
    extern __shared__ char fsm[];
    const uint32_t sb  = (smem_u32(fsm) + 1023) & ~1023u;
    const uint32_t kvb = sb + FQB;
    const uint32_t mbq = sb + FQB + 2*FSTG;
    const int bh = blockIdx.y;
    const int q0 = blockIdx.x * 64;
    const int row0 = bh * SS;
    const int t = threadIdx.x, wid = t >> 5, l = t & 31;
    const int q = l >> 3, lr = l & 7;
    const int wq0 = wid * 16;

    if (t == 0) { MBAR_INIT(mbq, 1); MBAR_INIT(mbq + 8, 1); MBAR_INIT(mbq + 16, 1); }
    __syncthreads();

    auto kvissue = [&](int ti) {
        const uint32_t d   = kvb + (uint32_t)(ti & 1) * FSTG;
        const uint32_t bar = mbq + 8 + (uint32_t)(ti & 1) * 8;
        EXPECT_TX(bar, (uint32_t)FSTG);
        const int y = row0 + ti*64;
        TMA2D(d + 0*FKB, &mKh, 0, y, bar);
        TMA2D(d + 1*FKB, &mKl, 0, y, bar);
        TMA2D(d + 2*FKB, &mVh, 0, y, bar);
        TMA2D(d + 3*FKB, &mVl, 0, y, bar);
    };
    if (t == 0) {
        EXPECT_TX(mbq, (uint32_t)FQB);
        TMA2D(sb, &mQh, 0, row0 + q0, mbq);
        kvissue(0);
        kvissue(1);
    }

    mbar_wait(mbq, 0);

    // Q fragments (persistent, hi only)
    uint32_t qhf[4][4];
    {
        const uint32_t qrow = (uint32_t)(wq0 + (q & 1)*8 + lr) * 128;
        #pragma unroll
        for (int kt = 0; kt < 4; kt++) {
            const uint32_t c = (uint32_t)((((q >> 1) + 2*kt) ^ lr) * 16);
            LDSM4(qhf[kt], sb + qrow + c);
        }
    }

    uint32_t krow[4], vrow[4], kxc[4], vxc[4];
    #pragma unroll
    for (int np = 0; np < 4; np++) krow[np] = (uint32_t)(np*16 + (q >> 1)*8 + lr) * 128;
    #pragma unroll
    for (int kt = 0; kt < 4; kt++) vrow[kt] = (uint32_t)(kt*16 + (q & 1)*8 + lr) * 128;
    #pragma unroll
    for (int kt = 0; kt < 4; kt++) kxc[kt] = (uint32_t)((((q & 1) + 2*kt) ^ lr) * 16);
    #pragma unroll
    for (int g = 0; g < 4; g++)  vxc[g]  = (uint32_t)(((2*g + (q >> 1)) ^ lr) * 16);

    float oacc[8][4];
    #pragma unroll
    for (int i = 0; i < 8; i++)
        #pragma unroll
        for (int j = 0; j < 4; j++) oacc[i][j] = 0.f;
    float mprev0 = -1e30f, mprev1 = -1e30f, lsum0 = 0.f, lsum1 = 0.f;

    int kvph0 = 0, kvph1 = 0;
    for (int ti = 0; ti < SS/64; ti++) {
        const int bsel = ti & 1;
        if (bsel == 0) { mbar_wait(mbq + 8,  (uint32_t)kvph0); kvph0 ^= 1; }
        else           { mbar_wait(mbq + 16, (uint32_t)kvph1); kvph1 ^= 1; }
        const uint32_t kb = kvb + (uint32_t)bsel * FSTG;

        // scores (log2 domain: Q pre-scaled by log2e/32)
        float sacc[8][4];
        #pragma unroll
        for (int i = 0; i < 8; i++)
            #pragma unroll
            for (int j = 0; j < 4; j++) sacc[i][j] = 0.f;

        #pragma unroll
        for (int kt = 0; kt < 4; kt++) {
            uint32_t khf[4][4], klf[4][4];
            #pragma unroll
            for (int np = 0; np < 4; np++) {
                uint32_t ba = krow[np] + kxc[kt];
                LDSM4(khf[np], kb + 0*FKB + ba);
                LDSM4(klf[np], kb + 1*FKB + ba);
            }
            #pragma unroll
            for (int nt = 0; nt < 8; nt++) {
                const int np = nt >> 1, h = (nt & 1)*2;
                MMA16816H(sacc[nt], qhf[kt], khf[np][h], khf[np][h+1]);
            }
            #pragma unroll
            for (int nt = 0; nt < 8; nt++) {
                const int np = nt >> 1, h = (nt & 1)*2;
                MMA16816H(sacc[nt], qhf[kt], klf[np][h], klf[np][h+1]);
            }
        }

        float m0 = sacc[0][0], m1 = sacc[0][2];
        #pragma unroll
        for (int nt = 0; nt < 8; nt++) {
            m0 = fmaxf(m0, fmaxf(sacc[nt][0], sacc[nt][1]));
            m1 = fmaxf(m1, fmaxf(sacc[nt][2], sacc[nt][3]));
        }
        m0 = fmaxf(m0, __shfl_xor_sync(0xffffffffu, m0, 1));
        m0 = fmaxf(m0, __shfl_xor_sync(0xffffffffu, m0, 2));
        m1 = fmaxf(m1, __shfl_xor_sync(0xffffffffu, m1, 1));
        m1 = fmaxf(m1, __shfl_xor_sync(0xffffffffu, m1, 2));

        const float mn0 = fmaxf(mprev0, m0);
        const float mn1 = fmaxf(mprev1, m1);
        const float a0 = ex2(mprev0 - mn0);
        const float a1 = ex2(mprev1 - mn1);
        mprev0 = mn0; mprev1 = mn1;

        float rs0 = 0.f, rs1 = 0.f;
        #pragma unroll
        for (int nt = 0; nt < 8; nt++) {
            sacc[nt][0] = ex2(sacc[nt][0] - mn0);
            sacc[nt][1] = ex2(sacc[nt][1] - mn0);
            sacc[nt][2] = ex2(sacc[nt][2] - mn1);
            sacc[nt][3] = ex2(sacc[nt][3] - mn1);
            rs0 += sacc[nt][0] + sacc[nt][1];
            rs1 += sacc[nt][2] + sacc[nt][3];
        }
        rs0 += __shfl_xor_sync(0xffffffffu, rs0, 1);
        rs0 += __shfl_xor_sync(0xffffffffu, rs0, 2);
        rs1 += __shfl_xor_sync(0xffffffffu, rs1, 1);
        rs1 += __shfl_xor_sync(0xffffffffu, rs1, 2);
        lsum0 = lsum0*a0 + rs0;
        lsum1 = lsum1*a1 + rs1;
        #pragma unroll
        for (int nj = 0; nj < 8; nj++) {
            oacc[nj][0] *= a0; oacc[nj][1] *= a0;
            oacc[nj][2] *= a1; oacc[nj][3] *= a1;
        }

        #pragma unroll
        for (int kt = 0; kt < 4; kt++) {
            uint32_t ph[4];
            #pragma unroll
            for (int e = 0; e < 4; e++) {
                const float* s0 = sacc[2*kt + (e >> 1)];
                ph[e] = pack_h(s0[(e & 1)*2 + 1], s0[(e & 1)*2]);
            }
            uint32_t vhf[4][4], vlf[4][4];
            #pragma unroll
            for (int g = 0; g < 4; g++) {
                uint32_t va = vrow[kt] + vxc[g];
                LDSM4T(vhf[g], kb + 2*FKB + va);
                LDSM4T(vlf[g], kb + 3*FKB + va);
            }
            #pragma unroll
            for (int nj = 0; nj < 8; nj++) {
                const int g = nj >> 1, o = (nj & 1)*2;
                MMA16816H(oacc[nj], ph, vhf[g][o], vhf[g][o+1]);
            }
            #pragma unroll
            for (int nj = 0; nj < 8; nj++) {
                const int g = nj >> 1, o = (nj & 1)*2;
                MMA16816H(oacc[nj], ph, vlf[g][o], vlf[g][o+1]);
            }
        }

        __syncthreads();
        if (t == 0 && ti + 2 < SS/64) kvissue(ti + 2);
    }

    const float inv0 = 1.0f / lsum0;
    const float inv1 = 1.0f / lsum1;
    const int r0 = q0 + wq0 + (l >> 2);
    const int bb = bh >> 4, hh = bh & 15;
    #pragma unroll
    for (int nj = 0; nj < 8; nj++) {
        const int col = hh*HD + nj*8 + (l & 3)*2;
        {
            const float e0 = oacc[nj][0]*inv0, e1 = oacc[nj][1]*inv0;
            __nv_bfloat16 h0 = __float2bfloat16(e0), h1 = __float2bfloat16(e1);
            __nv_bfloat16 l0 = __float2bfloat16(e0 - __bfloat162float(h0));
            __nv_bfloat16 l1 = __float2bfloat16(e1 - __bfloat162float(h1));
            size_t o = (size_t)(bb*SS + r0)*DM + col;
            *(__nv_bfloat162*)(g_ah + o) = __nv_bfloat162(h0, h1);
            *(__nv_bfloat162*)(g_al + o) = __nv_bfloat162(l0, l1);
        }
        {
            const float e0 = oacc[nj][2]*inv1, e1 = oacc[nj][3]*inv1;
            __nv_bfloat16 h0 = __float2bfloat16(e0), h1 = __float2bfloat16(e1);
            __nv_bfloat16 l0 = __float2bfloat16(e0 - __bfloat162float(h0));
            __nv_bfloat16 l1 = __float2bfloat16(e1 - __bfloat162float(h1));
            size_t o = (size_t)(bb*SS + r0 + 8)*DM + col;
            *(__nv_bfloat162*)(g_ah + o) = __nv_bfloat162(h0, h1);
            *(__nv_bfloat162*)(g_al + o) = __nv_bfloat162(l0, l1);
        }
    }
}

// ---------------------------------------------------------------------------
// host: tensor-map construction via driver entry point (no -lcuda needed)
// ---------------------------------------------------------------------------
typedef CUresult (CUDAAPI *PFN_encodeTiled)(
    CUtensorMap*, CUtensorMapDataType, cuuint32_t, void*,
    const cuuint64_t*, const cuuint64_t*, const cuuint32_t*, const cuuint32_t*,
    CUtensorMapInterleave, CUtensorMapSwizzle, CUtensorMapL2promotion,
    CUtensorMapFloatOOBfill);

static PFN_encodeTiled get_encoder() {
    static PFN_encodeTiled fn = nullptr;
    if (!fn) {
        void* p = nullptr;
        cudaDriverEntryPointQueryResult qr;
        cudaGetDriverEntryPoint("cuTensorMapEncodeTiled", &p, cudaEnableDefault, &qr);
        fn = (PFN_encodeTiled)p;
    }
    return fn;
}

static void mk2d(CUtensorMap* m, void* base, uint64_t d0, uint64_t rows,
                 uint32_t b0, uint32_t b1, CUtensorMapDataType dt) {
    cuuint64_t dims[2]    = {d0, rows};
    cuuint64_t strides[1] = {d0 * 2};     // bytes (both dtypes are 2B)
    cuuint32_t box[2]     = {b0, b1};
    cuuint32_t es[2]      = {1, 1};
    get_encoder()(m, dt, 2, base,
                  dims, strides, box, es,
                  CU_TENSOR_MAP_INTERLEAVE_NONE, CU_TENSOR_MAP_SWIZZLE_128B,
                  CU_TENSOR_MAP_L2_PROMOTION_L2_128B,
                  CU_TENSOR_MAP_FLOAT_OOB_FILL_NONE);
}

extern "C" void kernel_launch(void* const* d_in, const int* in_sizes, int n_in,
                              void* d_out, int out_size) {
    const float* x     = (const float*)d_in[0];
    const float* rel   = (const float*)d_in[1];
    const float* alpha = (const float*)d_in[2];
    const float* Wq    = (const float*)d_in[3];
    const float* bq    = (const float*)d_in[4];
    const float* Wk    = (const float*)d_in[5];
    const float* bk    = (const float*)d_in[6];
    const float* Wv    = (const float*)d_in[7];
    const float* bv    = (const float*)d_in[8];
    const float* Wo    = (const float*)d_in[9];
    const float* bo    = (const float*)d_in[10];
    float* out = (float*)d_out;

    cudaFuncSetAttribute(gemm_tma,  cudaFuncAttributeMaxDynamicSharedMemorySize, GEMM_SMEM);
    cudaFuncSetAttribute(flash_tma, cudaFuncAttributeMaxDynamicSharedMemorySize, FL_SMEM);

    void *ah, *al, *wh, *wl, *qh, *kh, *kl, *vh, *vl;
    cudaGetSymbolAddress(&ah, g_ah);
    cudaGetSymbolAddress(&al, g_al);
    cudaGetSymbolAddress(&wh, g_wh);
    cudaGetSymbolAddress(&wl, g_wl);
    cudaGetSymbolAddress(&qh, g_qh);
    cudaGetSymbolAddress(&kh, g_kh);
    cudaGetSymbolAddress(&kl, g_kl);
    cudaGetSymbolAddress(&vh, g_vh);
    cudaGetSymbolAddress(&vl, g_vl);

    const CUtensorMapDataType BF = CU_TENSOR_MAP_DATA_TYPE_BFLOAT16;
    const CUtensorMapDataType F16 = CU_TENSOR_MAP_DATA_TYPE_FLOAT16;

    CUtensorMap mAh, mAl, mWh, mWl, mQh, mKh, mKl, mVh, mVl;
    mk2d(&mAh, ah, DM, MT,          64, 128, BF);
    mk2d(&mAl, al, DM, MT,          64, 128, BF);
    mk2d(&mWh, wh, DM, 4*DM,        64, 64,  BF);
    mk2d(&mWl, wl, DM, 4*DM,        64, 64,  BF);
    mk2d(&mQh, qh, HD, BB*NH*SS,    64, 64,  F16);
    mk2d(&mKh, kh, HD, BB*NH*SS,    64, 64,  F16);
    mk2d(&mKl, kl, HD, BB*NH*SS,    64, 64,  F16);
    mk2d(&mVh, vh, HD, BB*NH*SS,    64, 64,  F16);
    mk2d(&mVl, vl, HD, BB*NH*SS,    64, 64,  F16);

    pe_split_kernel<<<(MT*(DM/2) + 255)/256, 256>>>(x, rel, alpha);
    split4_kernel<<<(4*NW4 + 255)/256, 256>>>(Wq, Wk, Wv, Wo);

    gemm_tma<<<dim3(3*DM/64, MT/128), 128, GEMM_SMEM>>>(
        mAh, mAl, mWh, mWl, bq, bk, bv, nullptr, 0, 0);

    flash_tma<<<dim3(SS/64, BB*NH), 128, FL_SMEM>>>(mQh, mKh, mKl, mVh, mVl);

    gemm_tma<<<dim3(DM/64, MT/128), 128, GEMM_SMEM>>>(
        mAh, mAl, mWh, mWl, bo, bo, bo, out, 3*DM, 3);
}

// round 13
// speedup vs baseline: 1.8902x; 1.3892x over previous
#include <cuda_runtime.h>
#include <cuda.h>
#include <cuda_bf16.h>
#include <cuda_fp16.h>
#include <math.h>
#include <stdint.h>

#define DM 1024
#define NH 16
#define HD 64
#define MSL 5000
#define BB 2
#define SS 2048
#define MT (BB*SS)   // 4096 rows total

// Scratch (allocation-free rule: device globals), all fp16 now
__device__ __half g_a[MT*DM];         // GEMM A operand (xpe, later attention O)
__device__ __half g_wh[4*DM*DM];      // stacked Wq|Wk|Wv|Wo hi
__device__ __half g_wl[4*DM*DM];      // lo
// Q/K/V in [B,H,S,hd]; Q pre-scaled by log2(e)/32; K single; V hi+lo
__device__ __half g_qh[MT*DM];
__device__ __half g_kh[MT*DM];
__device__ __half g_vh[MT*DM];
__device__ __half g_vl[MT*DM];

// ---------------------------------------------------------------------------
// helpers
// ---------------------------------------------------------------------------
__device__ __forceinline__ uint32_t smem_u32(const void* p) {
    uint32_t a;
    asm("{ .reg .u64 t; cvta.to.shared.u64 t, %1; cvt.u32.u64 %0, t; }" : "=r"(a) : "l"(p));
    return a;
}

#define MBAR_INIT(addr, cnt) \
    asm volatile("mbarrier.init.shared.b64 [%0], %1;" :: "r"(addr), "r"(cnt) : "memory")

#define EXPECT_TX(addr, bytes) \
    asm volatile("mbarrier.arrive.expect_tx.shared.b64 _, [%0], %1;" :: "r"(addr), "r"(bytes) : "memory")

#define TMA2D(smem, mapp, x, y, mbar) \
    asm volatile("cp.async.bulk.tensor.2d.shared::cluster.global.tile.mbarrier::complete_tx::bytes " \
        "[%0], [%1, {%2, %3}], [%4];" \
        :: "r"(smem), "l"(mapp), "r"(x), "r"(y), "r"(mbar) : "memory")

__device__ __forceinline__ void mbar_wait(uint32_t addr, uint32_t parity) {
    uint32_t done;
    asm volatile(
        "{\n\t.reg .pred p;\n\t"
        "mbarrier.try_wait.parity.shared.b64 p, [%1], %2;\n\t"
        "selp.b32 %0,1,0,p;\n\t}"
        : "=r"(done) : "r"(addr), "r"(parity) : "memory");
    while (!done) {
        asm volatile(
            "{\n\t.reg .pred p;\n\t"
            "mbarrier.try_wait.parity.shared.b64 p, [%1], %2, 0x989680;\n\t"
            "selp.b32 %0,1,0,p;\n\t}"
            : "=r"(done) : "r"(addr), "r"(parity) : "memory");
    }
}

#define LDSM4(r, addr) \
    asm volatile("ldmatrix.sync.aligned.m8n8.x4.shared.b16 {%0,%1,%2,%3}, [%4];" \
        : "=r"((r)[0]), "=r"((r)[1]), "=r"((r)[2]), "=r"((r)[3]) : "r"(addr))

#define LDSM4T(r, addr) \
    asm volatile("ldmatrix.sync.aligned.m8n8.x4.trans.shared.b16 {%0,%1,%2,%3}, [%4];" \
        : "=r"((r)[0]), "=r"((r)[1]), "=r"((r)[2]), "=r"((r)[3]) : "r"(addr))

// fp16 MMA
#define MMA16816H(d, a, b0v, b1v) \
    asm volatile("mma.sync.aligned.m16n8k16.row.col.f32.f16.f16.f32 " \
        "{%0,%1,%2,%3}, {%4,%5,%6,%7}, {%8,%9}, {%0,%1,%2,%3};" \
        : "+f"((d)[0]), "+f"((d)[1]), "+f"((d)[2]), "+f"((d)[3]) \
        : "r"((a)[0]), "r"((a)[1]), "r"((a)[2]), "r"((a)[3]), "r"(b0v), "r"(b1v))

__device__ __forceinline__ uint32_t pack_h(float hi, float lo) {
    __half2 h = __floats2half2_rn(lo, hi);   // lo -> low half, hi -> high half
    return *reinterpret_cast<uint32_t*>(&h);
}
__device__ __forceinline__ float ex2(float x) {
    float r;
    asm("ex2.approx.ftz.f32 %0, %1;" : "=f"(r) : "f"(x));
    return r;
}

// ---------------------------------------------------------------------------
// Kernel 1: fused PE:  (x + a*sin_pe + (1-a)*rel) -> g_a (fp16)
// ---------------------------------------------------------------------------
__global__ void pe_kernel(const float* __restrict__ x,
                          const float* __restrict__ rel,
                          const float* __restrict__ alphap) {
    int idx = blockIdx.x*blockDim.x + threadIdx.x;
    if (idx >= MT*(DM/2)) return;
    int m  = idx >> 9;
    int pp = idx & 511;
    int s  = m & (SS-1);
    float a = alphap[0];
    float freq = __expf(-(float)(2*pp) * (9.210340371976184f/(float)DM));
    float ang = (float)s * freq;
    float sn, cs;
    sincosf(ang, &sn, &cs);
    const float* rr = rel + (size_t)(MSL - SS + s)*DM + 2*pp;
    float2 xv = *(const float2*)(x + (size_t)idx*2);
    float om = 1.0f - a;
    float ox = xv.x + a*sn + om*rr[0];
    float oy = xv.y + a*cs + om*rr[1];
    *(__half2*)(g_a + (size_t)idx*2) = __floats2half2_rn(ox, oy);
}

// ---------------------------------------------------------------------------
// Kernel 2: all four weight matrices -> (hi, lo) fp16 split in one launch.
// ---------------------------------------------------------------------------
#define NW4 (DM*DM/4)   // 262144 float4 per matrix
__global__ void split4_kernel(const float* __restrict__ w0,
                              const float* __restrict__ w1,
                              const float* __restrict__ w2,
                              const float* __restrict__ w3) {
    int i = blockIdx.x*blockDim.x + threadIdx.x;
    if (i >= 4*NW4) return;
    const int which = i >> 18;            // NW4 = 2^18
    const int j = i & (NW4 - 1);
    const float* src = (which == 0) ? w0 : (which == 1) ? w1 : (which == 2) ? w2 : w3;
    float4 v = ((const float4*)src)[j];
    __half h0 = __float2half_rn(v.x);
    __half h1 = __float2half_rn(v.y);
    __half h2 = __float2half_rn(v.z);
    __half h3 = __float2half_rn(v.w);
    __half l0 = __float2half_rn(v.x - __half2float(h0));
    __half l1 = __float2half_rn(v.y - __half2float(h1));
    __half l2 = __float2half_rn(v.z - __half2float(h2));
    __half l3 = __float2half_rn(v.w - __half2float(h3));
    size_t o = (size_t)which*DM*DM + (size_t)j*4;
    __half2* hp = (__half2*)(g_wh + o);
    __half2* lp = (__half2*)(g_wl + o);
    hp[0] = __halves2half2(h0, h1); hp[1] = __halves2half2(h2, h3);
    lp[0] = __halves2half2(l0, l1); lp[1] = __halves2half2(l2, l3);
}

// ---------------------------------------------------------------------------
// TMA fp16 GEMM: C = A (Wh+Wl)^T + bias. Block 128x64, 128 threads,
// warp tile 64x32. K-chunk 64, 2-stage TMA, 3 CTAs/SM.
// mode 0: merged QKV (gridDim.x=48): Q->fp16 scaled, K->fp16, V->fp16 hi+lo.
// mode 3: out proj, fp32 row-major.
// ---------------------------------------------------------------------------
#define GA 16384                  // A tile: 128 rows x 128B (SW128)
#define GW 8192                   // W tile: 64 rows x 128B
#define GSTG (GA + 2*GW)          // A WH WL = 32768
#define GEMM_SMEM (2*GSTG + 1088) // 66624 -> 3 CTAs/SM

#define QSCALE 0.04508422002778f  // log2(e)/32

__global__ void __launch_bounds__(128, 3) gemm_tma(
    const __grid_constant__ CUtensorMap mA,
    const __grid_constant__ CUtensorMap mWh,
    const __grid_constant__ CUtensorMap mWl,
    const float* __restrict__ b0, const float* __restrict__ b1,
    const float* __restrict__ b2, float* __restrict__ outp,
    int wbase, int mode)
{
    extern __shared__ char smem[];
    const uint32_t sb = (smem_u32(smem) + 1023) & ~1023u;
    const uint32_t mb = sb + 2*GSTG;
    const int t  = threadIdx.x;
    const int m0 = blockIdx.y * 128;
    const int n0 = blockIdx.x * 64;

    if (t == 0) { MBAR_INIT(mb, 1); MBAR_INIT(mb + 8, 1); }
    __syncthreads();

    auto issue = [&](int ck) {
        const uint32_t d   = sb + (uint32_t)(ck & 1) * GSTG;
        const uint32_t bar = mb + (uint32_t)(ck & 1) * 8;
        EXPECT_TX(bar, (uint32_t)GSTG);
        TMA2D(d + 0,       &mA,  ck*64, m0, bar);
        TMA2D(d + GA,      &mWh, ck*64, wbase + n0, bar);
        TMA2D(d + GA + GW, &mWl, ck*64, wbase + n0, bar);
    };
    if (t == 0) { issue(0); issue(1); }

    const int wid = t >> 5, l = t & 31;
    const int warpM = wid & 1;
    const int warpN = wid >> 1;          // 0..1
    const int q  = l >> 3, lr = l & 7;

    float acc[16][4];
    #pragma unroll
    for (int i = 0; i < 16; i++)
        #pragma unroll
        for (int j = 0; j < 4; j++) acc[i][j] = 0.f;

    uint32_t arow[4], brow[2];
    #pragma unroll
    for (int mt = 0; mt < 4; mt++) arow[mt] = (uint32_t)(warpM*64 + mt*16 + (q & 1)*8 + lr) * 128;
    #pragma unroll
    for (int np = 0; np < 2; np++) brow[np] = (uint32_t)(warpN*32 + np*16 + (q >> 1)*8 + lr) * 128;
    uint32_t axc[4], bxc[4];
    #pragma unroll
    for (int s = 0; s < 4; s++) {
        axc[s] = (uint32_t)((((q >> 1) + 2*s) ^ lr) * 16);
        bxc[s] = (uint32_t)((((q & 1) + 2*s) ^ lr) * 16);
    }

    int ph0 = 0, ph1 = 0;
    for (int ch = 0; ch < DM/64; ch++) {
        const int bsel = ch & 1;
        if (bsel == 0) { mbar_wait(mb,     (uint32_t)ph0); ph0 ^= 1; }
        else           { mbar_wait(mb + 8, (uint32_t)ph1); ph1 ^= 1; }
        const uint32_t bs = sb + (uint32_t)bsel * GSTG;

        #pragma unroll
        for (int s = 0; s < 4; s++) {
            uint32_t ah[4][4];
            #pragma unroll
            for (int mt = 0; mt < 4; mt++)
                LDSM4(ah[mt], bs + arow[mt] + axc[s]);
            uint32_t bh[2][4], bl[2][4];
            #pragma unroll
            for (int np = 0; np < 2; np++) {
                uint32_t bo = brow[np] + bxc[s];
                LDSM4(bh[np], bs + GA      + bo);
                LDSM4(bl[np], bs + GA + GW + bo);
            }
            #pragma unroll
            for (int mt = 0; mt < 4; mt++)
                #pragma unroll
                for (int nt = 0; nt < 4; nt++) {
                    const int np = nt >> 1, h = (nt & 1) * 2;
                    MMA16816H(acc[mt*4+nt], ah[mt], bh[np][h], bh[np][h+1]);
                }
            #pragma unroll
            for (int mt = 0; mt < 4; mt++)
                #pragma unroll
                for (int nt = 0; nt < 4; nt++) {
                    const int np = nt >> 1, h = (nt & 1) * 2;
                    MMA16816H(acc[mt*4+nt], ah[mt], bl[np][h], bl[np][h+1]);
                }
        }
        __syncthreads();
        if (t == 0 && ch + 2 < DM/64) issue(ch + 2);
    }

    // epilogue
    if (mode == 0) {
        const int which = n0 >> 10;
        const float* bias = (which == 0) ? b0 : (which == 1) ? b1 : b2;
        const int nloc0 = n0 & 1023;
        #pragma unroll
        for (int nt = 0; nt < 4; nt++) {
            const int n = nloc0 + warpN*32 + nt*8 + (l & 3)*2;
            const float bx = bias[n], by = bias[n+1];
            #pragma unroll
            for (int mt = 0; mt < 4; mt++) {
                const float* d = acc[mt*4 + nt];
                #pragma unroll
                for (int half = 0; half < 2; half++) {
                    const int m = m0 + warpM*64 + mt*16 + (l >> 2) + half*8;
                    float vx = d[half*2 + 0] + bx;
                    float vy = d[half*2 + 1] + by;
                    const int bb = m >> 11, s = m & (SS-1);
                    const int hh = n >> 6, dd = n & 63;
                    size_t o = (size_t)((bb*NH + hh)*SS + s)*HD + dd;
                    if (which == 0) {
                        *(__half2*)(g_qh + o) = __floats2half2_rn(vx*QSCALE, vy*QSCALE);
                    } else if (which == 1) {
                        *(__half2*)(g_kh + o) = __floats2half2_rn(vx, vy);
                    } else {
                        __half hx = __float2half_rn(vx);
                        __half hy = __float2half_rn(vy);
                        __half lx = __float2half_rn(vx - __half2float(hx));
                        __half ly = __float2half_rn(vy - __half2float(hy));
                        *(__half2*)(g_vh + o) = __halves2half2(hx, hy);
                        *(__half2*)(g_vl + o) = __halves2half2(lx, ly);
                    }
                }
            }
        }
    } else {
        #pragma unroll
        for (int nt = 0; nt < 4; nt++) {
            const int n = n0 + warpN*32 + nt*8 + (l & 3)*2;
            const float bx = b0[n], by = b0[n+1];
            #pragma unroll
            for (int mt = 0; mt < 4; mt++) {
                const float* d = acc[mt*4 + nt];
                #pragma unroll
                for (int half = 0; half < 2; half++) {
                    const int m = m0 + warpM*64 + mt*16 + (l >> 2) + half*8;
                    float2 v;
                    v.x = d[half*2 + 0] + bx;
                    v.y = d[half*2 + 1] + by;
                    *(float2*)&outp[(size_t)m*DM + n] = v;
                }
            }
        }
    }
}

// ---------------------------------------------------------------------------
// Flash attention, fp16: S = Qh·Kh (1 pass), O += Ph(Vh+Vl). exp2 softmax.
// Block: 64 queries x one (b,h); 128 threads = 4 warps; 3 CTAs/SM.
// KV tile 64, double-buffered TMA (SW128).
// ---------------------------------------------------------------------------
#define FQB 8192                  // Q tile: 64 rows x 128B
#define FKB 8192                  // KV array tile: 64 rows x 128B
#define FSTG (3*FKB)              // KH VH VL = 24576
#define FL_SMEM (FQB + 2*FSTG + 1088)   // 58432 -> 3 CTAs/SM

__global__ void __launch_bounds__(128, 3) flash_tma(
    const __grid_constant__ CUtensorMap mQh,
    const __grid_constant__ CUtensorMap mKh,
    const __grid_constant__ CUtensorMap mVh,
    const __grid_constant__ CUtensorMap mVl)
{
    extern __shared__ char fsm[];
    const uint32_t sb  = (smem_u32(fsm) + 1023) & ~1023u;
    const uint32_t kvb = sb + FQB;
    const uint32_t mbq = sb + FQB + 2*FSTG;
    const int bh = blockIdx.y;
    const int q0 = blockIdx.x * 64;
    const int row0 = bh * SS;
    const int t = threadIdx.x, wid = t >> 5, l = t & 31;
    const int q = l >> 3, lr = l & 7;
    const int wq0 = wid * 16;

    if (t == 0) { MBAR_INIT(mbq, 1); MBAR_INIT(mbq + 8, 1); MBAR_INIT(mbq + 16, 1); }
    __syncthreads();

    auto kvissue = [&](int ti) {
        const uint32_t d   = kvb + (uint32_t)(ti & 1) * FSTG;
        const uint32_t bar = mbq + 8 + (uint32_t)(ti & 1) * 8;
        EXPECT_TX(bar, (uint32_t)FSTG);
        const int y = row0 + ti*64;
        TMA2D(d + 0*FKB, &mKh, 0, y, bar);
        TMA2D(d + 1*FKB, &mVh, 0, y, bar);
        TMA2D(d + 2*FKB, &mVl, 0, y, bar);
    };
    if (t == 0) {
        EXPECT_TX(mbq, (uint32_t)FQB);
        TMA2D(sb, &mQh, 0, row0 + q0, mbq);
        kvissue(0);
        kvissue(1);
    }

    mbar_wait(mbq, 0);

    uint32_t qhf[4][4];
    {
        const uint32_t qrow = (uint32_t)(wq0 + (q & 1)*8 + lr) * 128;
        #pragma unroll
        for (int kt = 0; kt < 4; kt++) {
            const uint32_t c = (uint32_t)((((q >> 1) + 2*kt) ^ lr) * 16);
            LDSM4(qhf[kt], sb + qrow + c);
        }
    }

    uint32_t krow[4], vrow[4], kxc[4], vxc[4];
    #pragma unroll
    for (int np = 0; np < 4; np++) krow[np] = (uint32_t)(np*16 + (q >> 1)*8 + lr) * 128;
    #pragma unroll
    for (int kt = 0; kt < 4; kt++) vrow[kt] = (uint32_t)(kt*16 + (q & 1)*8 + lr) * 128;
    #pragma unroll
    for (int kt = 0; kt < 4; kt++) kxc[kt] = (uint32_t)((((q & 1) + 2*kt) ^ lr) * 16);
    #pragma unroll
    for (int g = 0; g < 4; g++)  vxc[g]  = (uint32_t)(((2*g + (q >> 1)) ^ lr) * 16);

    float oacc[8][4];
    #pragma unroll
    for (int i = 0; i < 8; i++)
        #pragma unroll
        for (int j = 0; j < 4; j++) oacc[i][j] = 0.f;
    float mprev0 = -1e30f, mprev1 = -1e30f, lsum0 = 0.f, lsum1 = 0.f;

    int kvph0 = 0, kvph1 = 0;
    for (int ti = 0; ti < SS/64; ti++) {
        const int bsel = ti & 1;
        if (bsel == 0) { mbar_wait(mbq + 8,  (uint32_t)kvph0); kvph0 ^= 1; }
        else           { mbar_wait(mbq + 16, (uint32_t)kvph1); kvph1 ^= 1; }
        const uint32_t kb = kvb + (uint32_t)bsel * FSTG;

        float sacc[8][4];
        #pragma unroll
        for (int i = 0; i < 8; i++)
            #pragma unroll
            for (int j = 0; j < 4; j++) sacc[i][j] = 0.f;

        #pragma unroll
        for (int kt = 0; kt < 4; kt++) {
            uint32_t khf[4][4];
            #pragma unroll
            for (int np = 0; np < 4; np++)
                LDSM4(khf[np], kb + krow[np] + kxc[kt]);
            #pragma unroll
            for (int nt = 0; nt < 8; nt++) {
                const int np = nt >> 1, h = (nt & 1)*2;
                MMA16816H(sacc[nt], qhf[kt], khf[np][h], khf[np][h+1]);
            }
        }

        float m0 = sacc[0][0], m1 = sacc[0][2];
        #pragma unroll
        for (int nt = 0; nt < 8; nt++) {
            m0 = fmaxf(m0, fmaxf(sacc[nt][0], sacc[nt][1]));
            m1 = fmaxf(m1, fmaxf(sacc[nt][2], sacc[nt][3]));
        }
        m0 = fmaxf(m0, __shfl_xor_sync(0xffffffffu, m0, 1));
        m0 = fmaxf(m0, __shfl_xor_sync(0xffffffffu, m0, 2));
        m1 = fmaxf(m1, __shfl_xor_sync(0xffffffffu, m1, 1));
        m1 = fmaxf(m1, __shfl_xor_sync(0xffffffffu, m1, 2));

        const float mn0 = fmaxf(mprev0, m0);
        const float mn1 = fmaxf(mprev1, m1);
        const float a0 = ex2(mprev0 - mn0);
        const float a1 = ex2(mprev1 - mn1);
        mprev0 = mn0; mprev1 = mn1;

        float rs0 = 0.f, rs1 = 0.f;
        #pragma unroll
        for (int nt = 0; nt < 8; nt++) {
            sacc[nt][0] = ex2(sacc[nt][0] - mn0);
            sacc[nt][1] = ex2(sacc[nt][1] - mn0);
            sacc[nt][2] = ex2(sacc[nt][2] - mn1);
            sacc[nt][3] = ex2(sacc[nt][3] - mn1);
            rs0 += sacc[nt][0] + sacc[nt][1];
            rs1 += sacc[nt][2] + sacc[nt][3];
        }
        rs0 += __shfl_xor_sync(0xffffffffu, rs0, 1);
        rs0 += __shfl_xor_sync(0xffffffffu, rs0, 2);
        rs1 += __shfl_xor_sync(0xffffffffu, rs1, 1);
        rs1 += __shfl_xor_sync(0xffffffffu, rs1, 2);
        lsum0 = lsum0*a0 + rs0;
        lsum1 = lsum1*a1 + rs1;
        #pragma unroll
        for (int nj = 0; nj < 8; nj++) {
            oacc[nj][0] *= a0; oacc[nj][1] *= a0;
            oacc[nj][2] *= a1; oacc[nj][3] *= a1;
        }

        #pragma unroll
        for (int kt = 0; kt < 4; kt++) {
            uint32_t ph[4];
            #pragma unroll
            for (int e = 0; e < 4; e++) {
                const float* s0 = sacc[2*kt + (e >> 1)];
                ph[e] = pack_h(s0[(e & 1)*2 + 1], s0[(e & 1)*2]);
            }
            uint32_t vhf[4][4], vlf[4][4];
            #pragma unroll
            for (int g = 0; g < 4; g++) {
                uint32_t va = vrow[kt] + vxc[g];
                LDSM4T(vhf[g], kb + 1*FKB + va);
                LDSM4T(vlf[g], kb + 2*FKB + va);
            }
            #pragma unroll
            for (int nj = 0; nj < 8; nj++) {
                const int g = nj >> 1, o = (nj & 1)*2;
                MMA16816H(oacc[nj], ph, vhf[g][o], vhf[g][o+1]);
            }
            #pragma unroll
            for (int nj = 0; nj < 8; nj++) {
                const int g = nj >> 1, o = (nj & 1)*2;
                MMA16816H(oacc[nj], ph, vlf[g][o], vlf[g][o+1]);
            }
        }

        __syncthreads();
        if (t == 0 && ti + 2 < SS/64) kvissue(ti + 2);
    }

    // epilogue: normalize, write fp16 O into g_a ([B,S,D] layout)
    const float inv0 = 1.0f / lsum0;
    const float inv1 = 1.0f / lsum1;
    const int r0 = q0 + wq0 + (l >> 2);
    const int bb = bh >> 4, hh = bh & 15;
    #pragma unroll
    for (int nj = 0; nj < 8; nj++) {
        const int col = hh*HD + nj*8 + (l & 3)*2;
        *(__half2*)(g_a + (size_t)(bb*SS + r0)*DM + col) =
            __floats2half2_rn(oacc[nj][0]*inv0, oacc[nj][1]*inv0);
        *(__half2*)(g_a + (size_t)(bb*SS + r0 + 8)*DM + col) =
            __floats2half2_rn(oacc[nj][2]*inv1, oacc[nj][3]*inv1);
    }
}

// ---------------------------------------------------------------------------
// host: tensor-map construction via driver entry point (no -lcuda needed)
// ---------------------------------------------------------------------------
typedef CUresult (CUDAAPI *PFN_encodeTiled)(
    CUtensorMap*, CUtensorMapDataType, cuuint32_t, void*,
    const cuuint64_t*, const cuuint64_t*, const cuuint32_t*, const cuuint32_t*,
    CUtensorMapInterleave, CUtensorMapSwizzle, CUtensorMapL2promotion,
    CUtensorMapFloatOOBfill);

static PFN_encodeTiled get_encoder() {
    static PFN_encodeTiled fn = nullptr;
    if (!fn) {
        void* p = nullptr;
        cudaDriverEntryPointQueryResult qr;
        cudaGetDriverEntryPoint("cuTensorMapEncodeTiled", &p, cudaEnableDefault, &qr);
        fn = (PFN_encodeTiled)p;
    }
    return fn;
}

static void mk2d(CUtensorMap* m, void* base, uint64_t d0, uint64_t rows,
                 uint32_t b0, uint32_t b1) {
    cuuint64_t dims[2]    = {d0, rows};
    cuuint64_t strides[1] = {d0 * 2};     // bytes
    cuuint32_t box[2]     = {b0, b1};
    cuuint32_t es[2]      = {1, 1};
    get_encoder()(m, CU_TENSOR_MAP_DATA_TYPE_FLOAT16, 2, base,
                  dims, strides, box, es,
                  CU_TENSOR_MAP_INTERLEAVE_NONE, CU_TENSOR_MAP_SWIZZLE_128B,
                  CU_TENSOR_MAP_L2_PROMOTION_L2_128B,
                  CU_TENSOR_MAP_FLOAT_OOB_FILL_NONE);
}

extern "C" void kernel_launch(void* const* d_in, const int* in_sizes, int n_in,
                              void* d_out, int out_size) {
    const float* x     = (const float*)d_in[0];
    const float* rel   = (const float*)d_in[1];
    const float* alpha = (const float*)d_in[2];
    const float* Wq    = (const float*)d_in[3];
    const float* bq    = (const float*)d_in[4];
    const float* Wk    = (const float*)d_in[5];
    const float* bk    = (const float*)d_in[6];
    const float* Wv    = (const float*)d_in[7];
    const float* bv    = (const float*)d_in[8];
    const float* Wo    = (const float*)d_in[9];
    const float* bo    = (const float*)d_in[10];
    float* out = (float*)d_out;

    cudaFuncSetAttribute(gemm_tma,  cudaFuncAttributeMaxDynamicSharedMemorySize, GEMM_SMEM);
    cudaFuncSetAttribute(flash_tma, cudaFuncAttributeMaxDynamicSharedMemorySize, FL_SMEM);

    void *a, *wh, *wl, *qh, *kh, *vh, *vl;
    cudaGetSymbolAddress(&a,  g_a);
    cudaGetSymbolAddress(&wh, g_wh);
    cudaGetSymbolAddress(&wl, g_wl);
    cudaGetSymbolAddress(&qh, g_qh);
    cudaGetSymbolAddress(&kh, g_kh);
    cudaGetSymbolAddress(&vh, g_vh);
    cudaGetSymbolAddress(&vl, g_vl);

    CUtensorMap mA, mWh, mWl, mQh, mKh, mVh, mVl;
    mk2d(&mA,  a,  DM, MT,          64, 128);
    mk2d(&mWh, wh, DM, 4*DM,        64, 64);
    mk2d(&mWl, wl, DM, 4*DM,        64, 64);
    mk2d(&mQh, qh, HD, BB*NH*SS,    64, 64);
    mk2d(&mKh, kh, HD, BB*NH*SS,    64, 64);
    mk2d(&mVh, vh, HD, BB*NH*SS,    64, 64);
    mk2d(&mVl, vl, HD, BB*NH*SS,    64, 64);

    pe_kernel<<<(MT*(DM/2) + 255)/256, 256>>>(x, rel, alpha);
    split4_kernel<<<(4*NW4 + 255)/256, 256>>>(Wq, Wk, Wv, Wo);

    gemm_tma<<<dim3(3*DM/64, MT/128), 128, GEMM_SMEM>>>(
        mA, mWh, mWl, bq, bk, bv, nullptr, 0, 0);

    flash_tma<<<dim3(SS/64, BB*NH), 128, FL_SMEM>>>(mQh, mKh, mVh, mVl);

    gemm_tma<<<dim3(DM/64, MT/128), 128, GEMM_SMEM>>>(
        mA, mWh, mWl, bo, bo, bo, out, 3*DM, 3);
}

// round 14
// speedup vs baseline: 2.7084x; 1.4329x over previous
#include <cuda_runtime.h>
#include <cuda.h>
#include <cuda_fp16.h>
#include <math.h>
#include <stdint.h>

#define DM 1024
#define NH 16
#define HD 64
#define MSL 5000
#define BB 2
#define SS 2048
#define MT (BB*SS)   // 4096 rows total

// Scratch (allocation-free rule: device globals), all fp16
__device__ __half g_a[MT*DM];         // GEMM A operand (xpe, later attention O)
__device__ __half g_w[4*DM*DM];       // stacked Wq|Wk|Wv|Wo (single fp16)
// Q/K/V in [B,H,S,hd]; Q pre-scaled by log2(e)/32; all single fp16
__device__ __half g_qh[MT*DM];
__device__ __half g_kh[MT*DM];
__device__ __half g_vh[MT*DM];

// ---------------------------------------------------------------------------
// helpers
// ---------------------------------------------------------------------------
__device__ __forceinline__ uint32_t smem_u32(const void* p) {
    uint32_t a;
    asm("{ .reg .u64 t; cvta.to.shared.u64 t, %1; cvt.u32.u64 %0, t; }" : "=r"(a) : "l"(p));
    return a;
}

#define MBAR_INIT(addr, cnt) \
    asm volatile("mbarrier.init.shared.b64 [%0], %1;" :: "r"(addr), "r"(cnt) : "memory")

#define EXPECT_TX(addr, bytes) \
    asm volatile("mbarrier.arrive.expect_tx.shared.b64 _, [%0], %1;" :: "r"(addr), "r"(bytes) : "memory")

#define TMA2D(smem, mapp, x, y, mbar) \
    asm volatile("cp.async.bulk.tensor.2d.shared::cluster.global.tile.mbarrier::complete_tx::bytes " \
        "[%0], [%1, {%2, %3}], [%4];" \
        :: "r"(smem), "l"(mapp), "r"(x), "r"(y), "r"(mbar) : "memory")

__device__ __forceinline__ void mbar_wait(uint32_t addr, uint32_t parity) {
    uint32_t done;
    asm volatile(
        "{\n\t.reg .pred p;\n\t"
        "mbarrier.try_wait.parity.shared.b64 p, [%1], %2;\n\t"
        "selp.b32 %0,1,0,p;\n\t}"
        : "=r"(done) : "r"(addr), "r"(parity) : "memory");
    while (!done) {
        asm volatile(
            "{\n\t.reg .pred p;\n\t"
            "mbarrier.try_wait.parity.shared.b64 p, [%1], %2, 0x989680;\n\t"
            "selp.b32 %0,1,0,p;\n\t}"
            : "=r"(done) : "r"(addr), "r"(parity) : "memory");
    }
}

#define LDSM4(r, addr) \
    asm volatile("ldmatrix.sync.aligned.m8n8.x4.shared.b16 {%0,%1,%2,%3}, [%4];" \
        : "=r"((r)[0]), "=r"((r)[1]), "=r"((r)[2]), "=r"((r)[3]) : "r"(addr))

#define LDSM4T(r, addr) \
    asm volatile("ldmatrix.sync.aligned.m8n8.x4.trans.shared.b16 {%0,%1,%2,%3}, [%4];" \
        : "=r"((r)[0]), "=r"((r)[1]), "=r"((r)[2]), "=r"((r)[3]) : "r"(addr))

// fp16 MMA
#define MMA16816H(d, a, b0v, b1v) \
    asm volatile("mma.sync.aligned.m16n8k16.row.col.f32.f16.f16.f32 " \
        "{%0,%1,%2,%3}, {%4,%5,%6,%7}, {%8,%9}, {%0,%1,%2,%3};" \
        : "+f"((d)[0]), "+f"((d)[1]), "+f"((d)[2]), "+f"((d)[3]) \
        : "r"((a)[0]), "r"((a)[1]), "r"((a)[2]), "r"((a)[3]), "r"(b0v), "r"(b1v))

__device__ __forceinline__ uint32_t pack_h(float hi, float lo) {
    __half2 h = __floats2half2_rn(lo, hi);   // lo -> low half, hi -> high half
    return *reinterpret_cast<uint32_t*>(&h);
}
__device__ __forceinline__ float ex2(float x) {
    float r;
    asm("ex2.approx.ftz.f32 %0, %1;" : "=f"(r) : "f"(x));
    return r;
}

// ---------------------------------------------------------------------------
// Kernel 1: fused PE:  (x + a*sin_pe + (1-a)*rel) -> g_a (fp16)
// ---------------------------------------------------------------------------
__global__ void pe_kernel(const float* __restrict__ x,
                          const float* __restrict__ rel,
                          const float* __restrict__ alphap) {
    int idx = blockIdx.x*blockDim.x + threadIdx.x;
    if (idx >= MT*(DM/2)) return;
    int m  = idx >> 9;
    int pp = idx & 511;
    int s  = m & (SS-1);
    float a = alphap[0];
    float freq = __expf(-(float)(2*pp) * (9.210340371976184f/(float)DM));
    float ang = (float)s * freq;
    float sn, cs;
    sincosf(ang, &sn, &cs);
    const float* rr = rel + (size_t)(MSL - SS + s)*DM + 2*pp;
    float2 xv = *(const float2*)(x + (size_t)idx*2);
    float om = 1.0f - a;
    float ox = xv.x + a*sn + om*rr[0];
    float oy = xv.y + a*cs + om*rr[1];
    *(__half2*)(g_a + (size_t)idx*2) = __floats2half2_rn(ox, oy);
}

// ---------------------------------------------------------------------------
// Kernel 2: all four weight matrices -> fp16 in one launch.
// ---------------------------------------------------------------------------
#define NW4 (DM*DM/4)   // 262144 float4 per matrix
__global__ void conv4_kernel(const float* __restrict__ w0,
                             const float* __restrict__ w1,
                             const float* __restrict__ w2,
                             const float* __restrict__ w3) {
    int i = blockIdx.x*blockDim.x + threadIdx.x;
    if (i >= 4*NW4) return;
    const int which = i >> 18;            // NW4 = 2^18
    const int j = i & (NW4 - 1);
    const float* src = (which == 0) ? w0 : (which == 1) ? w1 : (which == 2) ? w2 : w3;
    float4 v = ((const float4*)src)[j];
    size_t o = (size_t)which*DM*DM + (size_t)j*4;
    __half2* hp = (__half2*)(g_w + o);
    hp[0] = __floats2half2_rn(v.x, v.y);
    hp[1] = __floats2half2_rn(v.z, v.w);
}

// ---------------------------------------------------------------------------
// TMA fp16 GEMM: C = A W^T + bias. Block 128x64, 128 threads,
// warp tile 64x32. K-chunk 64, 2-stage TMA, 3 CTAs/SM.
// mode 0: merged QKV (gridDim.x=48): Q->fp16 scaled, K/V->fp16.
// mode 3: out proj, fp32 row-major.
// ---------------------------------------------------------------------------
#define GA 16384                  // A tile: 128 rows x 128B (SW128)
#define GW 8192                   // W tile: 64 rows x 128B
#define GSTG (GA + GW)            // A W = 24576
#define GEMM_SMEM (2*GSTG + 1088) // 50240 -> 3 CTAs/SM (reg-capped)

#define QSCALE 0.04508422002778f  // log2(e)/32

__global__ void __launch_bounds__(128, 3) gemm_tma(
    const __grid_constant__ CUtensorMap mA,
    const __grid_constant__ CUtensorMap mW,
    const float* __restrict__ b0, const float* __restrict__ b1,
    const float* __restrict__ b2, float* __restrict__ outp,
    int wbase, int mode)
{
    extern __shared__ char smem[];
    const uint32_t sb = (smem_u32(smem) + 1023) & ~1023u;
    const uint32_t mb = sb + 2*GSTG;
    const int t  = threadIdx.x;
    const int m0 = blockIdx.y * 128;
    const int n0 = blockIdx.x * 64;

    if (t == 0) { MBAR_INIT(mb, 1); MBAR_INIT(mb + 8, 1); }
    __syncthreads();

    auto issue = [&](int ck) {
        const uint32_t d   = sb + (uint32_t)(ck & 1) * GSTG;
        const uint32_t bar = mb + (uint32_t)(ck & 1) * 8;
        EXPECT_TX(bar, (uint32_t)GSTG);
        TMA2D(d + 0,  &mA, ck*64, m0, bar);
        TMA2D(d + GA, &mW, ck*64, wbase + n0, bar);
    };
    if (t == 0) { issue(0); issue(1); }

    const int wid = t >> 5, l = t & 31;
    const int warpM = wid & 1;
    const int warpN = wid >> 1;          // 0..1
    const int q  = l >> 3, lr = l & 7;

    float acc[16][4];
    #pragma unroll
    for (int i = 0; i < 16; i++)
        #pragma unroll
        for (int j = 0; j < 4; j++) acc[i][j] = 0.f;

    uint32_t arow[4], brow[2];
    #pragma unroll
    for (int mt = 0; mt < 4; mt++) arow[mt] = (uint32_t)(warpM*64 + mt*16 + (q & 1)*8 + lr) * 128;
    #pragma unroll
    for (int np = 0; np < 2; np++) brow[np] = (uint32_t)(warpN*32 + np*16 + (q >> 1)*8 + lr) * 128;
    uint32_t axc[4], bxc[4];
    #pragma unroll
    for (int s = 0; s < 4; s++) {
        axc[s] = (uint32_t)((((q >> 1) + 2*s) ^ lr) * 16);
        bxc[s] = (uint32_t)((((q & 1) + 2*s) ^ lr) * 16);
    }

    int ph0 = 0, ph1 = 0;
    for (int ch = 0; ch < DM/64; ch++) {
        const int bsel = ch & 1;
        if (bsel == 0) { mbar_wait(mb,     (uint32_t)ph0); ph0 ^= 1; }
        else           { mbar_wait(mb + 8, (uint32_t)ph1); ph1 ^= 1; }
        const uint32_t bs = sb + (uint32_t)bsel * GSTG;

        #pragma unroll
        for (int s = 0; s < 4; s++) {
            uint32_t ah[4][4];
            #pragma unroll
            for (int mt = 0; mt < 4; mt++)
                LDSM4(ah[mt], bs + arow[mt] + axc[s]);
            uint32_t bh[2][4];
            #pragma unroll
            for (int np = 0; np < 2; np++)
                LDSM4(bh[np], bs + GA + brow[np] + bxc[s]);
            #pragma unroll
            for (int mt = 0; mt < 4; mt++)
                #pragma unroll
                for (int nt = 0; nt < 4; nt++) {
                    const int np = nt >> 1, h = (nt & 1) * 2;
                    MMA16816H(acc[mt*4+nt], ah[mt], bh[np][h], bh[np][h+1]);
                }
        }
        __syncthreads();
        if (t == 0 && ch + 2 < DM/64) issue(ch + 2);
    }

    // epilogue
    if (mode == 0) {
        const int which = n0 >> 10;
        const float* bias = (which == 0) ? b0 : (which == 1) ? b1 : b2;
        __half* dst = (which == 0) ? g_qh : (which == 1) ? g_kh : g_vh;
        const float scl = (which == 0) ? QSCALE : 1.0f;
        const int nloc0 = n0 & 1023;
        #pragma unroll
        for (int nt = 0; nt < 4; nt++) {
            const int n = nloc0 + warpN*32 + nt*8 + (l & 3)*2;
            const float bx = bias[n], by = bias[n+1];
            #pragma unroll
            for (int mt = 0; mt < 4; mt++) {
                const float* d = acc[mt*4 + nt];
                #pragma unroll
                for (int half = 0; half < 2; half++) {
                    const int m = m0 + warpM*64 + mt*16 + (l >> 2) + half*8;
                    float vx = (d[half*2 + 0] + bx) * scl;
                    float vy = (d[half*2 + 1] + by) * scl;
                    const int bb = m >> 11, s = m & (SS-1);
                    const int hh = n >> 6, dd = n & 63;
                    size_t o = (size_t)((bb*NH + hh)*SS + s)*HD + dd;
                    *(__half2*)(dst + o) = __floats2half2_rn(vx, vy);
                }
            }
        }
    } else {
        #pragma unroll
        for (int nt = 0; nt < 4; nt++) {
            const int n = n0 + warpN*32 + nt*8 + (l & 3)*2;
            const float bx = b0[n], by = b0[n+1];
            #pragma unroll
            for (int mt = 0; mt < 4; mt++) {
                const float* d = acc[mt*4 + nt];
                #pragma unroll
                for (int half = 0; half < 2; half++) {
                    const int m = m0 + warpM*64 + mt*16 + (l >> 2) + half*8;
                    float2 v;
                    v.x = d[half*2 + 0] + bx;
                    v.y = d[half*2 + 1] + by;
                    *(float2*)&outp[(size_t)m*DM + n] = v;
                }
            }
        }
    }
}

// ---------------------------------------------------------------------------
// Flash attention, fp16 single-term: S = Q·K, O += P·V. exp2 softmax.
// Block: 64 queries x one (b,h); 128 threads = 4 warps; 3 CTAs/SM.
// KV tile 64, double-buffered TMA (SW128).
// ---------------------------------------------------------------------------
#define FQB 8192                  // Q tile: 64 rows x 128B
#define FKB 8192                  // KV array tile: 64 rows x 128B
#define FSTG (2*FKB)              // KH VH = 16384
#define FL_SMEM (FQB + 2*FSTG + 1088)   // 42048 -> 3 CTAs/SM (reg-capped)

__global__ void __launch_bounds__(128, 3) flash_tma(
    const __grid_constant__ CUtensorMap mQh,
    const __grid_constant__ CUtensorMap mKh,
    const __grid_constant__ CUtensorMap mVh)
{
    extern __shared__ char fsm[];
    const uint32_t sb  = (smem_u32(fsm) + 1023) & ~1023u;
    const uint32_t kvb = sb + FQB;
    const uint32_t mbq = sb + FQB + 2*FSTG;
    const int bh = blockIdx.y;
    const int q0 = blockIdx.x * 64;
    const int row0 = bh * SS;
    const int t = threadIdx.x, wid = t >> 5, l = t & 31;
    const int q = l >> 3, lr = l & 7;
    const int wq0 = wid * 16;

    if (t == 0) { MBAR_INIT(mbq, 1); MBAR_INIT(mbq + 8, 1); MBAR_INIT(mbq + 16, 1); }
    __syncthreads();

    auto kvissue = [&](int ti) {
        const uint32_t d   = kvb + (uint32_t)(ti & 1) * FSTG;
        const uint32_t bar = mbq + 8 + (uint32_t)(ti & 1) * 8;
        EXPECT_TX(bar, (uint32_t)FSTG);
        const int y = row0 + ti*64;
        TMA2D(d + 0*FKB, &mKh, 0, y, bar);
        TMA2D(d + 1*FKB, &mVh, 0, y, bar);
    };
    if (t == 0) {
        EXPECT_TX(mbq, (uint32_t)FQB);
        TMA2D(sb, &mQh, 0, row0 + q0, mbq);
        kvissue(0);
        kvissue(1);
    }

    mbar_wait(mbq, 0);

    uint32_t qhf[4][4];
    {
        const uint32_t qrow = (uint32_t)(wq0 + (q & 1)*8 + lr) * 128;
        #pragma unroll
        for (int kt = 0; kt < 4; kt++) {
            const uint32_t c = (uint32_t)((((q >> 1) + 2*kt) ^ lr) * 16);
            LDSM4(qhf[kt], sb + qrow + c);
        }
    }

    uint32_t krow[4], vrow[4], kxc[4], vxc[4];
    #pragma unroll
    for (int np = 0; np < 4; np++) krow[np] = (uint32_t)(np*16 + (q >> 1)*8 + lr) * 128;
    #pragma unroll
    for (int kt = 0; kt < 4; kt++) vrow[kt] = (uint32_t)(kt*16 + (q & 1)*8 + lr) * 128;
    #pragma unroll
    for (int kt = 0; kt < 4; kt++) kxc[kt] = (uint32_t)((((q & 1) + 2*kt) ^ lr) * 16);
    #pragma unroll
    for (int g = 0; g < 4; g++)  vxc[g]  = (uint32_t)(((2*g + (q >> 1)) ^ lr) * 16);

    float oacc[8][4];
    #pragma unroll
    for (int i = 0; i < 8; i++)
        #pragma unroll
        for (int j = 0; j < 4; j++) oacc[i][j] = 0.f;
    float mprev0 = -1e30f, mprev1 = -1e30f, lsum0 = 0.f, lsum1 = 0.f;

    int kvph0 = 0, kvph1 = 0;
    for (int ti = 0; ti < SS/64; ti++) {
        const int bsel = ti & 1;
        if (bsel == 0) { mbar_wait(mbq + 8,  (uint32_t)kvph0); kvph0 ^= 1; }
        else           { mbar_wait(mbq + 16, (uint32_t)kvph1); kvph1 ^= 1; }
        const uint32_t kb = kvb + (uint32_t)bsel * FSTG;

        float sacc[8][4];
        #pragma unroll
        for (int i = 0; i < 8; i++)
            #pragma unroll
            for (int j = 0; j < 4; j++) sacc[i][j] = 0.f;

        #pragma unroll
        for (int kt = 0; kt < 4; kt++) {
            uint32_t khf[4][4];
            #pragma unroll
            for (int np = 0; np < 4; np++)
                LDSM4(khf[np], kb + krow[np] + kxc[kt]);
            #pragma unroll
            for (int nt = 0; nt < 8; nt++) {
                const int np = nt >> 1, h = (nt & 1)*2;
                MMA16816H(sacc[nt], qhf[kt], khf[np][h], khf[np][h+1]);
            }
        }

        float m0 = sacc[0][0], m1 = sacc[0][2];
        #pragma unroll
        for (int nt = 0; nt < 8; nt++) {
            m0 = fmaxf(m0, fmaxf(sacc[nt][0], sacc[nt][1]));
            m1 = fmaxf(m1, fmaxf(sacc[nt][2], sacc[nt][3]));
        }
        m0 = fmaxf(m0, __shfl_xor_sync(0xffffffffu, m0, 1));
        m0 = fmaxf(m0, __shfl_xor_sync(0xffffffffu, m0, 2));
        m1 = fmaxf(m1, __shfl_xor_sync(0xffffffffu, m1, 1));
        m1 = fmaxf(m1, __shfl_xor_sync(0xffffffffu, m1, 2));

        const float mn0 = fmaxf(mprev0, m0);
        const float mn1 = fmaxf(mprev1, m1);
        const float a0 = ex2(mprev0 - mn0);
        const float a1 = ex2(mprev1 - mn1);
        mprev0 = mn0; mprev1 = mn1;

        float rs0 = 0.f, rs1 = 0.f;
        #pragma unroll
        for (int nt = 0; nt < 8; nt++) {
            sacc[nt][0] = ex2(sacc[nt][0] - mn0);
            sacc[nt][1] = ex2(sacc[nt][1] - mn0);
            sacc[nt][2] = ex2(sacc[nt][2] - mn1);
            sacc[nt][3] = ex2(sacc[nt][3] - mn1);
            rs0 += sacc[nt][0] + sacc[nt][1];
            rs1 += sacc[nt][2] + sacc[nt][3];
        }
        rs0 += __shfl_xor_sync(0xffffffffu, rs0, 1);
        rs0 += __shfl_xor_sync(0xffffffffu, rs0, 2);
        rs1 += __shfl_xor_sync(0xffffffffu, rs1, 1);
        rs1 += __shfl_xor_sync(0xffffffffu, rs1, 2);
        lsum0 = lsum0*a0 + rs0;
        lsum1 = lsum1*a1 + rs1;
        #pragma unroll
        for (int nj = 0; nj < 8; nj++) {
            oacc[nj][0] *= a0; oacc[nj][1] *= a0;
            oacc[nj][2] *= a1; oacc[nj][3] *= a1;
        }

        #pragma unroll
        for (int kt = 0; kt < 4; kt++) {
            uint32_t ph[4];
            #pragma unroll
            for (int e = 0; e < 4; e++) {
                const float* s0 = sacc[2*kt + (e >> 1)];
                ph[e] = pack_h(s0[(e & 1)*2 + 1], s0[(e & 1)*2]);
            }
            uint32_t vhf[4][4];
            #pragma unroll
            for (int g = 0; g < 4; g++)
                LDSM4T(vhf[g], kb + FKB + vrow[kt] + vxc[g]);
            #pragma unroll
            for (int nj = 0; nj < 8; nj++) {
                const int g = nj >> 1, o = (nj & 1)*2;
                MMA16816H(oacc[nj], ph, vhf[g][o], vhf[g][o+1]);
            }
        }

        __syncthreads();
        if (t == 0 && ti + 2 < SS/64) kvissue(ti + 2);
    }

    // epilogue: normalize, write fp16 O into g_a ([B,S,D] layout)
    const float inv0 = 1.0f / lsum0;
    const float inv1 = 1.0f / lsum1;
    const int r0 = q0 + wq0 + (l >> 2);
    const int bb = bh >> 4, hh = bh & 15;
    #pragma unroll
    for (int nj = 0; nj < 8; nj++) {
        const int col = hh*HD + nj*8 + (l & 3)*2;
        *(__half2*)(g_a + (size_t)(bb*SS + r0)*DM + col) =
            __floats2half2_rn(oacc[nj][0]*inv0, oacc[nj][1]*inv0);
        *(__half2*)(g_a + (size_t)(bb*SS + r0 + 8)*DM + col) =
            __floats2half2_rn(oacc[nj][2]*inv1, oacc[nj][3]*inv1);
    }
}

// ---------------------------------------------------------------------------
// host: tensor-map construction via driver entry point (no -lcuda needed)
// ---------------------------------------------------------------------------
typedef CUresult (CUDAAPI *PFN_encodeTiled)(
    CUtensorMap*, CUtensorMapDataType, cuuint32_t, void*,
    const cuuint64_t*, const cuuint64_t*, const cuuint32_t*, const cuuint32_t*,
    CUtensorMapInterleave, CUtensorMapSwizzle, CUtensorMapL2promotion,
    CUtensorMapFloatOOBfill);

static PFN_encodeTiled get_encoder() {
    static PFN_encodeTiled fn = nullptr;
    if (!fn) {
        void* p = nullptr;
        cudaDriverEntryPointQueryResult qr;
        cudaGetDriverEntryPoint("cuTensorMapEncodeTiled", &p, cudaEnableDefault, &qr);
        fn = (PFN_encodeTiled)p;
    }
    return fn;
}

static void mk2d(CUtensorMap* m, void* base, uint64_t d0, uint64_t rows,
                 uint32_t b0, uint32_t b1) {
    cuuint64_t dims[2]    = {d0, rows};
    cuuint64_t strides[1] = {d0 * 2};     // bytes
    cuuint32_t box[2]     = {b0, b1};
    cuuint32_t es[2]      = {1, 1};
    get_encoder()(m, CU_TENSOR_MAP_DATA_TYPE_FLOAT16, 2, base,
                  dims, strides, box, es,
                  CU_TENSOR_MAP_INTERLEAVE_NONE, CU_TENSOR_MAP_SWIZZLE_128B,
                  CU_TENSOR_MAP_L2_PROMOTION_L2_128B,
                  CU_TENSOR_MAP_FLOAT_OOB_FILL_NONE);
}

extern "C" void kernel_launch(void* const* d_in, const int* in_sizes, int n_in,
                              void* d_out, int out_size) {
    const float* x     = (const float*)d_in[0];
    const float* rel   = (const float*)d_in[1];
    const float* alpha = (const float*)d_in[2];
    const float* Wq    = (const float*)d_in[3];
    const float* bq    = (const float*)d_in[4];
    const float* Wk    = (const float*)d_in[5];
    const float* bk    = (const float*)d_in[6];
    const float* Wv    = (const float*)d_in[7];
    const float* bv    = (const float*)d_in[8];
    const float* Wo    = (const float*)d_in[9];
    const float* bo    = (const float*)d_in[10];
    float* out = (float*)d_out;

    cudaFuncSetAttribute(gemm_tma,  cudaFuncAttributeMaxDynamicSharedMemorySize, GEMM_SMEM);
    cudaFuncSetAttribute(flash_tma, cudaFuncAttributeMaxDynamicSharedMemorySize, FL_SMEM);

    void *a, *w, *qh, *kh, *vh;
    cudaGetSymbolAddress(&a,  g_a);
    cudaGetSymbolAddress(&w,  g_w);
    cudaGetSymbolAddress(&qh, g_qh);
    cudaGetSymbolAddress(&kh, g_kh);
    cudaGetSymbolAddress(&vh, g_vh);

    CUtensorMap mA, mW, mQh, mKh, mVh;
    mk2d(&mA,  a,  DM, MT,          64, 128);
    mk2d(&mW,  w,  DM, 4*DM,        64, 64);
    mk2d(&mQh, qh, HD, BB*NH*SS,    64, 64);
    mk2d(&mKh, kh, HD, BB*NH*SS,    64, 64);
    mk2d(&mVh, vh, HD, BB*NH*SS,    64, 64);

    pe_kernel<<<(MT*(DM/2) + 255)/256, 256>>>(x, rel, alpha);
    conv4_kernel<<<(4*NW4 + 255)/256, 256>>>(Wq, Wk, Wv, Wo);

    gemm_tma<<<dim3(3*DM/64, MT/128), 128, GEMM_SMEM>>>(
        mA, mW, bq, bk, bv, nullptr, 0, 0);

    flash_tma<<<dim3(SS/64, BB*NH), 128, FL_SMEM>>>(mQh, mKh, mVh);

    gemm_tma<<<dim3(DM/64, MT/128), 128, GEMM_SMEM>>>(
        mA, mW, bo, bo, bo, out, 3*DM, 3);
}

// round 16
// speedup vs baseline: 2.9242x; 1.0797x over previous
#include <cuda_runtime.h>
#include <cuda.h>
#include <cuda_fp16.h>
#include <math.h>
#include <stdint.h>

#define DM 1024
#define NH 16
#define HD 64
#define MSL 5000
#define BB 2
#define SS 2048
#define MT (BB*SS)   // 4096 rows total

// Scratch (allocation-free rule: device globals), all fp16
__device__ __half g_a[MT*DM];         // GEMM A operand (xpe, later attention O)
__device__ __half g_w[4*DM*DM];       // stacked Wq|Wk|Wv|Wo (single fp16)
// Q/K/V in [B,H,S,hd]; Q pre-scaled by log2(e)/32; all single fp16
__device__ __half g_qh[MT*DM];
__device__ __half g_kh[MT*DM];
__device__ __half g_vh[MT*DM];

// ---------------------------------------------------------------------------
// helpers
// ---------------------------------------------------------------------------
__device__ __forceinline__ uint32_t smem_u32(const void* p) {
    uint32_t a;
    asm("{ .reg .u64 t; cvta.to.shared.u64 t, %1; cvt.u32.u64 %0, t; }" : "=r"(a) : "l"(p));
    return a;
}

#define MBAR_INIT(addr, cnt) \
    asm volatile("mbarrier.init.shared.b64 [%0], %1;" :: "r"(addr), "r"(cnt) : "memory")

#define EXPECT_TX(addr, bytes) \
    asm volatile("mbarrier.arrive.expect_tx.shared.b64 _, [%0], %1;" :: "r"(addr), "r"(bytes) : "memory")

#define TMA2D(smem, mapp, x, y, mbar) \
    asm volatile("cp.async.bulk.tensor.2d.shared::cluster.global.tile.mbarrier::complete_tx::bytes " \
        "[%0], [%1, {%2, %3}], [%4];" \
        :: "r"(smem), "l"(mapp), "r"(x), "r"(y), "r"(mbar) : "memory")

__device__ __forceinline__ void mbar_wait(uint32_t addr, uint32_t parity) {
    uint32_t done;
    asm volatile(
        "{\n\t.reg .pred p;\n\t"
        "mbarrier.try_wait.parity.shared.b64 p, [%1], %2;\n\t"
        "selp.b32 %0,1,0,p;\n\t}"
        : "=r"(done) : "r"(addr), "r"(parity) : "memory");
    while (!done) {
        asm volatile(
            "{\n\t.reg .pred p;\n\t"
            "mbarrier.try_wait.parity.shared.b64 p, [%1], %2, 0x989680;\n\t"
            "selp.b32 %0,1,0,p;\n\t}"
            : "=r"(done) : "r"(addr), "r"(parity) : "memory");
    }
}

#define LDSM4(r, addr) \
    asm volatile("ldmatrix.sync.aligned.m8n8.x4.shared.b16 {%0,%1,%2,%3}, [%4];" \
        : "=r"((r)[0]), "=r"((r)[1]), "=r"((r)[2]), "=r"((r)[3]) : "r"(addr))

#define LDSM4T(r, addr) \
    asm volatile("ldmatrix.sync.aligned.m8n8.x4.trans.shared.b16 {%0,%1,%2,%3}, [%4];" \
        : "=r"((r)[0]), "=r"((r)[1]), "=r"((r)[2]), "=r"((r)[3]) : "r"(addr))

// fp16 MMA
#define MMA16816H(d, a, b0v, b1v) \
    asm volatile("mma.sync.aligned.m16n8k16.row.col.f32.f16.f16.f32 " \
        "{%0,%1,%2,%3}, {%4,%5,%6,%7}, {%8,%9}, {%0,%1,%2,%3};" \
        : "+f"((d)[0]), "+f"((d)[1]), "+f"((d)[2]), "+f"((d)[3]) \
        : "r"((a)[0]), "r"((a)[1]), "r"((a)[2]), "r"((a)[3]), "r"(b0v), "r"(b1v))

__device__ __forceinline__ uint32_t pack_h(float hi, float lo) {
    __half2 h = __floats2half2_rn(lo, hi);   // lo -> low half, hi -> high half
    return *reinterpret_cast<uint32_t*>(&h);
}
__device__ __forceinline__ float ex2(float x) {
    float r;
    asm("ex2.approx.ftz.f32 %0, %1;" : "=f"(r) : "f"(x));
    return r;
}

// ---------------------------------------------------------------------------
// Kernel 1: fused PE:  (x + a*sin_pe + (1-a)*rel) -> g_a (fp16)
// ---------------------------------------------------------------------------
__global__ void pe_kernel(const float* __restrict__ x,
                          const float* __restrict__ rel,
                          const float* __restrict__ alphap) {
    int idx = blockIdx.x*blockDim.x + threadIdx.x;
    if (idx >= MT*(DM/2)) return;
    int m  = idx >> 9;
    int pp = idx & 511;
    int s  = m & (SS-1);
    float a = alphap[0];
    float freq = __expf(-(float)(2*pp) * (9.210340371976184f/(float)DM));
    float ang = (float)s * freq;
    float sn, cs;
    sincosf(ang, &sn, &cs);
    const float* rr = rel + (size_t)(MSL - SS + s)*DM + 2*pp;
    float2 xv = *(const float2*)(x + (size_t)idx*2);
    float om = 1.0f - a;
    float ox = xv.x + a*sn + om*rr[0];
    float oy = xv.y + a*cs + om*rr[1];
    *(__half2*)(g_a + (size_t)idx*2) = __floats2half2_rn(ox, oy);
}

// ---------------------------------------------------------------------------
// Kernel 2: all four weight matrices -> fp16 in one launch.
// ---------------------------------------------------------------------------
#define NW4 (DM*DM/4)   // 262144 float4 per matrix
__global__ void conv4_kernel(const float* __restrict__ w0,
                             const float* __restrict__ w1,
                             const float* __restrict__ w2,
                             const float* __restrict__ w3) {
    int i = blockIdx.x*blockDim.x + threadIdx.x;
    if (i >= 4*NW4) return;
    const int which = i >> 18;            // NW4 = 2^18
    const int j = i & (NW4 - 1);
    const float* src = (which == 0) ? w0 : (which == 1) ? w1 : (which == 2) ? w2 : w3;
    float4 v = ((const float4*)src)[j];
    size_t o = (size_t)which*DM*DM + (size_t)j*4;
    __half2* hp = (__half2*)(g_w + o);
    hp[0] = __floats2half2_rn(v.x, v.y);
    hp[1] = __floats2half2_rn(v.z, v.w);
}

// ---------------------------------------------------------------------------
// TMA fp16 GEMM: C = A W^T + bias. Block 128x64, 128 threads,
// warp tile 64x32. K-chunk 64, 2-stage TMA, 3 CTAs/SM.
// mode 0: merged QKV (gridDim.x=48): Q->fp16 scaled, K/V->fp16.
// mode 3: out proj, fp32 row-major.
// ---------------------------------------------------------------------------
#define GA 16384                  // A tile: 128 rows x 128B (SW128)
#define GW 8192                   // W tile: 64 rows x 128B
#define GSTG (GA + GW)            // A W = 24576
#define GEMM_SMEM (2*GSTG + 1088) // 50240 -> 3 CTAs/SM (reg-capped)

#define QSCALE 0.04508422002778f  // log2(e)/32
#define SMAX   16.0f              // fixed softmax stabilizer (log2 domain)

__global__ void __launch_bounds__(128, 3) gemm_tma(
    const __grid_constant__ CUtensorMap mA,
    const __grid_constant__ CUtensorMap mW,
    const float* __restrict__ b0, const float* __restrict__ b1,
    const float* __restrict__ b2, float* __restrict__ outp,
    int wbase, int mode)
{
    extern __shared__ char smem[];
    const uint32_t sb = (smem_u32(smem) + 1023) & ~1023u;
    const uint32_t mb = sb + 2*GSTG;
    const int t  = threadIdx.x;
    const int m0 = blockIdx.y * 128;
    const int n0 = blockIdx.x * 64;

    if (t == 0) { MBAR_INIT(mb, 1); MBAR_INIT(mb + 8, 1); }
    __syncthreads();

    auto issue = [&](int ck) {
        const uint32_t d   = sb + (uint32_t)(ck & 1) * GSTG;
        const uint32_t bar = mb + (uint32_t)(ck & 1) * 8;
        EXPECT_TX(bar, (uint32_t)GSTG);
        TMA2D(d + 0,  &mA, ck*64, m0, bar);
        TMA2D(d + GA, &mW, ck*64, wbase + n0, bar);
    };
    if (t == 0) { issue(0); issue(1); }

    const int wid = t >> 5, l = t & 31;
    const int warpM = wid & 1;
    const int warpN = wid >> 1;          // 0..1
    const int q  = l >> 3, lr = l & 7;

    float acc[16][4];
    #pragma unroll
    for (int i = 0; i < 16; i++)
        #pragma unroll
        for (int j = 0; j < 4; j++) acc[i][j] = 0.f;

    uint32_t arow[4], brow[2];
    #pragma unroll
    for (int mt = 0; mt < 4; mt++) arow[mt] = (uint32_t)(warpM*64 + mt*16 + (q & 1)*8 + lr) * 128;
    #pragma unroll
    for (int np = 0; np < 2; np++) brow[np] = (uint32_t)(warpN*32 + np*16 + (q >> 1)*8 + lr) * 128;
    uint32_t axc[4], bxc[4];
    #pragma unroll
    for (int s = 0; s < 4; s++) {
        axc[s] = (uint32_t)((((q >> 1) + 2*s) ^ lr) * 16);
        bxc[s] = (uint32_t)((((q & 1) + 2*s) ^ lr) * 16);
    }

    int ph0 = 0, ph1 = 0;
    for (int ch = 0; ch < DM/64; ch++) {
        const int bsel = ch & 1;
        if (bsel == 0) { mbar_wait(mb,     (uint32_t)ph0); ph0 ^= 1; }
        else           { mbar_wait(mb + 8, (uint32_t)ph1); ph1 ^= 1; }
        const uint32_t bs = sb + (uint32_t)bsel * GSTG;

        #pragma unroll
        for (int s = 0; s < 4; s++) {
            uint32_t ah[4][4];
            #pragma unroll
            for (int mt = 0; mt < 4; mt++)
                LDSM4(ah[mt], bs + arow[mt] + axc[s]);
            uint32_t bh[2][4];
            #pragma unroll
            for (int np = 0; np < 2; np++)
                LDSM4(bh[np], bs + GA + brow[np] + bxc[s]);
            #pragma unroll
            for (int mt = 0; mt < 4; mt++)
                #pragma unroll
                for (int nt = 0; nt < 4; nt++) {
                    const int np = nt >> 1, h = (nt & 1) * 2;
                    MMA16816H(acc[mt*4+nt], ah[mt], bh[np][h], bh[np][h+1]);
                }
        }
        __syncthreads();
        if (t == 0 && ch + 2 < DM/64) issue(ch + 2);
    }

    // epilogue
    if (mode == 0) {
        const int which = n0 >> 10;
        const float* bias = (which == 0) ? b0 : (which == 1) ? b1 : b2;
        __half* dst = (which == 0) ? g_qh : (which == 1) ? g_kh : g_vh;
        const float scl = (which == 0) ? QSCALE : 1.0f;
        const int nloc0 = n0 & 1023;
        #pragma unroll
        for (int nt = 0; nt < 4; nt++) {
            const int n = nloc0 + warpN*32 + nt*8 + (l & 3)*2;
            const float bx = bias[n], by = bias[n+1];
            #pragma unroll
            for (int mt = 0; mt < 4; mt++) {
                const float* d = acc[mt*4 + nt];
                #pragma unroll
                for (int half = 0; half < 2; half++) {
                    const int m = m0 + warpM*64 + mt*16 + (l >> 2) + half*8;
                    float vx = (d[half*2 + 0] + bx) * scl;
                    float vy = (d[half*2 + 1] + by) * scl;
                    const int bb = m >> 11, s = m & (SS-1);
                    const int hh = n >> 6, dd = n & 63;
                    size_t o = (size_t)((bb*NH + hh)*SS + s)*HD + dd;
                    *(__half2*)(dst + o) = __floats2half2_rn(vx, vy);
                }
            }
        }
    } else {
        #pragma unroll
        for (int nt = 0; nt < 4; nt++) {
            const int n = n0 + warpN*32 + nt*8 + (l & 3)*2;
            const float bx = b0[n], by = b0[n+1];
            #pragma unroll
            for (int mt = 0; mt < 4; mt++) {
                const float* d = acc[mt*4 + nt];
                #pragma unroll
                for (int half = 0; half < 2; half++) {
                    const int m = m0 + warpM*64 + mt*16 + (l >> 2) + half*8;
                    float2 v;
                    v.x = d[half*2 + 0] + bx;
                    v.y = d[half*2 + 1] + by;
                    *(float2*)&outp[(size_t)m*DM + n] = v;
                }
            }
        }
    }
}

// ---------------------------------------------------------------------------
// Flash attention, fp16, FIXED-MAX softmax: P = exp2(s - SMAX), no online
// rescaling; row sums deferred to one shfl pair at the end.
// Block: 64 queries x one (b,h); 128 threads = 4 warps; 3 CTAs/SM.
// KV tile 64, double-buffered TMA (SW128).
// ---------------------------------------------------------------------------
#define FQB 8192                  // Q tile: 64 rows x 128B
#define FKB 8192                  // KV array tile: 64 rows x 128B
#define FSTG (2*FKB)              // KH VH = 16384
#define FL_SMEM (FQB + 2*FSTG + 1088)   // 42048 -> 3 CTAs/SM (reg-capped)

__global__ void __launch_bounds__(128, 3) flash_tma(
    const __grid_constant__ CUtensorMap mQh,
    const __grid_constant__ CUtensorMap mKh,
    const __grid_constant__ CUtensorMap mVh)
{
    extern __shared__ char fsm[];
    const uint32_t sb  = (smem_u32(fsm) + 1023) & ~1023u;
    const uint32_t kvb = sb + FQB;
    const uint32_t mbq = sb + FQB + 2*FSTG;
    const int bh = blockIdx.y;
    const int q0 = blockIdx.x * 64;
    const int row0 = bh * SS;
    const int t = threadIdx.x, wid = t >> 5, l = t & 31;
    const int q = l >> 3, lr = l & 7;
    const int wq0 = wid * 16;

    if (t == 0) { MBAR_INIT(mbq, 1); MBAR_INIT(mbq + 8, 1); MBAR_INIT(mbq + 16, 1); }
    __syncthreads();

    auto kvissue = [&](int ti) {
        const uint32_t d   = kvb + (uint32_t)(ti & 1) * FSTG;
        const uint32_t bar = mbq + 8 + (uint32_t)(ti & 1) * 8;
        EXPECT_TX(bar, (uint32_t)FSTG);
        const int y = row0 + ti*64;
        TMA2D(d + 0*FKB, &mKh, 0, y, bar);
        TMA2D(d + 1*FKB, &mVh, 0, y, bar);
    };
    if (t == 0) {
        EXPECT_TX(mbq, (uint32_t)FQB);
        TMA2D(sb, &mQh, 0, row0 + q0, mbq);
        kvissue(0);
        kvissue(1);
    }

    mbar_wait(mbq, 0);

    uint32_t qhf[4][4];
    {
        const uint32_t qrow = (uint32_t)(wq0 + (q & 1)*8 + lr) * 128;
        #pragma unroll
        for (int kt = 0; kt < 4; kt++) {
            const uint32_t c = (uint32_t)((((q >> 1) + 2*kt) ^ lr) * 16);
            LDSM4(qhf[kt], sb + qrow + c);
        }
    }

    uint32_t krow[4], vrow[4], kxc[4], vxc[4];
    #pragma unroll
    for (int np = 0; np < 4; np++) krow[np] = (uint32_t)(np*16 + (q >> 1)*8 + lr) * 128;
    #pragma unroll
    for (int kt = 0; kt < 4; kt++) vrow[kt] = (uint32_t)(kt*16 + (q & 1)*8 + lr) * 128;
    #pragma unroll
    for (int kt = 0; kt < 4; kt++) kxc[kt] = (uint32_t)((((q & 1) + 2*kt) ^ lr) * 16);
    #pragma unroll
    for (int g = 0; g < 4; g++)  vxc[g]  = (uint32_t)(((2*g + (q >> 1)) ^ lr) * 16);

    float oacc[8][4];
    #pragma unroll
    for (int i = 0; i < 8; i++)
        #pragma unroll
        for (int j = 0; j < 4; j++) oacc[i][j] = 0.f;
    float lsum0 = 0.f, lsum1 = 0.f;   // per-lane partial row sums

    int kvph0 = 0, kvph1 = 0;
    for (int ti = 0; ti < SS/64; ti++) {
        const int bsel = ti & 1;
        if (bsel == 0) { mbar_wait(mbq + 8,  (uint32_t)kvph0); kvph0 ^= 1; }
        else           { mbar_wait(mbq + 16, (uint32_t)kvph1); kvph1 ^= 1; }
        const uint32_t kb = kvb + (uint32_t)bsel * FSTG;

        float sacc[8][4];
        #pragma unroll
        for (int i = 0; i < 8; i++)
            #pragma unroll
            for (int j = 0; j < 4; j++) sacc[i][j] = 0.f;

        #pragma unroll
        for (int kt = 0; kt < 4; kt++) {
            uint32_t khf[4][4];
            #pragma unroll
            for (int np = 0; np < 4; np++)
                LDSM4(khf[np], kb + krow[np] + kxc[kt]);
            #pragma unroll
            for (int nt = 0; nt < 8; nt++) {
                const int np = nt >> 1, h = (nt & 1)*2;
                MMA16816H(sacc[nt], qhf[kt], khf[np][h], khf[np][h+1]);
            }
        }

        // fixed-max softmax weights (log2 domain): P = exp2(s - SMAX)
        #pragma unroll
        for (int nt = 0; nt < 8; nt++) {
            sacc[nt][0] = ex2(sacc[nt][0] - SMAX);
            sacc[nt][1] = ex2(sacc[nt][1] - SMAX);
            sacc[nt][2] = ex2(sacc[nt][2] - SMAX);
            sacc[nt][3] = ex2(sacc[nt][3] - SMAX);
            lsum0 += sacc[nt][0] + sacc[nt][1];
            lsum1 += sacc[nt][2] + sacc[nt][3];
        }

        #pragma unroll
        for (int kt = 0; kt < 4; kt++) {
            uint32_t ph[4];
            #pragma unroll
            for (int e = 0; e < 4; e++) {
                const float* s0 = sacc[2*kt + (e >> 1)];
                ph[e] = pack_h(s0[(e & 1)*2 + 1], s0[(e & 1)*2]);
            }
            uint32_t vhf[4][4];
            #pragma unroll
            for (int g = 0; g < 4; g++)
                LDSM4T(vhf[g], kb + FKB + vrow[kt] + vxc[g]);
            #pragma unroll
            for (int nj = 0; nj < 8; nj++) {
                const int g = nj >> 1, o = (nj & 1)*2;
                MMA16816H(oacc[nj], ph, vhf[g][o], vhf[g][o+1]);
            }
        }

        __syncthreads();
        if (t == 0 && ti + 2 < SS/64) kvissue(ti + 2);
    }

    // final row-sum reduction (across the 4 lanes sharing each q row)
    lsum0 += __shfl_xor_sync(0xffffffffu, lsum0, 1);
    lsum0 += __shfl_xor_sync(0xffffffffu, lsum0, 2);
    lsum1 += __shfl_xor_sync(0xffffffffu, lsum1, 1);
    lsum1 += __shfl_xor_sync(0xffffffffu, lsum1, 2);
    const float inv0 = 1.0f / lsum0;
    const float inv1 = 1.0f / lsum1;

    const int r0 = q0 + wq0 + (l >> 2);
    const int bb = bh >> 4, hh = bh & 15;
    #pragma unroll
    for (int nj = 0; nj < 8; nj++) {
        const int col = hh*HD + nj*8 + (l & 3)*2;
        *(__half2*)(g_a + (size_t)(bb*SS + r0)*DM + col) =
            __floats2half2_rn(oacc[nj][0]*inv0, oacc[nj][1]*inv0);
        *(__half2*)(g_a + (size_t)(bb*SS + r0 + 8)*DM + col) =
            __floats2half2_rn(oacc[nj][2]*inv1, oacc[nj][3]*inv1);
    }
}

// ---------------------------------------------------------------------------
// host: tensor-map construction via driver entry point (no -lcuda needed)
// ---------------------------------------------------------------------------
typedef CUresult (CUDAAPI *PFN_encodeTiled)(
    CUtensorMap*, CUtensorMapDataType, cuuint32_t, void*,
    const cuuint64_t*, const cuuint64_t*, const cuuint32_t*, const cuuint32_t*,
    CUtensorMapInterleave, CUtensorMapSwizzle, CUtensorMapL2promotion,
    CUtensorMapFloatOOBfill);

static PFN_encodeTiled get_encoder() {
    static PFN_encodeTiled fn = nullptr;
    if (!fn) {
        void* p = nullptr;
        cudaDriverEntryPointQueryResult qr;
        cudaGetDriverEntryPoint("cuTensorMapEncodeTiled", &p, cudaEnableDefault, &qr);
        fn = (PFN_encodeTiled)p;
    }
    return fn;
}

static void mk2d(CUtensorMap* m, void* base, uint64_t d0, uint64_t rows,
                 uint32_t b0, uint32_t b1) {
    cuuint64_t dims[2]    = {d0, rows};
    cuuint64_t strides[1] = {d0 * 2};     // bytes
    cuuint32_t box[2]     = {b0, b1};
    cuuint32_t es[2]      = {1, 1};
    get_encoder()(m, CU_TENSOR_MAP_DATA_TYPE_FLOAT16, 2, base,
                  dims, strides, box, es,
                  CU_TENSOR_MAP_INTERLEAVE_NONE, CU_TENSOR_MAP_SWIZZLE_128B,
                  CU_TENSOR_MAP_L2_PROMOTION_L2_128B,
                  CU_TENSOR_MAP_FLOAT_OOB_FILL_NONE);
}

extern "C" void kernel_launch(void* const* d_in, const int* in_sizes, int n_in,
                              void* d_out, int out_size) {
    const float* x     = (const float*)d_in[0];
    const float* rel   = (const float*)d_in[1];
    const float* alpha = (const float*)d_in[2];
    const float* Wq    = (const float*)d_in[3];
    const float* bq    = (const float*)d_in[4];
    const float* Wk    = (const float*)d_in[5];
    const float* bk    = (const float*)d_in[6];
    const float* Wv    = (const float*)d_in[7];
    const float* bv    = (const float*)d_in[8];
    const float* Wo    = (const float*)d_in[9];
    const float* bo    = (const float*)d_in[10];
    float* out = (float*)d_out;

    cudaFuncSetAttribute(gemm_tma,  cudaFuncAttributeMaxDynamicSharedMemorySize, GEMM_SMEM);
    cudaFuncSetAttribute(flash_tma, cudaFuncAttributeMaxDynamicSharedMemorySize, FL_SMEM);

    void *a, *w, *qh, *kh, *vh;
    cudaGetSymbolAddress(&a,  g_a);
    cudaGetSymbolAddress(&w,  g_w);
    cudaGetSymbolAddress(&qh, g_qh);
    cudaGetSymbolAddress(&kh, g_kh);
    cudaGetSymbolAddress(&vh, g_vh);

    CUtensorMap mA, mW, mQh, mKh, mVh;
    mk2d(&mA,  a,  DM, MT,          64, 128);
    mk2d(&mW,  w,  DM, 4*DM,        64, 64);
    mk2d(&mQh, qh, HD, BB*NH*SS,    64, 64);
    mk2d(&mKh, kh, HD, BB*NH*SS,    64, 64);
    mk2d(&mVh, vh, HD, BB*NH*SS,    64, 64);

    pe_kernel<<<(MT*(DM/2) + 255)/256, 256>>>(x, rel, alpha);
    conv4_kernel<<<(4*NW4 + 255)/256, 256>>>(Wq, Wk, Wv, Wo);

    gemm_tma<<<dim3(3*DM/64, MT/128), 128, GEMM_SMEM>>>(
        mA, mW, bq, bk, bv, nullptr, 0, 0);

    flash_tma<<<dim3(SS/64, BB*NH), 128, FL_SMEM>>>(mQh, mKh, mVh);

    gemm_tma<<<dim3(DM/64, MT/128), 128, GEMM_SMEM>>>(
        mA, mW, bo, bo, bo, out, 3*DM, 3);
}